// round 1
// baseline (speedup 1.0000x reference)
#include <cuda_runtime.h>
#include <cuda_bf16.h>
#include <math.h>

// Problem constants
#define BATCH 2
#define TSEQ  2048
#define CDIM  1024
#define NHEAD 16
#define HDIM  64
#define MROWS (BATCH * TSEQ)   // 4096

// ---------------------------------------------------------------------------
// Scratch (allocation-free: __device__ globals)
// ---------------------------------------------------------------------------
__device__ __align__(16) float g_q[MROWS * CDIM];
__device__ __align__(16) float g_k[MROWS * CDIM];
__device__ __align__(16) float g_v[MROWS * CDIM];
__device__ __align__(16) float g_y[MROWS * CDIM];

// ---------------------------------------------------------------------------
// GEMM: C[M,N] = A[M,K] @ B[N,K]^T + bias[N]   (torch Linear, NT layout)
// Tiles: BM=64, BN=64, BK=32, 256 threads, 4x4 register tile per thread.
// ---------------------------------------------------------------------------
__global__ void __launch_bounds__(256)
gemm_nt_bias(const float* __restrict__ A, const float* __restrict__ B,
             const float* __restrict__ bias, float* __restrict__ C,
             int M, int N, int K)
{
    __shared__ float As[32][64];   // k-major: As[kk][m]
    __shared__ float Bs[32][64];   // k-major: Bs[kk][n]

    const int tid = threadIdx.x;
    const int m0 = blockIdx.y * 64;
    const int n0 = blockIdx.x * 64;
    const int tx = tid & 15;
    const int ty = tid >> 4;

    float acc[4][4] = {};

    for (int k0 = 0; k0 < K; k0 += 32) {
        // cooperative load: 64 rows x 32 cols each for A and B (512 float4 each)
        #pragma unroll
        for (int t = 0; t < 2; t++) {
            int f   = tid + t * 256;
            int row = f >> 3;        // 8 float4 per 32-float row
            int c4  = f & 7;
            float4 va = *(const float4*)&A[(size_t)(m0 + row) * K + k0 + c4 * 4];
            As[c4 * 4 + 0][row] = va.x;
            As[c4 * 4 + 1][row] = va.y;
            As[c4 * 4 + 2][row] = va.z;
            As[c4 * 4 + 3][row] = va.w;
            float4 vb = *(const float4*)&B[(size_t)(n0 + row) * K + k0 + c4 * 4];
            Bs[c4 * 4 + 0][row] = vb.x;
            Bs[c4 * 4 + 1][row] = vb.y;
            Bs[c4 * 4 + 2][row] = vb.z;
            Bs[c4 * 4 + 3][row] = vb.w;
        }
        __syncthreads();

        #pragma unroll
        for (int kk = 0; kk < 32; kk++) {
            float4 a = *(const float4*)&As[kk][ty * 4];
            float4 b = *(const float4*)&Bs[kk][tx * 4];
            float av[4] = {a.x, a.y, a.z, a.w};
            float bv[4] = {b.x, b.y, b.z, b.w};
            #pragma unroll
            for (int i = 0; i < 4; i++)
                #pragma unroll
                for (int j = 0; j < 4; j++)
                    acc[i][j] = fmaf(av[i], bv[j], acc[i][j]);
        }
        __syncthreads();
    }

    #pragma unroll
    for (int i = 0; i < 4; i++) {
        #pragma unroll
        for (int j = 0; j < 4; j++) {
            int n = n0 + tx * 4 + j;
            C[(size_t)(m0 + ty * 4 + i) * N + n] = acc[i][j] + bias[n];
        }
    }
}

// ---------------------------------------------------------------------------
// Flash attention (causal): one block per (b*h, q-tile of 64 rows).
// Q/K/V/Y all stored [B, T, C] row-major; head h occupies cols [h*64, h*64+64).
// Dynamic smem: qs[64][64] (d-major), ks[64][64] (d-major), vs[64][64] (k-major),
//               ps[64][64] (col-major, i.e. ps[j][r]) -> 64 KB.
// ---------------------------------------------------------------------------
__global__ void __launch_bounds__(256)
attn_kernel(const float* __restrict__ Q, const float* __restrict__ K,
            const float* __restrict__ V, float* __restrict__ Y)
{
    extern __shared__ float sm[];
    float* qs = sm;           // qs[d * 64 + r]
    float* ks = sm + 4096;    // ks[d * 64 + j]
    float* vs = sm + 8192;    // vs[j * 64 + d]
    float* ps = sm + 12288;   // ps[j * 64 + r]
    __shared__ float row_m[64], row_l[64], row_alpha[64];

    const int qt = blockIdx.x;
    const int bh = blockIdx.y;
    const int b  = bh >> 4;
    const int h  = bh & 15;
    const size_t headoff = (size_t)b * TSEQ * CDIM + (size_t)h * HDIM;

    const int tid = threadIdx.x;
    const int tx = tid & 15;   // -> 4 cols (d or k index)
    const int ty = tid >> 4;   // -> 4 rows (q index)

    // load Q tile transposed into qs[d][r]
    #pragma unroll
    for (int t = 0; t < 4; t++) {
        int f  = tid + t * 256;
        int r  = f >> 4;        // 16 float4 per 64-float row
        int c4 = f & 15;
        float4 v4 = *(const float4*)&Q[headoff + (size_t)(qt * 64 + r) * CDIM + c4 * 4];
        qs[(c4 * 4 + 0) * 64 + r] = v4.x;
        qs[(c4 * 4 + 1) * 64 + r] = v4.y;
        qs[(c4 * 4 + 2) * 64 + r] = v4.z;
        qs[(c4 * 4 + 3) * 64 + r] = v4.w;
    }
    if (tid < 64) { row_m[tid] = -INFINITY; row_l[tid] = 0.f; }

    float o[4][4] = {};
    const float scale = 0.125f;   // 1/sqrt(64)

    for (int kt = 0; kt <= qt; kt++) {
        __syncthreads();   // previous-iter consumers of ks/vs/ps done (also covers q load)

        // load K tile transposed (ks[d][j]) and V tile natural (vs[j][d])
        #pragma unroll
        for (int t = 0; t < 4; t++) {
            int f  = tid + t * 256;
            int r  = f >> 4;
            int c4 = f & 15;
            size_t goff = headoff + (size_t)(kt * 64 + r) * CDIM + c4 * 4;
            float4 kv = *(const float4*)&K[goff];
            ks[(c4 * 4 + 0) * 64 + r] = kv.x;
            ks[(c4 * 4 + 1) * 64 + r] = kv.y;
            ks[(c4 * 4 + 2) * 64 + r] = kv.z;
            ks[(c4 * 4 + 3) * 64 + r] = kv.w;
            float4 vv = *(const float4*)&V[goff];
            *(float4*)&vs[r * 64 + c4 * 4] = vv;
        }
        __syncthreads();

        // S = Q K^T (4x4 per thread), rows ty*4.., cols tx*4..
        float acc[4][4] = {};
        #pragma unroll
        for (int kk = 0; kk < 64; kk++) {
            float4 a = *(const float4*)&qs[kk * 64 + ty * 4];
            float4 bq = *(const float4*)&ks[kk * 64 + tx * 4];
            float av[4] = {a.x, a.y, a.z, a.w};
            float bv[4] = {bq.x, bq.y, bq.z, bq.w};
            #pragma unroll
            for (int i = 0; i < 4; i++)
                #pragma unroll
                for (int j = 0; j < 4; j++)
                    acc[i][j] = fmaf(av[i], bv[j], acc[i][j]);
        }
        // scale + causal mask + store transposed into ps[j][r]
        #pragma unroll
        for (int i = 0; i < 4; i++) {
            #pragma unroll
            for (int j = 0; j < 4; j++) {
                float s = acc[i][j] * scale;
                if (kt == qt && (tx * 4 + j) > (ty * 4 + i)) s = -INFINITY;
                ps[(tx * 4 + j) * 64 + (ty * 4 + i)] = s;
            }
        }
        __syncthreads();

        // online softmax: one thread per query row
        if (tid < 64) {
            int r = tid;
            float mold = row_m[r];
            float mnew = mold;
            #pragma unroll 8
            for (int j = 0; j < 64; j++) mnew = fmaxf(mnew, ps[j * 64 + r]);
            float alpha = expf(mold - mnew);     // mold=-inf -> 0
            float l = row_l[r] * alpha;
            #pragma unroll 8
            for (int j = 0; j < 64; j++) {
                float p = expf(ps[j * 64 + r] - mnew);   // -inf -> 0
                ps[j * 64 + r] = p;
                l += p;
            }
            row_m[r] = mnew;
            row_l[r] = l;
            row_alpha[r] = alpha;
        }
        __syncthreads();

        // rescale O, then O += P V
        float al[4];
        #pragma unroll
        for (int i = 0; i < 4; i++) al[i] = row_alpha[ty * 4 + i];
        #pragma unroll
        for (int i = 0; i < 4; i++)
            #pragma unroll
            for (int j = 0; j < 4; j++)
                o[i][j] *= al[i];

        #pragma unroll
        for (int kk = 0; kk < 64; kk++) {
            float4 p = *(const float4*)&ps[kk * 64 + ty * 4];
            float4 vv = *(const float4*)&vs[kk * 64 + tx * 4];
            float pv[4] = {p.x, p.y, p.z, p.w};
            float vvv[4] = {vv.x, vv.y, vv.z, vv.w};
            #pragma unroll
            for (int i = 0; i < 4; i++)
                #pragma unroll
                for (int j = 0; j < 4; j++)
                    o[i][j] = fmaf(pv[i], vvv[j], o[i][j]);
        }
    }

    // normalize and write Y (row_l written before the pre-PV barrier -> visible)
    float linv[4];
    #pragma unroll
    for (int i = 0; i < 4; i++) linv[i] = 1.0f / row_l[ty * 4 + i];
    #pragma unroll
    for (int i = 0; i < 4; i++) {
        #pragma unroll
        for (int j = 0; j < 4; j++) {
            Y[headoff + (size_t)(qt * 64 + ty * 4 + i) * CDIM + tx * 4 + j] =
                o[i][j] * linv[i];
        }
    }
}

// ---------------------------------------------------------------------------
// Launch
// ---------------------------------------------------------------------------
extern "C" void kernel_launch(void* const* d_in, const int* in_sizes, int n_in,
                              void* d_out, int out_size)
{
    const float* x  = (const float*)d_in[0];
    const float* Wq = (const float*)d_in[1];
    const float* bq = (const float*)d_in[2];
    const float* Wk = (const float*)d_in[3];
    const float* bk = (const float*)d_in[4];
    const float* Wv = (const float*)d_in[5];
    const float* bv = (const float*)d_in[6];
    const float* Wo = (const float*)d_in[7];
    const float* bo = (const float*)d_in[8];
    float* out = (float*)d_out;

    float *q, *k, *v, *y;
    cudaGetSymbolAddress((void**)&q, g_q);
    cudaGetSymbolAddress((void**)&k, g_k);
    cudaGetSymbolAddress((void**)&v, g_v);
    cudaGetSymbolAddress((void**)&y, g_y);

    const int attn_smem = 4 * 64 * 64 * (int)sizeof(float);  // 64 KB dynamic
    cudaFuncSetAttribute(attn_kernel, cudaFuncAttributeMaxDynamicSharedMemorySize,
                         attn_smem);

    dim3 gblk(256);
    dim3 ggrid(CDIM / 64, MROWS / 64);   // (16, 64)

    gemm_nt_bias<<<ggrid, gblk>>>(x, Wq, bq, q, MROWS, CDIM, CDIM);
    gemm_nt_bias<<<ggrid, gblk>>>(x, Wk, bk, k, MROWS, CDIM, CDIM);
    gemm_nt_bias<<<ggrid, gblk>>>(x, Wv, bv, v, MROWS, CDIM, CDIM);

    dim3 agrid(TSEQ / 64, BATCH * NHEAD);  // (32, 32)
    attn_kernel<<<agrid, gblk, attn_smem>>>(q, k, v, y);

    gemm_nt_bias<<<ggrid, gblk>>>(y, Wo, bo, out, MROWS, CDIM, CDIM);
}

// round 4
// speedup vs baseline: 1.7844x; 1.7844x over previous
#include <cuda_runtime.h>
#include <cuda_bf16.h>
#include <math.h>
#include <stdint.h>

// Problem constants
#define BATCH 2
#define TSEQ  2048
#define CDIM  1024
#define NHEAD 16
#define HDIM  64
#define MROWS (BATCH * TSEQ)   // 4096

// ---------------------------------------------------------------------------
// Scratch (allocation-free: __device__ globals)
// ---------------------------------------------------------------------------
__device__ __align__(16) float g_q[MROWS * CDIM];
__device__ __align__(16) float g_k[MROWS * CDIM];
__device__ __align__(16) float g_v[MROWS * CDIM];
__device__ __align__(16) float g_y[MROWS * CDIM];
__device__ __align__(16) __nv_bfloat16 g_xh[MROWS * CDIM];
__device__ __align__(16) __nv_bfloat16 g_xl[MROWS * CDIM];
__device__ __align__(16) __nv_bfloat16 g_yh[MROWS * CDIM];
__device__ __align__(16) __nv_bfloat16 g_yl[MROWS * CDIM];
__device__ __align__(16) __nv_bfloat16 g_wh[CDIM * CDIM];
__device__ __align__(16) __nv_bfloat16 g_wl[CDIM * CDIM];

// ---------------------------------------------------------------------------
// mma.sync m16n8k16 bf16 -> f32 (baseline PTX, works on compute_103)
// ---------------------------------------------------------------------------
__device__ __forceinline__ void mma16816(float* c, const uint32_t* a,
                                         const uint32_t* b) {
    asm volatile(
        "mma.sync.aligned.m16n8k16.row.col.f32.bf16.bf16.f32 "
        "{%0,%1,%2,%3}, {%4,%5,%6,%7}, {%8,%9}, {%0,%1,%2,%3};"
        : "+f"(c[0]), "+f"(c[1]), "+f"(c[2]), "+f"(c[3])
        : "r"(a[0]), "r"(a[1]), "r"(a[2]), "r"(a[3]), "r"(b[0]), "r"(b[1]));
}

// ---------------------------------------------------------------------------
// Split fp32 -> (hi bf16, lo bf16), lo = bf16(x - float(hi))
// ---------------------------------------------------------------------------
__global__ void __launch_bounds__(256)
split_kernel(const float* __restrict__ in, __nv_bfloat16* __restrict__ hi,
             __nv_bfloat16* __restrict__ lo, int n4)
{
    int i = blockIdx.x * blockDim.x + threadIdx.x;
    if (i >= n4) return;
    float4 v = ((const float4*)in)[i];
    float f[4] = {v.x, v.y, v.z, v.w};
    __nv_bfloat16 h[4], l[4];
    #pragma unroll
    for (int j = 0; j < 4; j++) {
        h[j] = __float2bfloat16(f[j]);
        l[j] = __float2bfloat16(f[j] - __bfloat162float(h[j]));
    }
    ((__nv_bfloat162*)hi)[2 * i]     = __halves2bfloat162(h[0], h[1]);
    ((__nv_bfloat162*)hi)[2 * i + 1] = __halves2bfloat162(h[2], h[3]);
    ((__nv_bfloat162*)lo)[2 * i]     = __halves2bfloat162(l[0], l[1]);
    ((__nv_bfloat162*)lo)[2 * i + 1] = __halves2bfloat162(l[2], l[3]);
}

// ---------------------------------------------------------------------------
// HMMA GEMM: C[M,N] = A[M,K] @ B[N,K]^T + bias, hi/lo bf16 split (3 MMAs).
// CTA tile 128x128, K-chunk 32, 8 warps in 4(M)x2(N), warp tile 32x64.
// smem padded: row stride 20 b32 (40 bf16) -> conflict-free fragment loads.
// ---------------------------------------------------------------------------
#define SSTR 20   // b32 per smem row

__global__ void __launch_bounds__(256)
gemm_mma(const __nv_bfloat16* __restrict__ Ah, const __nv_bfloat16* __restrict__ Al,
         const __nv_bfloat16* __restrict__ Bh, const __nv_bfloat16* __restrict__ Bl,
         const float* __restrict__ bias, float* __restrict__ C,
         int M, int N, int K)
{
    __shared__ uint32_t sAh[128 * SSTR], sAl[128 * SSTR];
    __shared__ uint32_t sBh[128 * SSTR], sBl[128 * SSTR];

    const int tid  = threadIdx.x;
    const int lane = tid & 31;
    const int warp = tid >> 5;
    const int wm   = (warp >> 1) * 32;   // 4 warps along M
    const int wn   = (warp & 1) * 64;    // 2 warps along N
    const int m0   = blockIdx.y * 128;
    const int n0   = blockIdx.x * 128;

    // per-thread gmem load slots: 2 x uint4 (8 bf16 each) per array.
    // f = tid + t*256: row = f>>2 (0..127), b32 col = (f&3)*4 (bf16 col *2)
    int sidx[2];
    size_t gA[2], gB[2];
    #pragma unroll
    for (int t = 0; t < 2; t++) {
        int f   = tid + t * 256;
        int row = f >> 2;
        int c4  = (f & 3) * 4;              // b32 col: 0,4,8,12
        sidx[t] = row * SSTR + c4;
        gA[t] = (size_t)(m0 + row) * K + c4 * 2;
        gB[t] = (size_t)(n0 + row) * K + c4 * 2;
    }

    const int fr = lane >> 2;   // fragment row (0..7)
    const int fc = lane & 3;    // fragment k-pair (0..3)

    float acc[2][8][4];
    #pragma unroll
    for (int mt = 0; mt < 2; mt++)
        #pragma unroll
        for (int nt = 0; nt < 8; nt++)
            #pragma unroll
            for (int j = 0; j < 4; j++) acc[mt][nt][j] = 0.f;

    uint4 pah[2], pal[2], pbh[2], pbl[2];
    #pragma unroll
    for (int t = 0; t < 2; t++) {
        pah[t] = *(const uint4*)(Ah + gA[t]);
        pal[t] = *(const uint4*)(Al + gA[t]);
        pbh[t] = *(const uint4*)(Bh + gB[t]);
        pbl[t] = *(const uint4*)(Bl + gB[t]);
    }

    const int nchunks = K / 32;
    for (int kc = 0; kc < nchunks; kc++) {
        #pragma unroll
        for (int t = 0; t < 2; t++) {
            *(uint4*)&sAh[sidx[t]] = pah[t];
            *(uint4*)&sAl[sidx[t]] = pal[t];
            *(uint4*)&sBh[sidx[t]] = pbh[t];
            *(uint4*)&sBl[sidx[t]] = pbl[t];
        }
        __syncthreads();

        if (kc + 1 < nchunks) {
            int ko = (kc + 1) * 32;
            #pragma unroll
            for (int t = 0; t < 2; t++) {
                pah[t] = *(const uint4*)(Ah + gA[t] + ko);
                pal[t] = *(const uint4*)(Al + gA[t] + ko);
                pbh[t] = *(const uint4*)(Bh + gB[t] + ko);
                pbl[t] = *(const uint4*)(Bl + gB[t] + ko);
            }
        }

        #pragma unroll
        for (int ks = 0; ks < 2; ks++) {
            const int kb = ks * 8;   // b32 offset of this k16 block
            uint32_t afh[2][4], afl[2][4];
            #pragma unroll
            for (int mt = 0; mt < 2; mt++) {
                int r0 = wm + mt * 16 + fr;
                afh[mt][0] = sAh[ r0      * SSTR + kb + fc];
                afh[mt][1] = sAh[(r0 + 8) * SSTR + kb + fc];
                afh[mt][2] = sAh[ r0      * SSTR + kb + fc + 4];
                afh[mt][3] = sAh[(r0 + 8) * SSTR + kb + fc + 4];
                afl[mt][0] = sAl[ r0      * SSTR + kb + fc];
                afl[mt][1] = sAl[(r0 + 8) * SSTR + kb + fc];
                afl[mt][2] = sAl[ r0      * SSTR + kb + fc + 4];
                afl[mt][3] = sAl[(r0 + 8) * SSTR + kb + fc + 4];
            }
            #pragma unroll
            for (int nt = 0; nt < 8; nt++) {
                int nr = wn + nt * 8 + fr;
                uint32_t bfh[2], bfl[2];
                bfh[0] = sBh[nr * SSTR + kb + fc];
                bfh[1] = sBh[nr * SSTR + kb + fc + 4];
                bfl[0] = sBl[nr * SSTR + kb + fc];
                bfl[1] = sBl[nr * SSTR + kb + fc + 4];
                #pragma unroll
                for (int mt = 0; mt < 2; mt++) {
                    mma16816(acc[mt][nt], afh[mt], bfh);
                    mma16816(acc[mt][nt], afh[mt], bfl);
                    mma16816(acc[mt][nt], afl[mt], bfh);
                }
            }
        }
        __syncthreads();
    }

    // epilogue: fragment layout -> gmem, + bias
    #pragma unroll
    for (int mt = 0; mt < 2; mt++) {
        #pragma unroll
        for (int nt = 0; nt < 8; nt++) {
            int row = m0 + wm + mt * 16 + fr;
            int col = n0 + wn + nt * 8 + fc * 2;
            float b0 = __ldg(&bias[col]);
            float b1 = __ldg(&bias[col + 1]);
            float2 v0 = make_float2(acc[mt][nt][0] + b0, acc[mt][nt][1] + b1);
            float2 v1 = make_float2(acc[mt][nt][2] + b0, acc[mt][nt][3] + b1);
            *(float2*)&C[(size_t)row * N + col]       = v0;
            *(float2*)&C[(size_t)(row + 8) * N + col] = v1;
        }
    }
}

// ---------------------------------------------------------------------------
// Flash attention (causal), register softmax via shfl within 16-lane row group
// smem: qs[d][r] 4096, ks[d][j] 4096, vs[j][d] 4096, ps[r][j] stride 68
// ---------------------------------------------------------------------------
__global__ void __launch_bounds__(256)
attn_kernel(const float* __restrict__ Q, const float* __restrict__ K,
            const float* __restrict__ V, float* __restrict__ Y)
{
    extern __shared__ char s_dyn[];
    float* sm = (float*)s_dyn;
    float* qs = sm;           // qs[d*64 + r]
    float* ks = sm + 4096;    // ks[d*64 + j]
    float* vs = sm + 8192;    // vs[j*64 + d]
    float* ps = sm + 12288;   // ps[r*68 + j]

    const int qt = blockIdx.x;
    const int bh = blockIdx.y;
    const int b  = bh >> 4;
    const int h  = bh & 15;
    const size_t headoff = (size_t)b * TSEQ * CDIM + (size_t)h * HDIM;

    const int tid = threadIdx.x;
    const int tx = tid & 15;
    const int ty = tid >> 4;

    #pragma unroll
    for (int t = 0; t < 4; t++) {
        int f  = tid + t * 256;
        int r  = f >> 4;
        int c4 = f & 15;
        float4 v4 = *(const float4*)&Q[headoff + (size_t)(qt * 64 + r) * CDIM + c4 * 4];
        qs[(c4 * 4 + 0) * 64 + r] = v4.x;
        qs[(c4 * 4 + 1) * 64 + r] = v4.y;
        qs[(c4 * 4 + 2) * 64 + r] = v4.z;
        qs[(c4 * 4 + 3) * 64 + r] = v4.w;
    }

    float m_i[4], l_i[4], o[4][4] = {};
    #pragma unroll
    for (int i = 0; i < 4; i++) { m_i[i] = -INFINITY; l_i[i] = 0.f; }

    const float scale = 0.125f;

    for (int kt = 0; kt <= qt; kt++) {
        __syncthreads();
        #pragma unroll
        for (int t = 0; t < 4; t++) {
            int f  = tid + t * 256;
            int r  = f >> 4;
            int c4 = f & 15;
            size_t goff = headoff + (size_t)(kt * 64 + r) * CDIM + c4 * 4;
            float4 kv = *(const float4*)&K[goff];
            ks[(c4 * 4 + 0) * 64 + r] = kv.x;
            ks[(c4 * 4 + 1) * 64 + r] = kv.y;
            ks[(c4 * 4 + 2) * 64 + r] = kv.z;
            ks[(c4 * 4 + 3) * 64 + r] = kv.w;
            *(float4*)&vs[r * 64 + c4 * 4] = *(const float4*)&V[goff];
        }
        __syncthreads();

        float sacc[4][4] = {};
        #pragma unroll
        for (int kk = 0; kk < 64; kk++) {
            float4 a  = *(const float4*)&qs[kk * 64 + ty * 4];
            float4 bq = *(const float4*)&ks[kk * 64 + tx * 4];
            float av[4] = {a.x, a.y, a.z, a.w};
            float bv[4] = {bq.x, bq.y, bq.z, bq.w};
            #pragma unroll
            for (int i = 0; i < 4; i++)
                #pragma unroll
                for (int j = 0; j < 4; j++)
                    sacc[i][j] = fmaf(av[i], bv[j], sacc[i][j]);
        }

        const bool diag = (kt == qt);
        #pragma unroll
        for (int i = 0; i < 4; i++) {
            int rloc = ty * 4 + i;
            #pragma unroll
            for (int j = 0; j < 4; j++) {
                float s = sacc[i][j] * scale;
                if (diag && (tx * 4 + j) > rloc) s = -INFINITY;
                sacc[i][j] = s;
            }
            float mx = fmaxf(fmaxf(sacc[i][0], sacc[i][1]),
                             fmaxf(sacc[i][2], sacc[i][3]));
            #pragma unroll
            for (int off = 8; off >= 1; off >>= 1)
                mx = fmaxf(mx, __shfl_xor_sync(0xffffffffu, mx, off));
            float mnew = fmaxf(m_i[i], mx);
            float alpha = __expf(m_i[i] - mnew);
            m_i[i] = mnew;
            float ls = 0.f;
            #pragma unroll
            for (int j = 0; j < 4; j++) {
                float p = __expf(sacc[i][j] - mnew);
                sacc[i][j] = p;
                ls += p;
            }
            #pragma unroll
            for (int off = 8; off >= 1; off >>= 1)
                ls += __shfl_xor_sync(0xffffffffu, ls, off);
            l_i[i] = l_i[i] * alpha + ls;
            #pragma unroll
            for (int j = 0; j < 4; j++) o[i][j] *= alpha;
            *(float4*)&ps[rloc * 68 + tx * 4] =
                make_float4(sacc[i][0], sacc[i][1], sacc[i][2], sacc[i][3]);
        }
        __syncthreads();

        #pragma unroll 4
        for (int kk = 0; kk < 64; kk++) {
            float4 v4 = *(const float4*)&vs[kk * 64 + tx * 4];
            float vv[4] = {v4.x, v4.y, v4.z, v4.w};
            float pr[4];
            #pragma unroll
            for (int i = 0; i < 4; i++) pr[i] = ps[(ty * 4 + i) * 68 + kk];
            #pragma unroll
            for (int i = 0; i < 4; i++)
                #pragma unroll
                for (int j = 0; j < 4; j++)
                    o[i][j] = fmaf(pr[i], vv[j], o[i][j]);
        }
    }

    float linv[4];
    #pragma unroll
    for (int i = 0; i < 4; i++) linv[i] = 1.0f / l_i[i];
    #pragma unroll
    for (int i = 0; i < 4; i++) {
        #pragma unroll
        for (int j = 0; j < 4; j++) {
            Y[headoff + (size_t)(qt * 64 + ty * 4 + i) * CDIM + tx * 4 + j] =
                o[i][j] * linv[i];
        }
    }
}

// ---------------------------------------------------------------------------
// Launch
// ---------------------------------------------------------------------------
extern "C" void kernel_launch(void* const* d_in, const int* in_sizes, int n_in,
                              void* d_out, int out_size)
{
    const float* x  = (const float*)d_in[0];
    const float* Wq = (const float*)d_in[1];
    const float* bq = (const float*)d_in[2];
    const float* Wk = (const float*)d_in[3];
    const float* bk = (const float*)d_in[4];
    const float* Wv = (const float*)d_in[5];
    const float* bv = (const float*)d_in[6];
    const float* Wo = (const float*)d_in[7];
    const float* bo = (const float*)d_in[8];
    float* out = (float*)d_out;

    float *q, *k, *v, *y;
    __nv_bfloat16 *xh, *xl, *yh, *yl, *wh, *wl;
    cudaGetSymbolAddress((void**)&q,  g_q);
    cudaGetSymbolAddress((void**)&k,  g_k);
    cudaGetSymbolAddress((void**)&v,  g_v);
    cudaGetSymbolAddress((void**)&y,  g_y);
    cudaGetSymbolAddress((void**)&xh, g_xh);
    cudaGetSymbolAddress((void**)&xl, g_xl);
    cudaGetSymbolAddress((void**)&yh, g_yh);
    cudaGetSymbolAddress((void**)&yl, g_yl);
    cudaGetSymbolAddress((void**)&wh, g_wh);
    cudaGetSymbolAddress((void**)&wl, g_wl);

    const int attn_smem = 16640 * (int)sizeof(float);  // 66560 B
    cudaFuncSetAttribute(attn_kernel,
                         cudaFuncAttributeMaxDynamicSharedMemorySize, attn_smem);

    const int nx4 = MROWS * CDIM / 4;   // 1048576
    const int nw4 = CDIM * CDIM / 4;    // 262144

    dim3 ggrid(CDIM / 128, MROWS / 128);   // (8, 32)

    split_kernel<<<nx4 / 256, 256>>>(x, xh, xl, nx4);

    split_kernel<<<nw4 / 256, 256>>>(Wq, wh, wl, nw4);
    gemm_mma<<<ggrid, 256>>>(xh, xl, wh, wl, bq, q, MROWS, CDIM, CDIM);
    split_kernel<<<nw4 / 256, 256>>>(Wk, wh, wl, nw4);
    gemm_mma<<<ggrid, 256>>>(xh, xl, wh, wl, bk, k, MROWS, CDIM, CDIM);
    split_kernel<<<nw4 / 256, 256>>>(Wv, wh, wl, nw4);
    gemm_mma<<<ggrid, 256>>>(xh, xl, wh, wl, bv, v, MROWS, CDIM, CDIM);

    dim3 agrid(TSEQ / 64, BATCH * NHEAD);  // (32, 32)
    attn_kernel<<<agrid, 256, attn_smem>>>(q, k, v, y);

    split_kernel<<<nx4 / 256, 256>>>(y, yh, yl, nx4);
    split_kernel<<<nw4 / 256, 256>>>(Wo, wh, wl, nw4);
    gemm_mma<<<ggrid, 256>>>(yh, yl, wh, wl, bo, out, MROWS, CDIM, CDIM);
}

// round 5
// speedup vs baseline: 2.8486x; 1.5963x over previous
#include <cuda_runtime.h>
#include <cuda_bf16.h>
#include <math.h>
#include <stdint.h>

// Problem constants
#define BATCH 2
#define TSEQ  2048
#define CDIM  1024
#define NHEAD 16
#define HDIM  64
#define MROWS (BATCH * TSEQ)   // 4096

// ---------------------------------------------------------------------------
// Scratch (allocation-free: __device__ globals)
// ---------------------------------------------------------------------------
__device__ __align__(16) float g_q[MROWS * CDIM];
__device__ __align__(16) float g_k[MROWS * CDIM];
__device__ __align__(16) float g_v[MROWS * CDIM];
__device__ __align__(16) float g_y[MROWS * CDIM];
__device__ __align__(16) __nv_bfloat16 g_xh[MROWS * CDIM];
__device__ __align__(16) __nv_bfloat16 g_xl[MROWS * CDIM];
__device__ __align__(16) __nv_bfloat16 g_yh[MROWS * CDIM];
__device__ __align__(16) __nv_bfloat16 g_yl[MROWS * CDIM];
__device__ __align__(16) __nv_bfloat16 g_wh[CDIM * CDIM];
__device__ __align__(16) __nv_bfloat16 g_wl[CDIM * CDIM];

// ---------------------------------------------------------------------------
// mma.sync m16n8k16 bf16 -> f32 (baseline PTX, works on compute_103)
// ---------------------------------------------------------------------------
__device__ __forceinline__ void mma16816(float* c, const uint32_t* a,
                                         const uint32_t* b) {
    asm volatile(
        "mma.sync.aligned.m16n8k16.row.col.f32.bf16.bf16.f32 "
        "{%0,%1,%2,%3}, {%4,%5,%6,%7}, {%8,%9}, {%0,%1,%2,%3};"
        : "+f"(c[0]), "+f"(c[1]), "+f"(c[2]), "+f"(c[3])
        : "r"(a[0]), "r"(a[1]), "r"(a[2]), "r"(a[3]), "r"(b[0]), "r"(b[1]));
}

__device__ __forceinline__ uint32_t packbf(__nv_bfloat16 a, __nv_bfloat16 b) {
    __nv_bfloat162 t = __halves2bfloat162(a, b);
    return *(uint32_t*)&t;
}

// split two fp32 -> packed hi b32 + packed lo b32
__device__ __forceinline__ void split2(float a, float b,
                                       uint32_t& hi, uint32_t& lo) {
    __nv_bfloat16 ha = __float2bfloat16(a);
    __nv_bfloat16 hb = __float2bfloat16(b);
    __nv_bfloat16 la = __float2bfloat16(a - __bfloat162float(ha));
    __nv_bfloat16 lb = __float2bfloat16(b - __bfloat162float(hb));
    hi = packbf(ha, hb);
    lo = packbf(la, lb);
}

// ---------------------------------------------------------------------------
// Split fp32 -> (hi bf16, lo bf16), lo = bf16(x - float(hi))
// ---------------------------------------------------------------------------
__global__ void __launch_bounds__(256)
split_kernel(const float* __restrict__ in, __nv_bfloat16* __restrict__ hi,
             __nv_bfloat16* __restrict__ lo, int n4)
{
    int i = blockIdx.x * blockDim.x + threadIdx.x;
    if (i >= n4) return;
    float4 v = ((const float4*)in)[i];
    float f[4] = {v.x, v.y, v.z, v.w};
    __nv_bfloat16 h[4], l[4];
    #pragma unroll
    for (int j = 0; j < 4; j++) {
        h[j] = __float2bfloat16(f[j]);
        l[j] = __float2bfloat16(f[j] - __bfloat162float(h[j]));
    }
    ((__nv_bfloat162*)hi)[2 * i]     = __halves2bfloat162(h[0], h[1]);
    ((__nv_bfloat162*)hi)[2 * i + 1] = __halves2bfloat162(h[2], h[3]);
    ((__nv_bfloat162*)lo)[2 * i]     = __halves2bfloat162(l[0], l[1]);
    ((__nv_bfloat162*)lo)[2 * i + 1] = __halves2bfloat162(l[2], l[3]);
}

// ---------------------------------------------------------------------------
// HMMA GEMM: C[M,N] = A[M,K] @ B[N,K]^T + bias, hi/lo bf16 split (3 MMAs).
// CTA tile 128x128, K-chunk 32, 8 warps in 4(M)x2(N), warp tile 32x64.
// ---------------------------------------------------------------------------
#define SSTR 20   // b32 per smem row

__global__ void __launch_bounds__(256)
gemm_mma(const __nv_bfloat16* __restrict__ Ah, const __nv_bfloat16* __restrict__ Al,
         const __nv_bfloat16* __restrict__ Bh, const __nv_bfloat16* __restrict__ Bl,
         const float* __restrict__ bias, float* __restrict__ C,
         int M, int N, int K)
{
    __shared__ uint32_t sAh[128 * SSTR], sAl[128 * SSTR];
    __shared__ uint32_t sBh[128 * SSTR], sBl[128 * SSTR];

    const int tid  = threadIdx.x;
    const int lane = tid & 31;
    const int warp = tid >> 5;
    const int wm   = (warp >> 1) * 32;
    const int wn   = (warp & 1) * 64;
    const int m0   = blockIdx.y * 128;
    const int n0   = blockIdx.x * 128;

    int sidx[2];
    size_t gA[2], gB[2];
    #pragma unroll
    for (int t = 0; t < 2; t++) {
        int f   = tid + t * 256;
        int row = f >> 2;
        int c4  = (f & 3) * 4;
        sidx[t] = row * SSTR + c4;
        gA[t] = (size_t)(m0 + row) * K + c4 * 2;
        gB[t] = (size_t)(n0 + row) * K + c4 * 2;
    }

    const int fr = lane >> 2;
    const int fc = lane & 3;

    float acc[2][8][4];
    #pragma unroll
    for (int mt = 0; mt < 2; mt++)
        #pragma unroll
        for (int nt = 0; nt < 8; nt++)
            #pragma unroll
            for (int j = 0; j < 4; j++) acc[mt][nt][j] = 0.f;

    uint4 pah[2], pal[2], pbh[2], pbl[2];
    #pragma unroll
    for (int t = 0; t < 2; t++) {
        pah[t] = *(const uint4*)(Ah + gA[t]);
        pal[t] = *(const uint4*)(Al + gA[t]);
        pbh[t] = *(const uint4*)(Bh + gB[t]);
        pbl[t] = *(const uint4*)(Bl + gB[t]);
    }

    const int nchunks = K / 32;
    for (int kc = 0; kc < nchunks; kc++) {
        #pragma unroll
        for (int t = 0; t < 2; t++) {
            *(uint4*)&sAh[sidx[t]] = pah[t];
            *(uint4*)&sAl[sidx[t]] = pal[t];
            *(uint4*)&sBh[sidx[t]] = pbh[t];
            *(uint4*)&sBl[sidx[t]] = pbl[t];
        }
        __syncthreads();

        if (kc + 1 < nchunks) {
            int ko = (kc + 1) * 32;
            #pragma unroll
            for (int t = 0; t < 2; t++) {
                pah[t] = *(const uint4*)(Ah + gA[t] + ko);
                pal[t] = *(const uint4*)(Al + gA[t] + ko);
                pbh[t] = *(const uint4*)(Bh + gB[t] + ko);
                pbl[t] = *(const uint4*)(Bl + gB[t] + ko);
            }
        }

        #pragma unroll
        for (int ks = 0; ks < 2; ks++) {
            const int kb = ks * 8;
            uint32_t afh[2][4], afl[2][4];
            #pragma unroll
            for (int mt = 0; mt < 2; mt++) {
                int r0 = wm + mt * 16 + fr;
                afh[mt][0] = sAh[ r0      * SSTR + kb + fc];
                afh[mt][1] = sAh[(r0 + 8) * SSTR + kb + fc];
                afh[mt][2] = sAh[ r0      * SSTR + kb + fc + 4];
                afh[mt][3] = sAh[(r0 + 8) * SSTR + kb + fc + 4];
                afl[mt][0] = sAl[ r0      * SSTR + kb + fc];
                afl[mt][1] = sAl[(r0 + 8) * SSTR + kb + fc];
                afl[mt][2] = sAl[ r0      * SSTR + kb + fc + 4];
                afl[mt][3] = sAl[(r0 + 8) * SSTR + kb + fc + 4];
            }
            #pragma unroll
            for (int nt = 0; nt < 8; nt++) {
                int nr = wn + nt * 8 + fr;
                uint32_t bfh[2], bfl[2];
                bfh[0] = sBh[nr * SSTR + kb + fc];
                bfh[1] = sBh[nr * SSTR + kb + fc + 4];
                bfl[0] = sBl[nr * SSTR + kb + fc];
                bfl[1] = sBl[nr * SSTR + kb + fc + 4];
                #pragma unroll
                for (int mt = 0; mt < 2; mt++) {
                    mma16816(acc[mt][nt], afh[mt], bfh);
                    mma16816(acc[mt][nt], afh[mt], bfl);
                    mma16816(acc[mt][nt], afl[mt], bfh);
                }
            }
        }
        __syncthreads();
    }

    #pragma unroll
    for (int mt = 0; mt < 2; mt++) {
        #pragma unroll
        for (int nt = 0; nt < 8; nt++) {
            int row = m0 + wm + mt * 16 + fr;
            int col = n0 + wn + nt * 8 + fc * 2;
            float b0 = __ldg(&bias[col]);
            float b1 = __ldg(&bias[col + 1]);
            float2 v0 = make_float2(acc[mt][nt][0] + b0, acc[mt][nt][1] + b1);
            float2 v1 = make_float2(acc[mt][nt][2] + b0, acc[mt][nt][3] + b1);
            *(float2*)&C[(size_t)row * N + col]       = v0;
            *(float2*)&C[(size_t)(row + 8) * N + col] = v1;
        }
    }
}

// ---------------------------------------------------------------------------
// HMMA flash attention (causal). One CTA per (b*h, 128-row q tile).
// 8 warps, each owns 16 q rows. Bc = 64 kv per iteration.
// S = QK^T with hi/lo split (3 MMAs), PV with hi/lo split (3 MMAs).
// P converted fp32->hi/lo bf16 in registers (C-frag == A-frag layout).
// smem (b32): qh[128*36] ql[128*36] kh[64*36] kl[64*36] vth[64*36] vtl[64*36]
// ---------------------------------------------------------------------------
#define QSTR 36
#define ATTN_SMEM_B32 (2 * 128 * QSTR + 4 * 64 * QSTR)   // 18432 b32 = 73728 B

__global__ void __launch_bounds__(256)
attn_mma(const float* __restrict__ Q, const float* __restrict__ K,
         const float* __restrict__ V, float* __restrict__ Y)
{
    extern __shared__ uint32_t s32[];
    uint32_t* qh  = s32;
    uint32_t* ql  = qh + 128 * QSTR;
    uint32_t* kh  = ql + 128 * QSTR;
    uint32_t* kl  = kh + 64 * QSTR;
    uint32_t* vth = kl + 64 * QSTR;
    uint32_t* vtl = vth + 64 * QSTR;
    __nv_bfloat16* vth16 = (__nv_bfloat16*)vth;
    __nv_bfloat16* vtl16 = (__nv_bfloat16*)vtl;

    const int qt = blockIdx.x;          // q tile (128 rows)
    const int bh = blockIdx.y;
    const int b  = bh >> 4;
    const int h  = bh & 15;
    const size_t headoff = (size_t)b * TSEQ * CDIM + (size_t)h * HDIM;

    const int tid  = threadIdx.x;
    const int lane = tid & 31;
    const int warp = tid >> 5;
    const int fr   = lane >> 2;   // 0..7
    const int fc   = lane & 3;    // 0..3
    const int wm   = warp * 16;   // warp q-row offset

    // ---- load Q tile 128x64 fp32 -> hi/lo bf16 smem ----
    #pragma unroll
    for (int t = 0; t < 8; t++) {
        int f  = tid + t * 256;
        int r  = f >> 4;          // 0..127
        int c4 = f & 15;          // d = c4*4
        float4 v4 = *(const float4*)&Q[headoff + (size_t)(qt * 128 + r) * CDIM + c4 * 4];
        uint32_t h01, l01, h23, l23;
        split2(v4.x, v4.y, h01, l01);
        split2(v4.z, v4.w, h23, l23);
        qh[r * QSTR + c4 * 2]     = h01;
        qh[r * QSTR + c4 * 2 + 1] = h23;
        ql[r * QSTR + c4 * 2]     = l01;
        ql[r * QSTR + c4 * 2 + 1] = l23;
    }

    const float scale = 0.125f;   // 1/sqrt(64)
    float o[8][4];
    #pragma unroll
    for (int nt = 0; nt < 8; nt++)
        #pragma unroll
        for (int j = 0; j < 4; j++) o[nt][j] = 0.f;
    float mA = -INFINITY, mB = -INFINITY, lA = 0.f, lB = 0.f;

    const int rowAg = qt * 128 + wm + fr;   // global q row (pair A)
    const int rowBg = rowAg + 8;            // pair B

    const int ktmax = 2 * qt + 1;
    for (int kt = 0; kt <= ktmax; kt++) {
        __syncthreads();   // smem K/V reuse safe; also covers Q load on kt=0

        // ---- load K tile 64x64 -> kh/kl; V tile transposed -> vth/vtl ----
        #pragma unroll
        for (int t = 0; t < 4; t++) {
            int f  = tid + t * 256;
            int r  = f >> 4;      // kv row 0..63
            int c4 = f & 15;      // d = c4*4
            size_t goff = headoff + (size_t)(kt * 64 + r) * CDIM + c4 * 4;
            float4 kv4 = *(const float4*)&K[goff];
            uint32_t h01, l01, h23, l23;
            split2(kv4.x, kv4.y, h01, l01);
            split2(kv4.z, kv4.w, h23, l23);
            kh[r * QSTR + c4 * 2]     = h01;
            kh[r * QSTR + c4 * 2 + 1] = h23;
            kl[r * QSTR + c4 * 2]     = l01;
            kl[r * QSTR + c4 * 2 + 1] = l23;

            float4 vv4 = *(const float4*)&V[goff];
            float vf[4] = {vv4.x, vv4.y, vv4.z, vv4.w};
            #pragma unroll
            for (int j = 0; j < 4; j++) {
                int d = c4 * 4 + j;
                __nv_bfloat16 hb = __float2bfloat16(vf[j]);
                __nv_bfloat16 lb = __float2bfloat16(vf[j] - __bfloat162float(hb));
                vth16[d * (QSTR * 2) + r] = hb;   // [d][kv]
                vtl16[d * (QSTR * 2) + r] = lb;
            }
        }
        __syncthreads();

        // ---- S = Q K^T (warp rows wm..wm+15, cols 0..63) ----
        float sacc[8][4];
        #pragma unroll
        for (int nt = 0; nt < 8; nt++)
            #pragma unroll
            for (int j = 0; j < 4; j++) sacc[nt][j] = 0.f;

        #pragma unroll
        for (int ks = 0; ks < 4; ks++) {
            const int kb = ks * 8;
            uint32_t ah[4], al[4];
            ah[0] = qh[(wm + fr)     * QSTR + kb + fc];
            ah[1] = qh[(wm + fr + 8) * QSTR + kb + fc];
            ah[2] = qh[(wm + fr)     * QSTR + kb + fc + 4];
            ah[3] = qh[(wm + fr + 8) * QSTR + kb + fc + 4];
            al[0] = ql[(wm + fr)     * QSTR + kb + fc];
            al[1] = ql[(wm + fr + 8) * QSTR + kb + fc];
            al[2] = ql[(wm + fr)     * QSTR + kb + fc + 4];
            al[3] = ql[(wm + fr + 8) * QSTR + kb + fc + 4];
            #pragma unroll
            for (int nt = 0; nt < 8; nt++) {
                int nr = nt * 8 + fr;
                uint32_t bh2[2], bl2[2];
                bh2[0] = kh[nr * QSTR + kb + fc];
                bh2[1] = kh[nr * QSTR + kb + fc + 4];
                bl2[0] = kl[nr * QSTR + kb + fc];
                bl2[1] = kl[nr * QSTR + kb + fc + 4];
                mma16816(sacc[nt], ah, bh2);
                mma16816(sacc[nt], ah, bl2);
                mma16816(sacc[nt], al, bh2);
            }
        }

        // ---- scale + causal mask ----
        const bool diag = (kt >= 2 * qt);
        #pragma unroll
        for (int nt = 0; nt < 8; nt++) {
            #pragma unroll
            for (int j = 0; j < 4; j++) sacc[nt][j] *= scale;
            if (diag) {
                int col0 = kt * 64 + nt * 8 + 2 * fc;
                if (col0     > rowAg) sacc[nt][0] = -INFINITY;
                if (col0 + 1 > rowAg) sacc[nt][1] = -INFINITY;
                if (col0     > rowBg) sacc[nt][2] = -INFINITY;
                if (col0 + 1 > rowBg) sacc[nt][3] = -INFINITY;
            }
        }

        // ---- online softmax (rows A = fr, B = fr+8; reduce over quad) ----
        float mxA = -INFINITY, mxB = -INFINITY;
        #pragma unroll
        for (int nt = 0; nt < 8; nt++) {
            mxA = fmaxf(mxA, fmaxf(sacc[nt][0], sacc[nt][1]));
            mxB = fmaxf(mxB, fmaxf(sacc[nt][2], sacc[nt][3]));
        }
        mxA = fmaxf(mxA, __shfl_xor_sync(0xffffffffu, mxA, 1));
        mxA = fmaxf(mxA, __shfl_xor_sync(0xffffffffu, mxA, 2));
        mxB = fmaxf(mxB, __shfl_xor_sync(0xffffffffu, mxB, 1));
        mxB = fmaxf(mxB, __shfl_xor_sync(0xffffffffu, mxB, 2));

        float mnA = fmaxf(mA, mxA), mnB = fmaxf(mB, mxB);
        float aA = __expf(mA - mnA), aB = __expf(mB - mnB);
        mA = mnA; mB = mnB;

        float lsA = 0.f, lsB = 0.f;
        #pragma unroll
        for (int nt = 0; nt < 8; nt++) {
            sacc[nt][0] = __expf(sacc[nt][0] - mnA);
            sacc[nt][1] = __expf(sacc[nt][1] - mnA);
            sacc[nt][2] = __expf(sacc[nt][2] - mnB);
            sacc[nt][3] = __expf(sacc[nt][3] - mnB);
            lsA += sacc[nt][0] + sacc[nt][1];
            lsB += sacc[nt][2] + sacc[nt][3];
        }
        lsA += __shfl_xor_sync(0xffffffffu, lsA, 1);
        lsA += __shfl_xor_sync(0xffffffffu, lsA, 2);
        lsB += __shfl_xor_sync(0xffffffffu, lsB, 1);
        lsB += __shfl_xor_sync(0xffffffffu, lsB, 2);
        lA = lA * aA + lsA;
        lB = lB * aB + lsB;

        #pragma unroll
        for (int nt = 0; nt < 8; nt++) {
            o[nt][0] *= aA; o[nt][1] *= aA;
            o[nt][2] *= aB; o[nt][3] *= aB;
        }

        // ---- O += P V (P from regs, hi/lo split) ----
        #pragma unroll
        for (int ks = 0; ks < 4; ks++) {
            uint32_t ph[4], pl[4];
            split2(sacc[2 * ks][0],     sacc[2 * ks][1],     ph[0], pl[0]);
            split2(sacc[2 * ks][2],     sacc[2 * ks][3],     ph[1], pl[1]);
            split2(sacc[2 * ks + 1][0], sacc[2 * ks + 1][1], ph[2], pl[2]);
            split2(sacc[2 * ks + 1][2], sacc[2 * ks + 1][3], ph[3], pl[3]);
            const int kb = ks * 8;
            #pragma unroll
            for (int nt = 0; nt < 8; nt++) {
                int nr = nt * 8 + fr;
                uint32_t vh2[2], vl2[2];
                vh2[0] = vth[nr * QSTR + kb + fc];
                vh2[1] = vth[nr * QSTR + kb + fc + 4];
                vl2[0] = vtl[nr * QSTR + kb + fc];
                vl2[1] = vtl[nr * QSTR + kb + fc + 4];
                mma16816(o[nt], ph, vh2);
                mma16816(o[nt], ph, vl2);
                mma16816(o[nt], pl, vh2);
            }
        }
    }

    // ---- normalize + write ----
    float liA = 1.0f / lA, liB = 1.0f / lB;
    #pragma unroll
    for (int nt = 0; nt < 8; nt++) {
        int col = nt * 8 + 2 * fc;
        *(float2*)&Y[headoff + (size_t)rowAg * CDIM + col] =
            make_float2(o[nt][0] * liA, o[nt][1] * liA);
        *(float2*)&Y[headoff + (size_t)rowBg * CDIM + col] =
            make_float2(o[nt][2] * liB, o[nt][3] * liB);
    }
}

// ---------------------------------------------------------------------------
// Launch
// ---------------------------------------------------------------------------
extern "C" void kernel_launch(void* const* d_in, const int* in_sizes, int n_in,
                              void* d_out, int out_size)
{
    const float* x  = (const float*)d_in[0];
    const float* Wq = (const float*)d_in[1];
    const float* bq = (const float*)d_in[2];
    const float* Wk = (const float*)d_in[3];
    const float* bk = (const float*)d_in[4];
    const float* Wv = (const float*)d_in[5];
    const float* bv = (const float*)d_in[6];
    const float* Wo = (const float*)d_in[7];
    const float* bo = (const float*)d_in[8];
    float* out = (float*)d_out;

    float *q, *k, *v, *y;
    __nv_bfloat16 *xh, *xl, *yh, *yl, *wh, *wl;
    cudaGetSymbolAddress((void**)&q,  g_q);
    cudaGetSymbolAddress((void**)&k,  g_k);
    cudaGetSymbolAddress((void**)&v,  g_v);
    cudaGetSymbolAddress((void**)&y,  g_y);
    cudaGetSymbolAddress((void**)&xh, g_xh);
    cudaGetSymbolAddress((void**)&xl, g_xl);
    cudaGetSymbolAddress((void**)&yh, g_yh);
    cudaGetSymbolAddress((void**)&yl, g_yl);
    cudaGetSymbolAddress((void**)&wh, g_wh);
    cudaGetSymbolAddress((void**)&wl, g_wl);

    const int attn_smem = ATTN_SMEM_B32 * 4;   // 73728 B
    cudaFuncSetAttribute(attn_mma,
                         cudaFuncAttributeMaxDynamicSharedMemorySize, attn_smem);

    const int nx4 = MROWS * CDIM / 4;
    const int nw4 = CDIM * CDIM / 4;

    dim3 ggrid(CDIM / 128, MROWS / 128);   // (8, 32)

    split_kernel<<<nx4 / 256, 256>>>(x, xh, xl, nx4);

    split_kernel<<<nw4 / 256, 256>>>(Wq, wh, wl, nw4);
    gemm_mma<<<ggrid, 256>>>(xh, xl, wh, wl, bq, q, MROWS, CDIM, CDIM);
    split_kernel<<<nw4 / 256, 256>>>(Wk, wh, wl, nw4);
    gemm_mma<<<ggrid, 256>>>(xh, xl, wh, wl, bk, k, MROWS, CDIM, CDIM);
    split_kernel<<<nw4 / 256, 256>>>(Wv, wh, wl, nw4);
    gemm_mma<<<ggrid, 256>>>(xh, xl, wh, wl, bv, v, MROWS, CDIM, CDIM);

    dim3 agrid(TSEQ / 128, BATCH * NHEAD);  // (16, 32)
    attn_mma<<<agrid, 256, attn_smem>>>(q, k, v, y);

    split_kernel<<<nx4 / 256, 256>>>(y, yh, yl, nx4);
    split_kernel<<<nw4 / 256, 256>>>(Wo, wh, wl, nw4);
    gemm_mma<<<ggrid, 256>>>(yh, yl, wh, wl, bo, out, MROWS, CDIM, CDIM);
}

// round 6
// speedup vs baseline: 3.2032x; 1.1245x over previous
#include <cuda_runtime.h>
#include <cuda_bf16.h>
#include <math.h>
#include <stdint.h>

// Problem constants
#define BATCH 2
#define TSEQ  2048
#define CDIM  1024
#define NHEAD 16
#define HDIM  64
#define MROWS (BATCH * TSEQ)   // 4096

// ---------------------------------------------------------------------------
// Scratch (allocation-free: __device__ globals)
// ---------------------------------------------------------------------------
__device__ __align__(16) __nv_bfloat16 g_xh[MROWS * CDIM];
__device__ __align__(16) __nv_bfloat16 g_xl[MROWS * CDIM];
__device__ __align__(16) __nv_bfloat16 g_qh[MROWS * CDIM];
__device__ __align__(16) __nv_bfloat16 g_ql[MROWS * CDIM];
__device__ __align__(16) __nv_bfloat16 g_kh[MROWS * CDIM];
__device__ __align__(16) __nv_bfloat16 g_kl[MROWS * CDIM];
__device__ __align__(16) __nv_bfloat16 g_vh[MROWS * CDIM];
__device__ __align__(16) __nv_bfloat16 g_vl[MROWS * CDIM];
__device__ __align__(16) __nv_bfloat16 g_yh[MROWS * CDIM];
__device__ __align__(16) __nv_bfloat16 g_yl[MROWS * CDIM];
__device__ __align__(16) __nv_bfloat16 g_wh[CDIM * CDIM];
__device__ __align__(16) __nv_bfloat16 g_wl[CDIM * CDIM];

// ---------------------------------------------------------------------------
// PTX helpers (all baseline PTX, valid for compute_103)
// ---------------------------------------------------------------------------
__device__ __forceinline__ void mma16816(float* c, const uint32_t* a,
                                         const uint32_t* b) {
    asm volatile(
        "mma.sync.aligned.m16n8k16.row.col.f32.bf16.bf16.f32 "
        "{%0,%1,%2,%3}, {%4,%5,%6,%7}, {%8,%9}, {%0,%1,%2,%3};"
        : "+f"(c[0]), "+f"(c[1]), "+f"(c[2]), "+f"(c[3])
        : "r"(a[0]), "r"(a[1]), "r"(a[2]), "r"(a[3]), "r"(b[0]), "r"(b[1]));
}

__device__ __forceinline__ void ldmatrix_x2_trans(uint32_t& b0, uint32_t& b1,
                                                  uint32_t saddr) {
    asm volatile(
        "ldmatrix.sync.aligned.m8n8.x2.trans.shared.b16 {%0,%1}, [%2];"
        : "=r"(b0), "=r"(b1) : "r"(saddr));
}

__device__ __forceinline__ uint32_t smem_u32(const void* p) {
    uint32_t a;
    asm("{ .reg .u64 t; cvta.to.shared.u64 t, %1; cvt.u32.u64 %0, t; }"
        : "=r"(a) : "l"(p));
    return a;
}

__device__ __forceinline__ uint32_t packbf(__nv_bfloat16 a, __nv_bfloat16 b) {
    __nv_bfloat162 t = __halves2bfloat162(a, b);
    return *(uint32_t*)&t;
}

// split two fp32 -> packed hi b32 + packed lo b32
__device__ __forceinline__ void split2(float a, float b,
                                       uint32_t& hi, uint32_t& lo) {
    __nv_bfloat16 ha = __float2bfloat16(a);
    __nv_bfloat16 hb = __float2bfloat16(b);
    __nv_bfloat16 la = __float2bfloat16(a - __bfloat162float(ha));
    __nv_bfloat16 lb = __float2bfloat16(b - __bfloat162float(hb));
    hi = packbf(ha, hb);
    lo = packbf(la, lb);
}

// ---------------------------------------------------------------------------
// Split fp32 -> (hi bf16, lo bf16)
// ---------------------------------------------------------------------------
__global__ void __launch_bounds__(256)
split_kernel(const float* __restrict__ in, __nv_bfloat16* __restrict__ hi,
             __nv_bfloat16* __restrict__ lo, int n4)
{
    int i = blockIdx.x * blockDim.x + threadIdx.x;
    if (i >= n4) return;
    float4 v = ((const float4*)in)[i];
    uint32_t h01, l01, h23, l23;
    split2(v.x, v.y, h01, l01);
    split2(v.z, v.w, h23, l23);
    ((uint32_t*)hi)[2 * i]     = h01;
    ((uint32_t*)hi)[2 * i + 1] = h23;
    ((uint32_t*)lo)[2 * i]     = l01;
    ((uint32_t*)lo)[2 * i + 1] = l23;
}

// ---------------------------------------------------------------------------
// HMMA GEMM: C = A[M,K] @ B[N,K]^T + bias, hi/lo bf16 split inputs (3 MMAs).
// CTA tile 128x128, K-chunk 32, 8 warps 4(M)x2(N), warp tile 32x64.
// BF16OUT=1: write hi/lo bf16 outputs; else fp32.
// ---------------------------------------------------------------------------
#define SSTR 20   // b32 per smem row

template<int BF16OUT>
__global__ void __launch_bounds__(256)
gemm_mma(const __nv_bfloat16* __restrict__ Ah, const __nv_bfloat16* __restrict__ Al,
         const __nv_bfloat16* __restrict__ Bh, const __nv_bfloat16* __restrict__ Bl,
         const float* __restrict__ bias, float* __restrict__ C,
         __nv_bfloat16* __restrict__ Ch, __nv_bfloat16* __restrict__ Cl,
         int M, int N, int K)
{
    __shared__ uint32_t sAh[128 * SSTR], sAl[128 * SSTR];
    __shared__ uint32_t sBh[128 * SSTR], sBl[128 * SSTR];

    const int tid  = threadIdx.x;
    const int lane = tid & 31;
    const int warp = tid >> 5;
    const int wm   = (warp >> 1) * 32;
    const int wn   = (warp & 1) * 64;
    const int m0   = blockIdx.y * 128;
    const int n0   = blockIdx.x * 128;

    int sidx[2];
    size_t gA[2], gB[2];
    #pragma unroll
    for (int t = 0; t < 2; t++) {
        int f   = tid + t * 256;
        int row = f >> 2;
        int c4  = (f & 3) * 4;
        sidx[t] = row * SSTR + c4;
        gA[t] = (size_t)(m0 + row) * K + c4 * 2;
        gB[t] = (size_t)(n0 + row) * K + c4 * 2;
    }

    const int fr = lane >> 2;
    const int fc = lane & 3;

    float acc[2][8][4];
    #pragma unroll
    for (int mt = 0; mt < 2; mt++)
        #pragma unroll
        for (int nt = 0; nt < 8; nt++)
            #pragma unroll
            for (int j = 0; j < 4; j++) acc[mt][nt][j] = 0.f;

    uint4 pah[2], pal[2], pbh[2], pbl[2];
    #pragma unroll
    for (int t = 0; t < 2; t++) {
        pah[t] = *(const uint4*)(Ah + gA[t]);
        pal[t] = *(const uint4*)(Al + gA[t]);
        pbh[t] = *(const uint4*)(Bh + gB[t]);
        pbl[t] = *(const uint4*)(Bl + gB[t]);
    }

    const int nchunks = K / 32;
    for (int kc = 0; kc < nchunks; kc++) {
        #pragma unroll
        for (int t = 0; t < 2; t++) {
            *(uint4*)&sAh[sidx[t]] = pah[t];
            *(uint4*)&sAl[sidx[t]] = pal[t];
            *(uint4*)&sBh[sidx[t]] = pbh[t];
            *(uint4*)&sBl[sidx[t]] = pbl[t];
        }
        __syncthreads();

        if (kc + 1 < nchunks) {
            int ko = (kc + 1) * 32;
            #pragma unroll
            for (int t = 0; t < 2; t++) {
                pah[t] = *(const uint4*)(Ah + gA[t] + ko);
                pal[t] = *(const uint4*)(Al + gA[t] + ko);
                pbh[t] = *(const uint4*)(Bh + gB[t] + ko);
                pbl[t] = *(const uint4*)(Bl + gB[t] + ko);
            }
        }

        #pragma unroll
        for (int ks = 0; ks < 2; ks++) {
            const int kb = ks * 8;
            uint32_t afh[2][4], afl[2][4];
            #pragma unroll
            for (int mt = 0; mt < 2; mt++) {
                int r0 = wm + mt * 16 + fr;
                afh[mt][0] = sAh[ r0      * SSTR + kb + fc];
                afh[mt][1] = sAh[(r0 + 8) * SSTR + kb + fc];
                afh[mt][2] = sAh[ r0      * SSTR + kb + fc + 4];
                afh[mt][3] = sAh[(r0 + 8) * SSTR + kb + fc + 4];
                afl[mt][0] = sAl[ r0      * SSTR + kb + fc];
                afl[mt][1] = sAl[(r0 + 8) * SSTR + kb + fc];
                afl[mt][2] = sAl[ r0      * SSTR + kb + fc + 4];
                afl[mt][3] = sAl[(r0 + 8) * SSTR + kb + fc + 4];
            }
            #pragma unroll
            for (int nt = 0; nt < 8; nt++) {
                int nr = wn + nt * 8 + fr;
                uint32_t bfh[2], bfl[2];
                bfh[0] = sBh[nr * SSTR + kb + fc];
                bfh[1] = sBh[nr * SSTR + kb + fc + 4];
                bfl[0] = sBl[nr * SSTR + kb + fc];
                bfl[1] = sBl[nr * SSTR + kb + fc + 4];
                #pragma unroll
                for (int mt = 0; mt < 2; mt++) {
                    mma16816(acc[mt][nt], afh[mt], bfh);
                    mma16816(acc[mt][nt], afh[mt], bfl);
                    mma16816(acc[mt][nt], afl[mt], bfh);
                }
            }
        }
        __syncthreads();
    }

    #pragma unroll
    for (int mt = 0; mt < 2; mt++) {
        #pragma unroll
        for (int nt = 0; nt < 8; nt++) {
            int row = m0 + wm + mt * 16 + fr;
            int col = n0 + wn + nt * 8 + fc * 2;
            float b0 = __ldg(&bias[col]);
            float b1 = __ldg(&bias[col + 1]);
            float c0 = acc[mt][nt][0] + b0, c1 = acc[mt][nt][1] + b1;
            float c2 = acc[mt][nt][2] + b0, c3 = acc[mt][nt][3] + b1;
            if (BF16OUT) {
                uint32_t hi, lo;
                split2(c0, c1, hi, lo);
                *(uint32_t*)&Ch[(size_t)row * N + col] = hi;
                *(uint32_t*)&Cl[(size_t)row * N + col] = lo;
                split2(c2, c3, hi, lo);
                *(uint32_t*)&Ch[(size_t)(row + 8) * N + col] = hi;
                *(uint32_t*)&Cl[(size_t)(row + 8) * N + col] = lo;
            } else {
                *(float2*)&C[(size_t)row * N + col]       = make_float2(c0, c1);
                *(float2*)&C[(size_t)(row + 8) * N + col] = make_float2(c2, c3);
            }
        }
    }
}

// ---------------------------------------------------------------------------
// HMMA flash attention (causal), pre-split bf16 inputs/outputs.
// One CTA per (b*h, 128-row q tile); 8 warps, 16 q rows each; Bc = 64.
// S = QK^T 3 MMAs (hi/lo); P split in regs; PV 3 MMAs, V via ldmatrix.trans.
// smem (u32): qh/ql 128*36 each, kh/kl 64*36 each, vh/vl 64*36 each (bf16 rows
// of 72 = 64 data + 8 pad).
// ---------------------------------------------------------------------------
#define QSTR 36
#define ATTN_SMEM_B32 (2 * 128 * QSTR + 4 * 64 * QSTR)   // 18432 u32 = 73728 B

__global__ void __launch_bounds__(256)
attn_mma(const __nv_bfloat16* __restrict__ Qh, const __nv_bfloat16* __restrict__ Ql,
         const __nv_bfloat16* __restrict__ Kh, const __nv_bfloat16* __restrict__ Kl,
         const __nv_bfloat16* __restrict__ Vh, const __nv_bfloat16* __restrict__ Vl,
         __nv_bfloat16* __restrict__ Yh, __nv_bfloat16* __restrict__ Yl)
{
    extern __shared__ uint32_t s32[];
    uint32_t* qh = s32;
    uint32_t* ql = qh + 128 * QSTR;
    uint32_t* kh = ql + 128 * QSTR;
    uint32_t* kl = kh + 64 * QSTR;
    uint32_t* vh = kl + 64 * QSTR;
    uint32_t* vl = vh + 64 * QSTR;

    const int qt = blockIdx.x;
    const int bh = blockIdx.y;
    const int b  = bh >> 4;
    const int h  = bh & 15;
    const size_t headoff = (size_t)b * TSEQ * CDIM + (size_t)h * HDIM;

    const int tid  = threadIdx.x;
    const int lane = tid & 31;
    const int warp = tid >> 5;
    const int fr   = lane >> 2;
    const int fc   = lane & 3;
    const int wm   = warp * 16;

    const uint32_t vhb = smem_u32(vh);
    const uint32_t vlb = smem_u32(vl);

    // ---- load Q tile 128x64 (hi+lo bf16) ----
    #pragma unroll
    for (int t = 0; t < 4; t++) {
        int f  = tid + t * 256;
        int r  = f >> 3;          // 0..127
        int c8 = f & 7;           // uint4 within row
        size_t g = headoff + (size_t)(qt * 128 + r) * CDIM + c8 * 8;
        *(uint4*)&qh[r * QSTR + c8 * 4] = *(const uint4*)(Qh + g);
        *(uint4*)&ql[r * QSTR + c8 * 4] = *(const uint4*)(Ql + g);
    }

    const float scale = 0.125f;
    float o[8][4];
    #pragma unroll
    for (int nt = 0; nt < 8; nt++)
        #pragma unroll
        for (int j = 0; j < 4; j++) o[nt][j] = 0.f;
    float mA = -INFINITY, mB = -INFINITY, lA = 0.f, lB = 0.f;

    const int rowAg = qt * 128 + wm + fr;
    const int rowBg = rowAg + 8;

    const int ktmax = 2 * qt + 1;
    for (int kt = 0; kt <= ktmax; kt++) {
        __syncthreads();

        // ---- load K/V tiles 64x64 (hi+lo bf16), natural layout ----
        #pragma unroll
        for (int t = 0; t < 2; t++) {
            int f  = tid + t * 256;
            int r  = f >> 3;      // 0..63
            int c8 = f & 7;
            size_t g = headoff + (size_t)(kt * 64 + r) * CDIM + c8 * 8;
            int si = r * QSTR + c8 * 4;
            *(uint4*)&kh[si] = *(const uint4*)(Kh + g);
            *(uint4*)&kl[si] = *(const uint4*)(Kl + g);
            *(uint4*)&vh[si] = *(const uint4*)(Vh + g);
            *(uint4*)&vl[si] = *(const uint4*)(Vl + g);
        }
        __syncthreads();

        // ---- S = Q K^T ----
        float sacc[8][4];
        #pragma unroll
        for (int nt = 0; nt < 8; nt++)
            #pragma unroll
            for (int j = 0; j < 4; j++) sacc[nt][j] = 0.f;

        #pragma unroll
        for (int ks = 0; ks < 4; ks++) {
            const int kb = ks * 8;
            uint32_t ah[4], al[4];
            ah[0] = qh[(wm + fr)     * QSTR + kb + fc];
            ah[1] = qh[(wm + fr + 8) * QSTR + kb + fc];
            ah[2] = qh[(wm + fr)     * QSTR + kb + fc + 4];
            ah[3] = qh[(wm + fr + 8) * QSTR + kb + fc + 4];
            al[0] = ql[(wm + fr)     * QSTR + kb + fc];
            al[1] = ql[(wm + fr + 8) * QSTR + kb + fc];
            al[2] = ql[(wm + fr)     * QSTR + kb + fc + 4];
            al[3] = ql[(wm + fr + 8) * QSTR + kb + fc + 4];
            #pragma unroll
            for (int nt = 0; nt < 8; nt++) {
                int nr = nt * 8 + fr;
                uint32_t bh2[2], bl2[2];
                bh2[0] = kh[nr * QSTR + kb + fc];
                bh2[1] = kh[nr * QSTR + kb + fc + 4];
                bl2[0] = kl[nr * QSTR + kb + fc];
                bl2[1] = kl[nr * QSTR + kb + fc + 4];
                mma16816(sacc[nt], ah, bh2);
                mma16816(sacc[nt], ah, bl2);
                mma16816(sacc[nt], al, bh2);
            }
        }

        // ---- scale + causal mask ----
        const bool diag = (kt >= 2 * qt);
        #pragma unroll
        for (int nt = 0; nt < 8; nt++) {
            #pragma unroll
            for (int j = 0; j < 4; j++) sacc[nt][j] *= scale;
            if (diag) {
                int col0 = kt * 64 + nt * 8 + 2 * fc;
                if (col0     > rowAg) sacc[nt][0] = -INFINITY;
                if (col0 + 1 > rowAg) sacc[nt][1] = -INFINITY;
                if (col0     > rowBg) sacc[nt][2] = -INFINITY;
                if (col0 + 1 > rowBg) sacc[nt][3] = -INFINITY;
            }
        }

        // ---- online softmax ----
        float mxA = -INFINITY, mxB = -INFINITY;
        #pragma unroll
        for (int nt = 0; nt < 8; nt++) {
            mxA = fmaxf(mxA, fmaxf(sacc[nt][0], sacc[nt][1]));
            mxB = fmaxf(mxB, fmaxf(sacc[nt][2], sacc[nt][3]));
        }
        mxA = fmaxf(mxA, __shfl_xor_sync(0xffffffffu, mxA, 1));
        mxA = fmaxf(mxA, __shfl_xor_sync(0xffffffffu, mxA, 2));
        mxB = fmaxf(mxB, __shfl_xor_sync(0xffffffffu, mxB, 1));
        mxB = fmaxf(mxB, __shfl_xor_sync(0xffffffffu, mxB, 2));

        float mnA = fmaxf(mA, mxA), mnB = fmaxf(mB, mxB);
        float aA = __expf(mA - mnA), aB = __expf(mB - mnB);
        mA = mnA; mB = mnB;

        float lsA = 0.f, lsB = 0.f;
        #pragma unroll
        for (int nt = 0; nt < 8; nt++) {
            sacc[nt][0] = __expf(sacc[nt][0] - mnA);
            sacc[nt][1] = __expf(sacc[nt][1] - mnA);
            sacc[nt][2] = __expf(sacc[nt][2] - mnB);
            sacc[nt][3] = __expf(sacc[nt][3] - mnB);
            lsA += sacc[nt][0] + sacc[nt][1];
            lsB += sacc[nt][2] + sacc[nt][3];
        }
        lsA += __shfl_xor_sync(0xffffffffu, lsA, 1);
        lsA += __shfl_xor_sync(0xffffffffu, lsA, 2);
        lsB += __shfl_xor_sync(0xffffffffu, lsB, 1);
        lsB += __shfl_xor_sync(0xffffffffu, lsB, 2);
        lA = lA * aA + lsA;
        lB = lB * aB + lsB;

        #pragma unroll
        for (int nt = 0; nt < 8; nt++) {
            o[nt][0] *= aA; o[nt][1] *= aA;
            o[nt][2] *= aB; o[nt][3] *= aB;
        }

        // ---- O += P V (P split in regs; V via ldmatrix.trans) ----
        #pragma unroll
        for (int ks = 0; ks < 4; ks++) {
            uint32_t ph[4], pl[4];
            split2(sacc[2 * ks][0],     sacc[2 * ks][1],     ph[0], pl[0]);
            split2(sacc[2 * ks][2],     sacc[2 * ks][3],     ph[1], pl[1]);
            split2(sacc[2 * ks + 1][0], sacc[2 * ks + 1][1], ph[2], pl[2]);
            split2(sacc[2 * ks + 1][2], sacc[2 * ks + 1][3], ph[3], pl[3]);
            // row address for this lane: kv row = ks*16 + (lane&15)
            const uint32_t roff = (uint32_t)(ks * 16 + (lane & 15)) * (QSTR * 4);
            #pragma unroll
            for (int nt = 0; nt < 8; nt++) {
                uint32_t vh2[2], vl2[2];
                ldmatrix_x2_trans(vh2[0], vh2[1], vhb + roff + nt * 16);
                ldmatrix_x2_trans(vl2[0], vl2[1], vlb + roff + nt * 16);
                mma16816(o[nt], ph, vh2);
                mma16816(o[nt], ph, vl2);
                mma16816(o[nt], pl, vh2);
            }
        }
    }

    // ---- normalize + write hi/lo bf16 ----
    float liA = 1.0f / lA, liB = 1.0f / lB;
    #pragma unroll
    for (int nt = 0; nt < 8; nt++) {
        int col = nt * 8 + 2 * fc;
        size_t gA = headoff + (size_t)rowAg * CDIM + col;
        size_t gB = headoff + (size_t)rowBg * CDIM + col;
        uint32_t hi, lo;
        split2(o[nt][0] * liA, o[nt][1] * liA, hi, lo);
        *(uint32_t*)&Yh[gA] = hi;
        *(uint32_t*)&Yl[gA] = lo;
        split2(o[nt][2] * liB, o[nt][3] * liB, hi, lo);
        *(uint32_t*)&Yh[gB] = hi;
        *(uint32_t*)&Yl[gB] = lo;
    }
}

// ---------------------------------------------------------------------------
// Launch
// ---------------------------------------------------------------------------
extern "C" void kernel_launch(void* const* d_in, const int* in_sizes, int n_in,
                              void* d_out, int out_size)
{
    const float* x  = (const float*)d_in[0];
    const float* Wq = (const float*)d_in[1];
    const float* bq = (const float*)d_in[2];
    const float* Wk = (const float*)d_in[3];
    const float* bk = (const float*)d_in[4];
    const float* Wv = (const float*)d_in[5];
    const float* bv = (const float*)d_in[6];
    const float* Wo = (const float*)d_in[7];
    const float* bo = (const float*)d_in[8];
    float* out = (float*)d_out;

    __nv_bfloat16 *xh, *xl, *qh, *ql, *kh, *kl, *vh, *vl, *yh, *yl, *wh, *wl;
    cudaGetSymbolAddress((void**)&xh, g_xh);
    cudaGetSymbolAddress((void**)&xl, g_xl);
    cudaGetSymbolAddress((void**)&qh, g_qh);
    cudaGetSymbolAddress((void**)&ql, g_ql);
    cudaGetSymbolAddress((void**)&kh, g_kh);
    cudaGetSymbolAddress((void**)&kl, g_kl);
    cudaGetSymbolAddress((void**)&vh, g_vh);
    cudaGetSymbolAddress((void**)&vl, g_vl);
    cudaGetSymbolAddress((void**)&yh, g_yh);
    cudaGetSymbolAddress((void**)&yl, g_yl);
    cudaGetSymbolAddress((void**)&wh, g_wh);
    cudaGetSymbolAddress((void**)&wl, g_wl);

    const int attn_smem = ATTN_SMEM_B32 * 4;   // 73728 B
    cudaFuncSetAttribute(attn_mma,
                         cudaFuncAttributeMaxDynamicSharedMemorySize, attn_smem);

    const int nx4 = MROWS * CDIM / 4;
    const int nw4 = CDIM * CDIM / 4;

    dim3 ggrid(CDIM / 128, MROWS / 128);   // (8, 32)

    split_kernel<<<nx4 / 256, 256>>>(x, xh, xl, nx4);

    split_kernel<<<nw4 / 256, 256>>>(Wq, wh, wl, nw4);
    gemm_mma<1><<<ggrid, 256>>>(xh, xl, wh, wl, bq, nullptr, qh, ql,
                                MROWS, CDIM, CDIM);
    split_kernel<<<nw4 / 256, 256>>>(Wk, wh, wl, nw4);
    gemm_mma<1><<<ggrid, 256>>>(xh, xl, wh, wl, bk, nullptr, kh, kl,
                                MROWS, CDIM, CDIM);
    split_kernel<<<nw4 / 256, 256>>>(Wv, wh, wl, nw4);
    gemm_mma<1><<<ggrid, 256>>>(xh, xl, wh, wl, bv, nullptr, vh, vl,
                                MROWS, CDIM, CDIM);

    dim3 agrid(TSEQ / 128, BATCH * NHEAD);  // (16, 32)
    attn_mma<<<agrid, 256, attn_smem>>>(qh, ql, kh, kl, vh, vl, yh, yl);

    split_kernel<<<nw4 / 256, 256>>>(Wo, wh, wl, nw4);
    gemm_mma<0><<<ggrid, 256>>>(yh, yl, wh, wl, bo, out, nullptr, nullptr,
                                MROWS, CDIM, CDIM);
}

// round 7
// speedup vs baseline: 3.2880x; 1.0265x over previous
#include <cuda_runtime.h>
#include <cuda_bf16.h>
#include <math.h>
#include <stdint.h>

// Problem constants
#define BATCH 2
#define TSEQ  2048
#define CDIM  1024
#define NHEAD 16
#define HDIM  64
#define MROWS (BATCH * TSEQ)   // 4096

// ---------------------------------------------------------------------------
// Scratch (allocation-free: __device__ globals)
// ---------------------------------------------------------------------------
__device__ __align__(16) __nv_bfloat16 g_xh[MROWS * CDIM];
__device__ __align__(16) __nv_bfloat16 g_xl[MROWS * CDIM];
__device__ __align__(16) __nv_bfloat16 g_qh[MROWS * CDIM];
__device__ __align__(16) __nv_bfloat16 g_ql[MROWS * CDIM];
__device__ __align__(16) __nv_bfloat16 g_kh[MROWS * CDIM];
__device__ __align__(16) __nv_bfloat16 g_kl[MROWS * CDIM];
__device__ __align__(16) __nv_bfloat16 g_vh[MROWS * CDIM];
__device__ __align__(16) __nv_bfloat16 g_vl[MROWS * CDIM];
__device__ __align__(16) __nv_bfloat16 g_yh[MROWS * CDIM];
__device__ __align__(16) __nv_bfloat16 g_yl[MROWS * CDIM];
__device__ __align__(16) __nv_bfloat16 g_wqh[CDIM * CDIM], g_wql[CDIM * CDIM];
__device__ __align__(16) __nv_bfloat16 g_wkh[CDIM * CDIM], g_wkl[CDIM * CDIM];
__device__ __align__(16) __nv_bfloat16 g_wvh[CDIM * CDIM], g_wvl[CDIM * CDIM];
__device__ __align__(16) __nv_bfloat16 g_woh[CDIM * CDIM], g_wol[CDIM * CDIM];

// ---------------------------------------------------------------------------
// PTX helpers (all baseline PTX, valid for compute_103)
// ---------------------------------------------------------------------------
__device__ __forceinline__ void mma16816(float* c, const uint32_t* a,
                                         const uint32_t* b) {
    asm volatile(
        "mma.sync.aligned.m16n8k16.row.col.f32.bf16.bf16.f32 "
        "{%0,%1,%2,%3}, {%4,%5,%6,%7}, {%8,%9}, {%0,%1,%2,%3};"
        : "+f"(c[0]), "+f"(c[1]), "+f"(c[2]), "+f"(c[3])
        : "r"(a[0]), "r"(a[1]), "r"(a[2]), "r"(a[3]), "r"(b[0]), "r"(b[1]));
}

__device__ __forceinline__ void ldm_x4(uint32_t* r, uint32_t saddr) {
    asm volatile(
        "ldmatrix.sync.aligned.m8n8.x4.shared.b16 {%0,%1,%2,%3}, [%4];"
        : "=r"(r[0]), "=r"(r[1]), "=r"(r[2]), "=r"(r[3]) : "r"(saddr));
}

__device__ __forceinline__ void ldm_x4_trans(uint32_t* r, uint32_t saddr) {
    asm volatile(
        "ldmatrix.sync.aligned.m8n8.x4.trans.shared.b16 {%0,%1,%2,%3}, [%4];"
        : "=r"(r[0]), "=r"(r[1]), "=r"(r[2]), "=r"(r[3]) : "r"(saddr));
}

__device__ __forceinline__ uint32_t smem_u32(const void* p) {
    uint32_t a;
    asm("{ .reg .u64 t; cvta.to.shared.u64 t, %1; cvt.u32.u64 %0, t; }"
        : "=r"(a) : "l"(p));
    return a;
}

__device__ __forceinline__ void cpa16(uint32_t s, const void* g) {
    asm volatile("cp.async.cg.shared.global [%0], [%1], 16;"
                 :: "r"(s), "l"(g));
}
__device__ __forceinline__ void cpa_commit() {
    asm volatile("cp.async.commit_group;");
}
template<int N> __device__ __forceinline__ void cpa_wait() {
    asm volatile("cp.async.wait_group %0;" :: "n"(N));
}

__device__ __forceinline__ uint32_t packbf(__nv_bfloat16 a, __nv_bfloat16 b) {
    __nv_bfloat162 t = __halves2bfloat162(a, b);
    return *(uint32_t*)&t;
}

__device__ __forceinline__ void split2(float a, float b,
                                       uint32_t& hi, uint32_t& lo) {
    __nv_bfloat16 ha = __float2bfloat16(a);
    __nv_bfloat16 hb = __float2bfloat16(b);
    __nv_bfloat16 la = __float2bfloat16(a - __bfloat162float(ha));
    __nv_bfloat16 lb = __float2bfloat16(b - __bfloat162float(hb));
    hi = packbf(ha, hb);
    lo = packbf(la, lb);
}

// ---------------------------------------------------------------------------
// Split fp32 -> (hi bf16, lo bf16)
// ---------------------------------------------------------------------------
__global__ void __launch_bounds__(256)
split_kernel(const float* __restrict__ in, __nv_bfloat16* __restrict__ hi,
             __nv_bfloat16* __restrict__ lo, int n4)
{
    int i = blockIdx.x * blockDim.x + threadIdx.x;
    if (i >= n4) return;
    float4 v = ((const float4*)in)[i];
    uint32_t h01, l01, h23, l23;
    split2(v.x, v.y, h01, l01);
    split2(v.z, v.w, h23, l23);
    ((uint32_t*)hi)[2 * i]     = h01;
    ((uint32_t*)hi)[2 * i + 1] = h23;
    ((uint32_t*)lo)[2 * i]     = l01;
    ((uint32_t*)lo)[2 * i + 1] = l23;
}

// ---------------------------------------------------------------------------
// HMMA GEMM: C = A[M,K] @ B[N,K]^T + bias. hi/lo split (3 MMAs).
// CTA tile 128x128, K-chunk 32, double-buffered cp.async, ldmatrix frags.
// ---------------------------------------------------------------------------
#define SSTR  20                     // u32 per smem row
#define GARR  (128 * SSTR)           // u32 per array (2560)
#define GARRB (GARR * 4)             // bytes per array (10240)
#define GBUFB (4 * GARRB)            // bytes per buffer (40960)
#define GEMM_SMEM (2 * GBUFB)        // 81920

template<int BF16OUT>
__global__ void __launch_bounds__(256)
gemm_mma(const __nv_bfloat16* __restrict__ Ah, const __nv_bfloat16* __restrict__ Al,
         const __nv_bfloat16* __restrict__ Bh, const __nv_bfloat16* __restrict__ Bl,
         const float* __restrict__ bias, float* __restrict__ C,
         __nv_bfloat16* __restrict__ Ch, __nv_bfloat16* __restrict__ Cl,
         int M, int N, int K)
{
    extern __shared__ uint32_t sg[];
    const uint32_t sbase = smem_u32(sg);

    const int tid  = threadIdx.x;
    const int lane = tid & 31;
    const int warp = tid >> 5;
    const int wm   = (warp >> 1) * 32;
    const int wn   = (warp & 1) * 64;
    const int m0   = blockIdx.y * 128;
    const int n0   = blockIdx.x * 128;

    // cp.async slots: f = tid + t*256, row = f>>2, u32col = (f&3)*4
    uint32_t s_off[2];
    size_t gA[2], gB[2];
    #pragma unroll
    for (int t = 0; t < 2; t++) {
        int f   = tid + t * 256;
        int row = f >> 2;
        int c4  = (f & 3) * 4;
        s_off[t] = (uint32_t)(row * SSTR + c4) * 4;
        gA[t] = (size_t)(m0 + row) * K + c4 * 2;
        gB[t] = (size_t)(n0 + row) * K + c4 * 2;
    }

    // ldmatrix lane addressing
    const int arow  = (lane & 7) + ((lane >> 3) & 1) * 8;
    const int acol  = (lane >> 4) * 4;
    const int brow  = (lane & 7) + (lane >> 4) * 8;
    const int bcol4 = ((lane >> 3) & 1) * 4;

    uint32_t aoff[2], boff[4];
    #pragma unroll
    for (int mt = 0; mt < 2; mt++)
        aoff[mt] = (uint32_t)((wm + mt * 16 + arow) * SSTR + acol) * 4;
    #pragma unroll
    for (int np = 0; np < 4; np++)
        boff[np] = (uint32_t)((wn + np * 16 + brow) * SSTR + bcol4) * 4;

    const int fr = lane >> 2;
    const int fc = lane & 3;

    float acc[2][8][4];
    #pragma unroll
    for (int mt = 0; mt < 2; mt++)
        #pragma unroll
        for (int nt = 0; nt < 8; nt++)
            #pragma unroll
            for (int j = 0; j < 4; j++) acc[mt][nt][j] = 0.f;

    const int nchunks = K / 32;

    // prefetch chunk 0 into buffer 0
    #pragma unroll
    for (int t = 0; t < 2; t++) {
        cpa16(sbase + 0 * GARRB + s_off[t], Ah + gA[t]);
        cpa16(sbase + 1 * GARRB + s_off[t], Al + gA[t]);
        cpa16(sbase + 2 * GARRB + s_off[t], Bh + gB[t]);
        cpa16(sbase + 3 * GARRB + s_off[t], Bl + gB[t]);
    }
    cpa_commit();

    for (int kc = 0; kc < nchunks; kc++) {
        if (kc + 1 < nchunks) {
            const uint32_t bb = sbase + ((kc + 1) & 1) * GBUFB;
            const int ko = (kc + 1) * 32;
            #pragma unroll
            for (int t = 0; t < 2; t++) {
                cpa16(bb + 0 * GARRB + s_off[t], Ah + gA[t] + ko);
                cpa16(bb + 1 * GARRB + s_off[t], Al + gA[t] + ko);
                cpa16(bb + 2 * GARRB + s_off[t], Bh + gB[t] + ko);
                cpa16(bb + 3 * GARRB + s_off[t], Bl + gB[t] + ko);
            }
            cpa_commit();
            cpa_wait<1>();
        } else {
            cpa_wait<0>();
        }
        __syncthreads();

        const uint32_t cb  = sbase + (kc & 1) * GBUFB;
        const uint32_t aAh = cb, aAl = cb + GARRB;
        const uint32_t aBh = cb + 2 * GARRB, aBl = cb + 3 * GARRB;

        #pragma unroll
        for (int ks = 0; ks < 2; ks++) {
            const uint32_t kbb = (uint32_t)(ks * 8) * 4;
            uint32_t afh[2][4], afl[2][4];
            #pragma unroll
            for (int mt = 0; mt < 2; mt++) {
                ldm_x4(afh[mt], aAh + aoff[mt] + kbb);
                ldm_x4(afl[mt], aAl + aoff[mt] + kbb);
            }
            #pragma unroll
            for (int np = 0; np < 4; np++) {
                uint32_t b4h[4], b4l[4];
                ldm_x4(b4h, aBh + boff[np] + kbb);
                ldm_x4(b4l, aBl + boff[np] + kbb);
                #pragma unroll
                for (int hf = 0; hf < 2; hf++) {
                    const int nt = np * 2 + hf;
                    #pragma unroll
                    for (int mt = 0; mt < 2; mt++) {
                        mma16816(acc[mt][nt], afh[mt], &b4h[hf * 2]);
                        mma16816(acc[mt][nt], afh[mt], &b4l[hf * 2]);
                        mma16816(acc[mt][nt], afl[mt], &b4h[hf * 2]);
                    }
                }
            }
        }
        __syncthreads();
    }

    #pragma unroll
    for (int mt = 0; mt < 2; mt++) {
        #pragma unroll
        for (int nt = 0; nt < 8; nt++) {
            int row = m0 + wm + mt * 16 + fr;
            int col = n0 + wn + nt * 8 + fc * 2;
            float b0 = __ldg(&bias[col]);
            float b1 = __ldg(&bias[col + 1]);
            float c0 = acc[mt][nt][0] + b0, c1 = acc[mt][nt][1] + b1;
            float c2 = acc[mt][nt][2] + b0, c3 = acc[mt][nt][3] + b1;
            if (BF16OUT) {
                uint32_t hi, lo;
                split2(c0, c1, hi, lo);
                *(uint32_t*)&Ch[(size_t)row * N + col] = hi;
                *(uint32_t*)&Cl[(size_t)row * N + col] = lo;
                split2(c2, c3, hi, lo);
                *(uint32_t*)&Ch[(size_t)(row + 8) * N + col] = hi;
                *(uint32_t*)&Cl[(size_t)(row + 8) * N + col] = lo;
            } else {
                *(float2*)&C[(size_t)row * N + col]       = make_float2(c0, c1);
                *(float2*)&C[(size_t)(row + 8) * N + col] = make_float2(c2, c3);
            }
        }
    }
}

// ---------------------------------------------------------------------------
// HMMA flash attention (causal). Pre-split bf16 in/out. 128-row q tile/CTA,
// Bc=64. cp.async double-buffered KV, ldmatrix frags, longest-qt-first order.
// smem (u32): qh 4608 | ql 4608 | 2 x { kh 2304, kl 2304, vh 2304, vl 2304 }
// ---------------------------------------------------------------------------
#define QSTR 36
#define QARR (128 * QSTR)              // 4608 u32
#define KARR (64 * QSTR)               // 2304 u32
#define KBUF (4 * KARR)                // u32 per kv buffer
#define ATTN_SMEM ((2 * QARR + 2 * KBUF) * 4)   // 110592 B

__global__ void __launch_bounds__(256)
attn_mma(const __nv_bfloat16* __restrict__ Qh, const __nv_bfloat16* __restrict__ Ql,
         const __nv_bfloat16* __restrict__ Kh, const __nv_bfloat16* __restrict__ Kl,
         const __nv_bfloat16* __restrict__ Vh, const __nv_bfloat16* __restrict__ Vl,
         __nv_bfloat16* __restrict__ Yh, __nv_bfloat16* __restrict__ Yl)
{
    extern __shared__ uint32_t s32[];
    const uint32_t sbase = smem_u32(s32);
    const uint32_t aQh = sbase;
    const uint32_t aQl = sbase + QARR * 4;

    const int qt = gridDim.x - 1 - blockIdx.x;   // longest-first
    const int bh = blockIdx.y;
    const int b  = bh >> 4;
    const int h  = bh & 15;
    const size_t headoff = (size_t)b * TSEQ * CDIM + (size_t)h * HDIM;

    const int tid  = threadIdx.x;
    const int lane = tid & 31;
    const int warp = tid >> 5;
    const int fr   = lane >> 2;
    const int fc   = lane & 3;
    const int wm   = warp * 16;

    // ldmatrix lane addressing
    const int arow  = (lane & 7) + ((lane >> 3) & 1) * 8;
    const int acol  = (lane >> 4) * 4;
    const int brow  = (lane & 7) + (lane >> 4) * 8;
    const int bcol4 = ((lane >> 3) & 1) * 4;
    const uint32_t qoff = (uint32_t)((wm + arow) * QSTR + acol) * 4;
    uint32_t koff[4], voff[4];
    #pragma unroll
    for (int np = 0; np < 4; np++) {
        koff[np] = (uint32_t)((np * 16 + brow) * QSTR + bcol4) * 4;
        // V trans: row = k (arow pattern), col pair selected by lane>>4
        voff[np] = (uint32_t)(arow * QSTR + (np * 2 + (lane >> 4)) * 4) * 4;
    }

    // ---- Q tile via cp.async (group 0) ----
    #pragma unroll
    for (int t = 0; t < 4; t++) {
        int f  = tid + t * 256;
        int r  = f >> 3;
        int c8 = f & 7;
        size_t g = headoff + (size_t)(qt * 128 + r) * CDIM + c8 * 8;
        uint32_t so = (uint32_t)(r * QSTR + c8 * 4) * 4;
        cpa16(aQh + so, Qh + g);
        cpa16(aQl + so, Ql + g);
    }
    cpa_commit();

    // kv cp.async slots
    uint32_t kvso[2];
    size_t kvg[2];
    #pragma unroll
    for (int t = 0; t < 2; t++) {
        int f  = tid + t * 256;
        int r  = f >> 3;
        int c8 = f & 7;
        kvso[t] = (uint32_t)(r * QSTR + c8 * 4) * 4;
        kvg[t]  = headoff + (size_t)r * CDIM + c8 * 8;
    }
    const uint32_t kvbase = sbase + 2 * QARR * 4;

    const int ktmax = 2 * qt + 1;

    // prefetch tile 0 into kv buffer 0 (group 1)
    #pragma unroll
    for (int t = 0; t < 2; t++) {
        cpa16(kvbase + 0 * KARR * 4 + kvso[t], Kh + kvg[t]);
        cpa16(kvbase + 1 * KARR * 4 + kvso[t], Kl + kvg[t]);
        cpa16(kvbase + 2 * KARR * 4 + kvso[t], Vh + kvg[t]);
        cpa16(kvbase + 3 * KARR * 4 + kvso[t], Vl + kvg[t]);
    }
    cpa_commit();

    const float scale = 0.125f;
    float o[8][4];
    #pragma unroll
    for (int nt = 0; nt < 8; nt++)
        #pragma unroll
        for (int j = 0; j < 4; j++) o[nt][j] = 0.f;
    float mA = -INFINITY, mB = -INFINITY, lA = 0.f, lB = 0.f;

    const int rowAg = qt * 128 + wm + fr;
    const int rowBg = rowAg + 8;

    for (int kt = 0; kt <= ktmax; kt++) {
        if (kt < ktmax) {
            const uint32_t bb = kvbase + ((kt + 1) & 1) * KBUF * 4;
            const size_t go = (size_t)(kt + 1) * 64 * CDIM;
            #pragma unroll
            for (int t = 0; t < 2; t++) {
                cpa16(bb + 0 * KARR * 4 + kvso[t], Kh + kvg[t] + go);
                cpa16(bb + 1 * KARR * 4 + kvso[t], Kl + kvg[t] + go);
                cpa16(bb + 2 * KARR * 4 + kvso[t], Vh + kvg[t] + go);
                cpa16(bb + 3 * KARR * 4 + kvso[t], Vl + kvg[t] + go);
            }
            cpa_commit();
            cpa_wait<1>();
        } else {
            cpa_wait<0>();
        }
        __syncthreads();

        const uint32_t cb  = kvbase + (kt & 1) * KBUF * 4;
        const uint32_t aKh = cb, aKl = cb + KARR * 4;
        const uint32_t aVh = cb + 2 * KARR * 4, aVl = cb + 3 * KARR * 4;

        // ---- S = Q K^T ----
        float sacc[8][4];
        #pragma unroll
        for (int nt = 0; nt < 8; nt++)
            #pragma unroll
            for (int j = 0; j < 4; j++) sacc[nt][j] = 0.f;

        #pragma unroll
        for (int ks = 0; ks < 4; ks++) {
            const uint32_t kbb = (uint32_t)(ks * 8) * 4;
            uint32_t ah[4], al[4];
            ldm_x4(ah, aQh + qoff + kbb);
            ldm_x4(al, aQl + qoff + kbb);
            #pragma unroll
            for (int np = 0; np < 4; np++) {
                uint32_t k4h[4], k4l[4];
                ldm_x4(k4h, aKh + koff[np] + kbb);
                ldm_x4(k4l, aKl + koff[np] + kbb);
                #pragma unroll
                for (int hf = 0; hf < 2; hf++) {
                    const int nt = np * 2 + hf;
                    mma16816(sacc[nt], ah, &k4h[hf * 2]);
                    mma16816(sacc[nt], ah, &k4l[hf * 2]);
                    mma16816(sacc[nt], al, &k4h[hf * 2]);
                }
            }
        }

        // ---- scale + causal mask ----
        const bool diag = (kt >= 2 * qt);
        #pragma unroll
        for (int nt = 0; nt < 8; nt++) {
            #pragma unroll
            for (int j = 0; j < 4; j++) sacc[nt][j] *= scale;
            if (diag) {
                int col0 = kt * 64 + nt * 8 + 2 * fc;
                if (col0     > rowAg) sacc[nt][0] = -INFINITY;
                if (col0 + 1 > rowAg) sacc[nt][1] = -INFINITY;
                if (col0     > rowBg) sacc[nt][2] = -INFINITY;
                if (col0 + 1 > rowBg) sacc[nt][3] = -INFINITY;
            }
        }

        // ---- online softmax ----
        float mxA = -INFINITY, mxB = -INFINITY;
        #pragma unroll
        for (int nt = 0; nt < 8; nt++) {
            mxA = fmaxf(mxA, fmaxf(sacc[nt][0], sacc[nt][1]));
            mxB = fmaxf(mxB, fmaxf(sacc[nt][2], sacc[nt][3]));
        }
        mxA = fmaxf(mxA, __shfl_xor_sync(0xffffffffu, mxA, 1));
        mxA = fmaxf(mxA, __shfl_xor_sync(0xffffffffu, mxA, 2));
        mxB = fmaxf(mxB, __shfl_xor_sync(0xffffffffu, mxB, 1));
        mxB = fmaxf(mxB, __shfl_xor_sync(0xffffffffu, mxB, 2));

        float mnA = fmaxf(mA, mxA), mnB = fmaxf(mB, mxB);
        float aA = __expf(mA - mnA), aB = __expf(mB - mnB);
        mA = mnA; mB = mnB;

        float lsA = 0.f, lsB = 0.f;
        #pragma unroll
        for (int nt = 0; nt < 8; nt++) {
            sacc[nt][0] = __expf(sacc[nt][0] - mnA);
            sacc[nt][1] = __expf(sacc[nt][1] - mnA);
            sacc[nt][2] = __expf(sacc[nt][2] - mnB);
            sacc[nt][3] = __expf(sacc[nt][3] - mnB);
            lsA += sacc[nt][0] + sacc[nt][1];
            lsB += sacc[nt][2] + sacc[nt][3];
        }
        lsA += __shfl_xor_sync(0xffffffffu, lsA, 1);
        lsA += __shfl_xor_sync(0xffffffffu, lsA, 2);
        lsB += __shfl_xor_sync(0xffffffffu, lsB, 1);
        lsB += __shfl_xor_sync(0xffffffffu, lsB, 2);
        lA = lA * aA + lsA;
        lB = lB * aB + lsB;

        #pragma unroll
        for (int nt = 0; nt < 8; nt++) {
            o[nt][0] *= aA; o[nt][1] *= aA;
            o[nt][2] *= aB; o[nt][3] *= aB;
        }

        // ---- O += P V ----
        #pragma unroll
        for (int ks = 0; ks < 4; ks++) {
            uint32_t ph[4], pl[4];
            split2(sacc[2 * ks][0],     sacc[2 * ks][1],     ph[0], pl[0]);
            split2(sacc[2 * ks][2],     sacc[2 * ks][3],     ph[1], pl[1]);
            split2(sacc[2 * ks + 1][0], sacc[2 * ks + 1][1], ph[2], pl[2]);
            split2(sacc[2 * ks + 1][2], sacc[2 * ks + 1][3], ph[3], pl[3]);
            const uint32_t ro = (uint32_t)(ks * 16 * QSTR) * 4;
            #pragma unroll
            for (int np = 0; np < 4; np++) {
                uint32_t v4h[4], v4l[4];
                ldm_x4_trans(v4h, aVh + ro + voff[np]);
                ldm_x4_trans(v4l, aVl + ro + voff[np]);
                #pragma unroll
                for (int hf = 0; hf < 2; hf++) {
                    const int nt = np * 2 + hf;
                    mma16816(o[nt], ph, &v4h[hf * 2]);
                    mma16816(o[nt], ph, &v4l[hf * 2]);
                    mma16816(o[nt], pl, &v4h[hf * 2]);
                }
            }
        }
        __syncthreads();
    }

    // ---- normalize + write hi/lo bf16 ----
    float liA = 1.0f / lA, liB = 1.0f / lB;
    #pragma unroll
    for (int nt = 0; nt < 8; nt++) {
        int col = nt * 8 + 2 * fc;
        size_t gA = headoff + (size_t)rowAg * CDIM + col;
        size_t gB = headoff + (size_t)rowBg * CDIM + col;
        uint32_t hi, lo;
        split2(o[nt][0] * liA, o[nt][1] * liA, hi, lo);
        *(uint32_t*)&Yh[gA] = hi;
        *(uint32_t*)&Yl[gA] = lo;
        split2(o[nt][2] * liB, o[nt][3] * liB, hi, lo);
        *(uint32_t*)&Yh[gB] = hi;
        *(uint32_t*)&Yl[gB] = lo;
    }
}

// ---------------------------------------------------------------------------
// Launch
// ---------------------------------------------------------------------------
extern "C" void kernel_launch(void* const* d_in, const int* in_sizes, int n_in,
                              void* d_out, int out_size)
{
    const float* x  = (const float*)d_in[0];
    const float* Wq = (const float*)d_in[1];
    const float* bq = (const float*)d_in[2];
    const float* Wk = (const float*)d_in[3];
    const float* bk = (const float*)d_in[4];
    const float* Wv = (const float*)d_in[5];
    const float* bv = (const float*)d_in[6];
    const float* Wo = (const float*)d_in[7];
    const float* bo = (const float*)d_in[8];
    float* out = (float*)d_out;

    __nv_bfloat16 *xh, *xl, *qh, *ql, *kh, *kl, *vh, *vl, *yh, *yl;
    __nv_bfloat16 *wqh, *wql, *wkh, *wkl, *wvh, *wvl, *woh, *wol;
    cudaGetSymbolAddress((void**)&xh, g_xh);
    cudaGetSymbolAddress((void**)&xl, g_xl);
    cudaGetSymbolAddress((void**)&qh, g_qh);
    cudaGetSymbolAddress((void**)&ql, g_ql);
    cudaGetSymbolAddress((void**)&kh, g_kh);
    cudaGetSymbolAddress((void**)&kl, g_kl);
    cudaGetSymbolAddress((void**)&vh, g_vh);
    cudaGetSymbolAddress((void**)&vl, g_vl);
    cudaGetSymbolAddress((void**)&yh, g_yh);
    cudaGetSymbolAddress((void**)&yl, g_yl);
    cudaGetSymbolAddress((void**)&wqh, g_wqh);
    cudaGetSymbolAddress((void**)&wql, g_wql);
    cudaGetSymbolAddress((void**)&wkh, g_wkh);
    cudaGetSymbolAddress((void**)&wkl, g_wkl);
    cudaGetSymbolAddress((void**)&wvh, g_wvh);
    cudaGetSymbolAddress((void**)&wvl, g_wvl);
    cudaGetSymbolAddress((void**)&woh, g_woh);
    cudaGetSymbolAddress((void**)&wol, g_wol);

    cudaFuncSetAttribute(attn_mma,
                         cudaFuncAttributeMaxDynamicSharedMemorySize, ATTN_SMEM);
    cudaFuncSetAttribute(gemm_mma<0>,
                         cudaFuncAttributeMaxDynamicSharedMemorySize, GEMM_SMEM);
    cudaFuncSetAttribute(gemm_mma<1>,
                         cudaFuncAttributeMaxDynamicSharedMemorySize, GEMM_SMEM);

    const int nx4 = MROWS * CDIM / 4;
    const int nw4 = CDIM * CDIM / 4;

    dim3 ggrid(CDIM / 128, MROWS / 128);   // (8, 32)

    // all splits first (6th launch = gemm_mma -> ncu samples it)
    split_kernel<<<nx4 / 256, 256>>>(x, xh, xl, nx4);
    split_kernel<<<nw4 / 256, 256>>>(Wq, wqh, wql, nw4);
    split_kernel<<<nw4 / 256, 256>>>(Wk, wkh, wkl, nw4);
    split_kernel<<<nw4 / 256, 256>>>(Wv, wvh, wvl, nw4);
    split_kernel<<<nw4 / 256, 256>>>(Wo, woh, wol, nw4);

    gemm_mma<1><<<ggrid, 256, GEMM_SMEM>>>(xh, xl, wqh, wql, bq, nullptr, qh, ql,
                                           MROWS, CDIM, CDIM);
    gemm_mma<1><<<ggrid, 256, GEMM_SMEM>>>(xh, xl, wkh, wkl, bk, nullptr, kh, kl,
                                           MROWS, CDIM, CDIM);
    gemm_mma<1><<<ggrid, 256, GEMM_SMEM>>>(xh, xl, wvh, wvl, bv, nullptr, vh, vl,
                                           MROWS, CDIM, CDIM);

    dim3 agrid(TSEQ / 128, BATCH * NHEAD);  // (16, 32)
    attn_mma<<<agrid, 256, ATTN_SMEM>>>(qh, ql, kh, kl, vh, vl, yh, yl);

    gemm_mma<0><<<ggrid, 256, GEMM_SMEM>>>(yh, yl, woh, wol, bo, out, nullptr, nullptr,
                                           MROWS, CDIM, CDIM);
}

// round 8
// speedup vs baseline: 3.6410x; 1.1074x over previous
#include <cuda_runtime.h>
#include <cuda_bf16.h>
#include <math.h>
#include <stdint.h>

// Problem constants
#define BATCH 2
#define TSEQ  2048
#define CDIM  1024
#define NHEAD 16
#define HDIM  64
#define MROWS (BATCH * TSEQ)   // 4096

// ---------------------------------------------------------------------------
// Scratch (allocation-free: __device__ globals)
// ---------------------------------------------------------------------------
__device__ __align__(16) __nv_bfloat16 g_xh[MROWS * CDIM];
__device__ __align__(16) __nv_bfloat16 g_xl[MROWS * CDIM];
__device__ __align__(16) __nv_bfloat16 g_qh[MROWS * CDIM];
__device__ __align__(16) __nv_bfloat16 g_ql[MROWS * CDIM];
__device__ __align__(16) __nv_bfloat16 g_kh[MROWS * CDIM];
__device__ __align__(16) __nv_bfloat16 g_kl[MROWS * CDIM];
__device__ __align__(16) __nv_bfloat16 g_vh[MROWS * CDIM];
__device__ __align__(16) __nv_bfloat16 g_vl[MROWS * CDIM];
__device__ __align__(16) __nv_bfloat16 g_yh[MROWS * CDIM];
__device__ __align__(16) __nv_bfloat16 g_yl[MROWS * CDIM];
__device__ __align__(16) __nv_bfloat16 g_wqh[CDIM * CDIM], g_wql[CDIM * CDIM];
__device__ __align__(16) __nv_bfloat16 g_wkh[CDIM * CDIM], g_wkl[CDIM * CDIM];
__device__ __align__(16) __nv_bfloat16 g_wvh[CDIM * CDIM], g_wvl[CDIM * CDIM];
__device__ __align__(16) __nv_bfloat16 g_woh[CDIM * CDIM], g_wol[CDIM * CDIM];

// ---------------------------------------------------------------------------
// PTX helpers (baseline PTX, valid for compute_103)
// ---------------------------------------------------------------------------
__device__ __forceinline__ void mma16816(float* c, const uint32_t* a,
                                         const uint32_t* b) {
    asm volatile(
        "mma.sync.aligned.m16n8k16.row.col.f32.bf16.bf16.f32 "
        "{%0,%1,%2,%3}, {%4,%5,%6,%7}, {%8,%9}, {%0,%1,%2,%3};"
        : "+f"(c[0]), "+f"(c[1]), "+f"(c[2]), "+f"(c[3])
        : "r"(a[0]), "r"(a[1]), "r"(a[2]), "r"(a[3]), "r"(b[0]), "r"(b[1]));
}

__device__ __forceinline__ void ldm_x4(uint32_t* r, uint32_t saddr) {
    asm volatile(
        "ldmatrix.sync.aligned.m8n8.x4.shared.b16 {%0,%1,%2,%3}, [%4];"
        : "=r"(r[0]), "=r"(r[1]), "=r"(r[2]), "=r"(r[3]) : "r"(saddr));
}

__device__ __forceinline__ void ldm_x4_trans(uint32_t* r, uint32_t saddr) {
    asm volatile(
        "ldmatrix.sync.aligned.m8n8.x4.trans.shared.b16 {%0,%1,%2,%3}, [%4];"
        : "=r"(r[0]), "=r"(r[1]), "=r"(r[2]), "=r"(r[3]) : "r"(saddr));
}

__device__ __forceinline__ uint32_t smem_u32(const void* p) {
    uint32_t a;
    asm("{ .reg .u64 t; cvta.to.shared.u64 t, %1; cvt.u32.u64 %0, t; }"
        : "=r"(a) : "l"(p));
    return a;
}

__device__ __forceinline__ void cpa16(uint32_t s, const void* g) {
    asm volatile("cp.async.cg.shared.global [%0], [%1], 16;"
                 :: "r"(s), "l"(g));
}
__device__ __forceinline__ void cpa_commit() {
    asm volatile("cp.async.commit_group;");
}
template<int N> __device__ __forceinline__ void cpa_wait() {
    asm volatile("cp.async.wait_group %0;" :: "n"(N));
}

__device__ __forceinline__ uint32_t packbf(__nv_bfloat16 a, __nv_bfloat16 b) {
    __nv_bfloat162 t = __halves2bfloat162(a, b);
    return *(uint32_t*)&t;
}

__device__ __forceinline__ void split2(float a, float b,
                                       uint32_t& hi, uint32_t& lo) {
    __nv_bfloat16 ha = __float2bfloat16(a);
    __nv_bfloat16 hb = __float2bfloat16(b);
    __nv_bfloat16 la = __float2bfloat16(a - __bfloat162float(ha));
    __nv_bfloat16 lb = __float2bfloat16(b - __bfloat162float(hb));
    hi = packbf(ha, hb);
    lo = packbf(la, lb);
}

// ---------------------------------------------------------------------------
// Split kernels
// ---------------------------------------------------------------------------
__global__ void __launch_bounds__(256)
split_kernel(const float* __restrict__ in, __nv_bfloat16* __restrict__ hi,
             __nv_bfloat16* __restrict__ lo, int n4)
{
    int i = blockIdx.x * blockDim.x + threadIdx.x;
    if (i >= n4) return;
    float4 v = ((const float4*)in)[i];
    uint32_t h01, l01, h23, l23;
    split2(v.x, v.y, h01, l01);
    split2(v.z, v.w, h23, l23);
    ((uint32_t*)hi)[2 * i]     = h01;
    ((uint32_t*)hi)[2 * i + 1] = h23;
    ((uint32_t*)lo)[2 * i]     = l01;
    ((uint32_t*)lo)[2 * i + 1] = l23;
}

struct SplitBatch {
    const float* in[4];
    __nv_bfloat16* hi[4];
    __nv_bfloat16* lo[4];
};

__global__ void __launch_bounds__(256)
split4_kernel(SplitBatch sb, int n4)
{
    int i = blockIdx.x * blockDim.x + threadIdx.x;
    if (i >= n4) return;
    const float* in = sb.in[blockIdx.y];
    __nv_bfloat16* hi = sb.hi[blockIdx.y];
    __nv_bfloat16* lo = sb.lo[blockIdx.y];
    float4 v = ((const float4*)in)[i];
    uint32_t h01, l01, h23, l23;
    split2(v.x, v.y, h01, l01);
    split2(v.z, v.w, h23, l23);
    ((uint32_t*)hi)[2 * i]     = h01;
    ((uint32_t*)hi)[2 * i + 1] = h23;
    ((uint32_t*)lo)[2 * i]     = l01;
    ((uint32_t*)lo)[2 * i + 1] = l23;
}

// ---------------------------------------------------------------------------
// HMMA GEMM body: C = A[M,K] @ B[N,K]^T + bias. hi/lo split (3 MMAs).
// CTA tile 128x128 (blockIdx.x/y), K-chunk 32, double-buffered cp.async,
// ldmatrix frags.
// ---------------------------------------------------------------------------
#define SSTR  20                     // u32 per smem row
#define GARR  (128 * SSTR)           // u32 per array (2560)
#define GARRB (GARR * 4)             // bytes per array (10240)
#define GBUFB (4 * GARRB)            // bytes per buffer (40960)
#define GEMM_SMEM (2 * GBUFB)        // 81920

template<int BF16OUT>
__device__ __forceinline__ void
gemm_body(uint32_t* sg,
          const __nv_bfloat16* __restrict__ Ah, const __nv_bfloat16* __restrict__ Al,
          const __nv_bfloat16* __restrict__ Bh, const __nv_bfloat16* __restrict__ Bl,
          const float* __restrict__ bias, float* __restrict__ C,
          __nv_bfloat16* __restrict__ Ch, __nv_bfloat16* __restrict__ Cl,
          int M, int N, int K)
{
    const uint32_t sbase = smem_u32(sg);

    const int tid  = threadIdx.x;
    const int lane = tid & 31;
    const int warp = tid >> 5;
    const int wm   = (warp >> 1) * 32;
    const int wn   = (warp & 1) * 64;
    const int m0   = blockIdx.y * 128;
    const int n0   = blockIdx.x * 128;

    uint32_t s_off[2];
    size_t gA[2], gB[2];
    #pragma unroll
    for (int t = 0; t < 2; t++) {
        int f   = tid + t * 256;
        int row = f >> 2;
        int c4  = (f & 3) * 4;
        s_off[t] = (uint32_t)(row * SSTR + c4) * 4;
        gA[t] = (size_t)(m0 + row) * K + c4 * 2;
        gB[t] = (size_t)(n0 + row) * K + c4 * 2;
    }

    const int arow  = (lane & 7) + ((lane >> 3) & 1) * 8;
    const int acol  = (lane >> 4) * 4;
    const int brow  = (lane & 7) + (lane >> 4) * 8;
    const int bcol4 = ((lane >> 3) & 1) * 4;

    uint32_t aoff[2], boff[4];
    #pragma unroll
    for (int mt = 0; mt < 2; mt++)
        aoff[mt] = (uint32_t)((wm + mt * 16 + arow) * SSTR + acol) * 4;
    #pragma unroll
    for (int np = 0; np < 4; np++)
        boff[np] = (uint32_t)((wn + np * 16 + brow) * SSTR + bcol4) * 4;

    const int fr = lane >> 2;
    const int fc = lane & 3;

    float acc[2][8][4];
    #pragma unroll
    for (int mt = 0; mt < 2; mt++)
        #pragma unroll
        for (int nt = 0; nt < 8; nt++)
            #pragma unroll
            for (int j = 0; j < 4; j++) acc[mt][nt][j] = 0.f;

    const int nchunks = K / 32;

    #pragma unroll
    for (int t = 0; t < 2; t++) {
        cpa16(sbase + 0 * GARRB + s_off[t], Ah + gA[t]);
        cpa16(sbase + 1 * GARRB + s_off[t], Al + gA[t]);
        cpa16(sbase + 2 * GARRB + s_off[t], Bh + gB[t]);
        cpa16(sbase + 3 * GARRB + s_off[t], Bl + gB[t]);
    }
    cpa_commit();

    for (int kc = 0; kc < nchunks; kc++) {
        if (kc + 1 < nchunks) {
            const uint32_t bb = sbase + ((kc + 1) & 1) * GBUFB;
            const int ko = (kc + 1) * 32;
            #pragma unroll
            for (int t = 0; t < 2; t++) {
                cpa16(bb + 0 * GARRB + s_off[t], Ah + gA[t] + ko);
                cpa16(bb + 1 * GARRB + s_off[t], Al + gA[t] + ko);
                cpa16(bb + 2 * GARRB + s_off[t], Bh + gB[t] + ko);
                cpa16(bb + 3 * GARRB + s_off[t], Bl + gB[t] + ko);
            }
            cpa_commit();
            cpa_wait<1>();
        } else {
            cpa_wait<0>();
        }
        __syncthreads();

        const uint32_t cb  = sbase + (kc & 1) * GBUFB;
        const uint32_t aAh = cb, aAl = cb + GARRB;
        const uint32_t aBh = cb + 2 * GARRB, aBl = cb + 3 * GARRB;

        #pragma unroll
        for (int ks = 0; ks < 2; ks++) {
            const uint32_t kbb = (uint32_t)(ks * 8) * 4;
            uint32_t afh[2][4], afl[2][4];
            #pragma unroll
            for (int mt = 0; mt < 2; mt++) {
                ldm_x4(afh[mt], aAh + aoff[mt] + kbb);
                ldm_x4(afl[mt], aAl + aoff[mt] + kbb);
            }
            #pragma unroll
            for (int np = 0; np < 4; np++) {
                uint32_t b4h[4], b4l[4];
                ldm_x4(b4h, aBh + boff[np] + kbb);
                ldm_x4(b4l, aBl + boff[np] + kbb);
                #pragma unroll
                for (int hf = 0; hf < 2; hf++) {
                    const int nt = np * 2 + hf;
                    #pragma unroll
                    for (int mt = 0; mt < 2; mt++) {
                        mma16816(acc[mt][nt], afh[mt], &b4h[hf * 2]);
                        mma16816(acc[mt][nt], afh[mt], &b4l[hf * 2]);
                        mma16816(acc[mt][nt], afl[mt], &b4h[hf * 2]);
                    }
                }
            }
        }
        __syncthreads();
    }

    #pragma unroll
    for (int mt = 0; mt < 2; mt++) {
        #pragma unroll
        for (int nt = 0; nt < 8; nt++) {
            int row = m0 + wm + mt * 16 + fr;
            int col = n0 + wn + nt * 8 + fc * 2;
            float b0 = __ldg(&bias[col]);
            float b1 = __ldg(&bias[col + 1]);
            float c0 = acc[mt][nt][0] + b0, c1 = acc[mt][nt][1] + b1;
            float c2 = acc[mt][nt][2] + b0, c3 = acc[mt][nt][3] + b1;
            if (BF16OUT) {
                uint32_t hi, lo;
                split2(c0, c1, hi, lo);
                *(uint32_t*)&Ch[(size_t)row * N + col] = hi;
                *(uint32_t*)&Cl[(size_t)row * N + col] = lo;
                split2(c2, c3, hi, lo);
                *(uint32_t*)&Ch[(size_t)(row + 8) * N + col] = hi;
                *(uint32_t*)&Cl[(size_t)(row + 8) * N + col] = lo;
            } else {
                *(float2*)&C[(size_t)row * N + col]       = make_float2(c0, c1);
                *(float2*)&C[(size_t)(row + 8) * N + col] = make_float2(c2, c3);
            }
        }
    }
}

struct GemmBatch {
    const __nv_bfloat16* Bh[3];
    const __nv_bfloat16* Bl[3];
    const float* bias[3];
    __nv_bfloat16* Ch[3];
    __nv_bfloat16* Cl[3];
};

// merged Q/K/V projection: blockIdx.z selects weight/output
__global__ void __launch_bounds__(256, 2)
gemm_qkv(GemmBatch gb, const __nv_bfloat16* __restrict__ Ah,
         const __nv_bfloat16* __restrict__ Al)
{
    extern __shared__ uint32_t sg[];
    const int z = blockIdx.z;
    gemm_body<1>(sg, Ah, Al, gb.Bh[z], gb.Bl[z], gb.bias[z],
                 nullptr, gb.Ch[z], gb.Cl[z], MROWS, CDIM, CDIM);
}

// output projection (fp32 out)
__global__ void __launch_bounds__(256, 2)
gemm_o(const __nv_bfloat16* __restrict__ Ah, const __nv_bfloat16* __restrict__ Al,
       const __nv_bfloat16* __restrict__ Bh, const __nv_bfloat16* __restrict__ Bl,
       const float* __restrict__ bias, float* __restrict__ C)
{
    extern __shared__ uint32_t sg[];
    gemm_body<0>(sg, Ah, Al, Bh, Bl, bias, C, nullptr, nullptr,
                 MROWS, CDIM, CDIM);
}

// ---------------------------------------------------------------------------
// HMMA flash attention (causal). Pre-split bf16 in/out. 128-row q tile/CTA,
// Bc=64. cp.async double-buffered KV, ldmatrix frags, longest-qt-first order.
// ---------------------------------------------------------------------------
#define QSTR 36
#define QARR (128 * QSTR)              // 4608 u32
#define KARR (64 * QSTR)               // 2304 u32
#define KBUF (4 * KARR)                // u32 per kv buffer
#define ATTN_SMEM ((2 * QARR + 2 * KBUF) * 4)   // 110592 B

__global__ void __launch_bounds__(256, 2)
attn_mma(const __nv_bfloat16* __restrict__ Qh, const __nv_bfloat16* __restrict__ Ql,
         const __nv_bfloat16* __restrict__ Kh, const __nv_bfloat16* __restrict__ Kl,
         const __nv_bfloat16* __restrict__ Vh, const __nv_bfloat16* __restrict__ Vl,
         __nv_bfloat16* __restrict__ Yh, __nv_bfloat16* __restrict__ Yl)
{
    extern __shared__ uint32_t s32[];
    const uint32_t sbase = smem_u32(s32);
    const uint32_t aQh = sbase;
    const uint32_t aQl = sbase + QARR * 4;

    const int qt = gridDim.x - 1 - blockIdx.x;   // longest-first
    const int bh = blockIdx.y;
    const int b  = bh >> 4;
    const int h  = bh & 15;
    const size_t headoff = (size_t)b * TSEQ * CDIM + (size_t)h * HDIM;

    const int tid  = threadIdx.x;
    const int lane = tid & 31;
    const int warp = tid >> 5;
    const int fr   = lane >> 2;
    const int fc   = lane & 3;
    const int wm   = warp * 16;

    const int arow  = (lane & 7) + ((lane >> 3) & 1) * 8;
    const int acol  = (lane >> 4) * 4;
    const int brow  = (lane & 7) + (lane >> 4) * 8;
    const int bcol4 = ((lane >> 3) & 1) * 4;
    const uint32_t qoff = (uint32_t)((wm + arow) * QSTR + acol) * 4;
    uint32_t koff[4], voff[4];
    #pragma unroll
    for (int np = 0; np < 4; np++) {
        koff[np] = (uint32_t)((np * 16 + brow) * QSTR + bcol4) * 4;
        voff[np] = (uint32_t)(arow * QSTR + (np * 2 + (lane >> 4)) * 4) * 4;
    }

    // Q tile via cp.async
    #pragma unroll
    for (int t = 0; t < 4; t++) {
        int f  = tid + t * 256;
        int r  = f >> 3;
        int c8 = f & 7;
        size_t g = headoff + (size_t)(qt * 128 + r) * CDIM + c8 * 8;
        uint32_t so = (uint32_t)(r * QSTR + c8 * 4) * 4;
        cpa16(aQh + so, Qh + g);
        cpa16(aQl + so, Ql + g);
    }
    cpa_commit();

    uint32_t kvso[2];
    size_t kvg[2];
    #pragma unroll
    for (int t = 0; t < 2; t++) {
        int f  = tid + t * 256;
        int r  = f >> 3;
        int c8 = f & 7;
        kvso[t] = (uint32_t)(r * QSTR + c8 * 4) * 4;
        kvg[t]  = headoff + (size_t)r * CDIM + c8 * 8;
    }
    const uint32_t kvbase = sbase + 2 * QARR * 4;

    const int ktmax = 2 * qt + 1;

    #pragma unroll
    for (int t = 0; t < 2; t++) {
        cpa16(kvbase + 0 * KARR * 4 + kvso[t], Kh + kvg[t]);
        cpa16(kvbase + 1 * KARR * 4 + kvso[t], Kl + kvg[t]);
        cpa16(kvbase + 2 * KARR * 4 + kvso[t], Vh + kvg[t]);
        cpa16(kvbase + 3 * KARR * 4 + kvso[t], Vl + kvg[t]);
    }
    cpa_commit();

    const float scale = 0.125f;
    float o[8][4];
    #pragma unroll
    for (int nt = 0; nt < 8; nt++)
        #pragma unroll
        for (int j = 0; j < 4; j++) o[nt][j] = 0.f;
    float mA = -INFINITY, mB = -INFINITY, lA = 0.f, lB = 0.f;

    const int rowAg = qt * 128 + wm + fr;
    const int rowBg = rowAg + 8;

    for (int kt = 0; kt <= ktmax; kt++) {
        if (kt < ktmax) {
            const uint32_t bb = kvbase + ((kt + 1) & 1) * KBUF * 4;
            const size_t go = (size_t)(kt + 1) * 64 * CDIM;
            #pragma unroll
            for (int t = 0; t < 2; t++) {
                cpa16(bb + 0 * KARR * 4 + kvso[t], Kh + kvg[t] + go);
                cpa16(bb + 1 * KARR * 4 + kvso[t], Kl + kvg[t] + go);
                cpa16(bb + 2 * KARR * 4 + kvso[t], Vh + kvg[t] + go);
                cpa16(bb + 3 * KARR * 4 + kvso[t], Vl + kvg[t] + go);
            }
            cpa_commit();
            cpa_wait<1>();
        } else {
            cpa_wait<0>();
        }
        __syncthreads();

        const uint32_t cb  = kvbase + (kt & 1) * KBUF * 4;
        const uint32_t aKh = cb, aKl = cb + KARR * 4;
        const uint32_t aVh = cb + 2 * KARR * 4, aVl = cb + 3 * KARR * 4;

        // S = Q K^T
        float sacc[8][4];
        #pragma unroll
        for (int nt = 0; nt < 8; nt++)
            #pragma unroll
            for (int j = 0; j < 4; j++) sacc[nt][j] = 0.f;

        #pragma unroll
        for (int ks = 0; ks < 4; ks++) {
            const uint32_t kbb = (uint32_t)(ks * 8) * 4;
            uint32_t ah[4], al[4];
            ldm_x4(ah, aQh + qoff + kbb);
            ldm_x4(al, aQl + qoff + kbb);
            #pragma unroll
            for (int np = 0; np < 4; np++) {
                uint32_t k4h[4], k4l[4];
                ldm_x4(k4h, aKh + koff[np] + kbb);
                ldm_x4(k4l, aKl + koff[np] + kbb);
                #pragma unroll
                for (int hf = 0; hf < 2; hf++) {
                    const int nt = np * 2 + hf;
                    mma16816(sacc[nt], ah, &k4h[hf * 2]);
                    mma16816(sacc[nt], ah, &k4l[hf * 2]);
                    mma16816(sacc[nt], al, &k4h[hf * 2]);
                }
            }
        }

        // scale + causal mask
        const bool diag = (kt >= 2 * qt);
        #pragma unroll
        for (int nt = 0; nt < 8; nt++) {
            #pragma unroll
            for (int j = 0; j < 4; j++) sacc[nt][j] *= scale;
            if (diag) {
                int col0 = kt * 64 + nt * 8 + 2 * fc;
                if (col0     > rowAg) sacc[nt][0] = -INFINITY;
                if (col0 + 1 > rowAg) sacc[nt][1] = -INFINITY;
                if (col0     > rowBg) sacc[nt][2] = -INFINITY;
                if (col0 + 1 > rowBg) sacc[nt][3] = -INFINITY;
            }
        }

        // online softmax
        float mxA = -INFINITY, mxB = -INFINITY;
        #pragma unroll
        for (int nt = 0; nt < 8; nt++) {
            mxA = fmaxf(mxA, fmaxf(sacc[nt][0], sacc[nt][1]));
            mxB = fmaxf(mxB, fmaxf(sacc[nt][2], sacc[nt][3]));
        }
        mxA = fmaxf(mxA, __shfl_xor_sync(0xffffffffu, mxA, 1));
        mxA = fmaxf(mxA, __shfl_xor_sync(0xffffffffu, mxA, 2));
        mxB = fmaxf(mxB, __shfl_xor_sync(0xffffffffu, mxB, 1));
        mxB = fmaxf(mxB, __shfl_xor_sync(0xffffffffu, mxB, 2));

        float mnA = fmaxf(mA, mxA), mnB = fmaxf(mB, mxB);
        float aA = __expf(mA - mnA), aB = __expf(mB - mnB);
        mA = mnA; mB = mnB;

        float lsA = 0.f, lsB = 0.f;
        #pragma unroll
        for (int nt = 0; nt < 8; nt++) {
            sacc[nt][0] = __expf(sacc[nt][0] - mnA);
            sacc[nt][1] = __expf(sacc[nt][1] - mnA);
            sacc[nt][2] = __expf(sacc[nt][2] - mnB);
            sacc[nt][3] = __expf(sacc[nt][3] - mnB);
            lsA += sacc[nt][0] + sacc[nt][1];
            lsB += sacc[nt][2] + sacc[nt][3];
        }
        lsA += __shfl_xor_sync(0xffffffffu, lsA, 1);
        lsA += __shfl_xor_sync(0xffffffffu, lsA, 2);
        lsB += __shfl_xor_sync(0xffffffffu, lsB, 1);
        lsB += __shfl_xor_sync(0xffffffffu, lsB, 2);
        lA = lA * aA + lsA;
        lB = lB * aB + lsB;

        #pragma unroll
        for (int nt = 0; nt < 8; nt++) {
            o[nt][0] *= aA; o[nt][1] *= aA;
            o[nt][2] *= aB; o[nt][3] *= aB;
        }

        // O += P V
        #pragma unroll
        for (int ks = 0; ks < 4; ks++) {
            uint32_t ph[4], pl[4];
            split2(sacc[2 * ks][0],     sacc[2 * ks][1],     ph[0], pl[0]);
            split2(sacc[2 * ks][2],     sacc[2 * ks][3],     ph[1], pl[1]);
            split2(sacc[2 * ks + 1][0], sacc[2 * ks + 1][1], ph[2], pl[2]);
            split2(sacc[2 * ks + 1][2], sacc[2 * ks + 1][3], ph[3], pl[3]);
            const uint32_t ro = (uint32_t)(ks * 16 * QSTR) * 4;
            #pragma unroll
            for (int np = 0; np < 4; np++) {
                uint32_t v4h[4], v4l[4];
                ldm_x4_trans(v4h, aVh + ro + voff[np]);
                ldm_x4_trans(v4l, aVl + ro + voff[np]);
                #pragma unroll
                for (int hf = 0; hf < 2; hf++) {
                    const int nt = np * 2 + hf;
                    mma16816(o[nt], ph, &v4h[hf * 2]);
                    mma16816(o[nt], ph, &v4l[hf * 2]);
                    mma16816(o[nt], pl, &v4h[hf * 2]);
                }
            }
        }
        __syncthreads();
    }

    // normalize + write hi/lo bf16
    float liA = 1.0f / lA, liB = 1.0f / lB;
    #pragma unroll
    for (int nt = 0; nt < 8; nt++) {
        int col = nt * 8 + 2 * fc;
        size_t gA = headoff + (size_t)rowAg * CDIM + col;
        size_t gB = headoff + (size_t)rowBg * CDIM + col;
        uint32_t hi, lo;
        split2(o[nt][0] * liA, o[nt][1] * liA, hi, lo);
        *(uint32_t*)&Yh[gA] = hi;
        *(uint32_t*)&Yl[gA] = lo;
        split2(o[nt][2] * liB, o[nt][3] * liB, hi, lo);
        *(uint32_t*)&Yh[gB] = hi;
        *(uint32_t*)&Yl[gB] = lo;
    }
}

// ---------------------------------------------------------------------------
// Launch
// ---------------------------------------------------------------------------
extern "C" void kernel_launch(void* const* d_in, const int* in_sizes, int n_in,
                              void* d_out, int out_size)
{
    const float* x  = (const float*)d_in[0];
    const float* Wq = (const float*)d_in[1];
    const float* bq = (const float*)d_in[2];
    const float* Wk = (const float*)d_in[3];
    const float* bk = (const float*)d_in[4];
    const float* Wv = (const float*)d_in[5];
    const float* bv = (const float*)d_in[6];
    const float* Wo = (const float*)d_in[7];
    const float* bo = (const float*)d_in[8];
    float* out = (float*)d_out;

    __nv_bfloat16 *xh, *xl, *qh, *ql, *kh, *kl, *vh, *vl, *yh, *yl;
    __nv_bfloat16 *wqh, *wql, *wkh, *wkl, *wvh, *wvl, *woh, *wol;
    cudaGetSymbolAddress((void**)&xh, g_xh);
    cudaGetSymbolAddress((void**)&xl, g_xl);
    cudaGetSymbolAddress((void**)&qh, g_qh);
    cudaGetSymbolAddress((void**)&ql, g_ql);
    cudaGetSymbolAddress((void**)&kh, g_kh);
    cudaGetSymbolAddress((void**)&kl, g_kl);
    cudaGetSymbolAddress((void**)&vh, g_vh);
    cudaGetSymbolAddress((void**)&vl, g_vl);
    cudaGetSymbolAddress((void**)&yh, g_yh);
    cudaGetSymbolAddress((void**)&yl, g_yl);
    cudaGetSymbolAddress((void**)&wqh, g_wqh);
    cudaGetSymbolAddress((void**)&wql, g_wql);
    cudaGetSymbolAddress((void**)&wkh, g_wkh);
    cudaGetSymbolAddress((void**)&wkl, g_wkl);
    cudaGetSymbolAddress((void**)&wvh, g_wvh);
    cudaGetSymbolAddress((void**)&wvl, g_wvl);
    cudaGetSymbolAddress((void**)&woh, g_woh);
    cudaGetSymbolAddress((void**)&wol, g_wol);

    cudaFuncSetAttribute(attn_mma,
                         cudaFuncAttributeMaxDynamicSharedMemorySize, ATTN_SMEM);
    cudaFuncSetAttribute(gemm_qkv,
                         cudaFuncAttributeMaxDynamicSharedMemorySize, GEMM_SMEM);
    cudaFuncSetAttribute(gemm_o,
                         cudaFuncAttributeMaxDynamicSharedMemorySize, GEMM_SMEM);

    const int nx4 = MROWS * CDIM / 4;
    const int nw4 = CDIM * CDIM / 4;

    // 1) split x
    split_kernel<<<nx4 / 256, 256>>>(x, xh, xl, nx4);

    // 2) split all 4 weights in one launch
    SplitBatch sb;
    sb.in[0] = Wq; sb.hi[0] = wqh; sb.lo[0] = wql;
    sb.in[1] = Wk; sb.hi[1] = wkh; sb.lo[1] = wkl;
    sb.in[2] = Wv; sb.hi[2] = wvh; sb.lo[2] = wvl;
    sb.in[3] = Wo; sb.hi[3] = woh; sb.lo[3] = wol;
    dim3 sgrid(nw4 / 256, 4);
    split4_kernel<<<sgrid, 256>>>(sb, nw4);

    // 3) merged Q/K/V projection
    GemmBatch gb;
    gb.Bh[0] = wqh; gb.Bl[0] = wql; gb.bias[0] = bq; gb.Ch[0] = qh; gb.Cl[0] = ql;
    gb.Bh[1] = wkh; gb.Bl[1] = wkl; gb.bias[1] = bk; gb.Ch[1] = kh; gb.Cl[1] = kl;
    gb.Bh[2] = wvh; gb.Bl[2] = wvl; gb.bias[2] = bv; gb.Ch[2] = vh; gb.Cl[2] = vl;
    dim3 qkvgrid(CDIM / 128, MROWS / 128, 3);   // (8, 32, 3)
    gemm_qkv<<<qkvgrid, 256, GEMM_SMEM>>>(gb, xh, xl);

    // 4) attention
    dim3 agrid(TSEQ / 128, BATCH * NHEAD);  // (16, 32)
    attn_mma<<<agrid, 256, ATTN_SMEM>>>(qh, ql, kh, kl, vh, vl, yh, yl);

    // 5) output projection
    dim3 ogrid(CDIM / 128, MROWS / 128);    // (8, 32)
    gemm_o<<<ogrid, 256, GEMM_SMEM>>>(yh, yl, woh, wol, bo, out);
}

// round 9
// speedup vs baseline: 3.7917x; 1.0414x over previous
#include <cuda_runtime.h>
#include <cuda_bf16.h>
#include <math.h>
#include <stdint.h>

// Problem constants
#define BATCH 2
#define TSEQ  2048
#define CDIM  1024
#define NHEAD 16
#define HDIM  64
#define MROWS (BATCH * TSEQ)   // 4096

// ---------------------------------------------------------------------------
// Scratch (allocation-free: __device__ globals)
// ---------------------------------------------------------------------------
__device__ __align__(16) __nv_bfloat16 g_xh[MROWS * CDIM];
__device__ __align__(16) __nv_bfloat16 g_xl[MROWS * CDIM];
__device__ __align__(16) __nv_bfloat16 g_qh[MROWS * CDIM];
__device__ __align__(16) __nv_bfloat16 g_ql[MROWS * CDIM];
__device__ __align__(16) __nv_bfloat16 g_kh[MROWS * CDIM];
__device__ __align__(16) __nv_bfloat16 g_kl[MROWS * CDIM];
__device__ __align__(16) __nv_bfloat16 g_vh[MROWS * CDIM];
__device__ __align__(16) __nv_bfloat16 g_vl[MROWS * CDIM];
__device__ __align__(16) __nv_bfloat16 g_yh[MROWS * CDIM];
__device__ __align__(16) __nv_bfloat16 g_yl[MROWS * CDIM];
__device__ __align__(16) __nv_bfloat16 g_wqh[CDIM * CDIM], g_wql[CDIM * CDIM];
__device__ __align__(16) __nv_bfloat16 g_wkh[CDIM * CDIM], g_wkl[CDIM * CDIM];
__device__ __align__(16) __nv_bfloat16 g_wvh[CDIM * CDIM], g_wvl[CDIM * CDIM];
__device__ __align__(16) __nv_bfloat16 g_woh[CDIM * CDIM], g_wol[CDIM * CDIM];

// ---------------------------------------------------------------------------
// PTX helpers (baseline PTX, valid for compute_103)
// ---------------------------------------------------------------------------
__device__ __forceinline__ void mma16816(float* c, const uint32_t* a,
                                         const uint32_t* b) {
    asm volatile(
        "mma.sync.aligned.m16n8k16.row.col.f32.bf16.bf16.f32 "
        "{%0,%1,%2,%3}, {%4,%5,%6,%7}, {%8,%9}, {%0,%1,%2,%3};"
        : "+f"(c[0]), "+f"(c[1]), "+f"(c[2]), "+f"(c[3])
        : "r"(a[0]), "r"(a[1]), "r"(a[2]), "r"(a[3]), "r"(b[0]), "r"(b[1]));
}

__device__ __forceinline__ void ldm_x4(uint32_t* r, uint32_t saddr) {
    asm volatile(
        "ldmatrix.sync.aligned.m8n8.x4.shared.b16 {%0,%1,%2,%3}, [%4];"
        : "=r"(r[0]), "=r"(r[1]), "=r"(r[2]), "=r"(r[3]) : "r"(saddr));
}

__device__ __forceinline__ void ldm_x4_trans(uint32_t* r, uint32_t saddr) {
    asm volatile(
        "ldmatrix.sync.aligned.m8n8.x4.trans.shared.b16 {%0,%1,%2,%3}, [%4];"
        : "=r"(r[0]), "=r"(r[1]), "=r"(r[2]), "=r"(r[3]) : "r"(saddr));
}

__device__ __forceinline__ uint32_t smem_u32(const void* p) {
    uint32_t a;
    asm("{ .reg .u64 t; cvta.to.shared.u64 t, %1; cvt.u32.u64 %0, t; }"
        : "=r"(a) : "l"(p));
    return a;
}

__device__ __forceinline__ void cpa16(uint32_t s, const void* g) {
    asm volatile("cp.async.cg.shared.global [%0], [%1], 16;"
                 :: "r"(s), "l"(g));
}
__device__ __forceinline__ void cpa_commit() {
    asm volatile("cp.async.commit_group;");
}
template<int N> __device__ __forceinline__ void cpa_wait() {
    asm volatile("cp.async.wait_group %0;" :: "n"(N));
}

__device__ __forceinline__ uint32_t packbf(__nv_bfloat16 a, __nv_bfloat16 b) {
    __nv_bfloat162 t = __halves2bfloat162(a, b);
    return *(uint32_t*)&t;
}

__device__ __forceinline__ void split2(float a, float b,
                                       uint32_t& hi, uint32_t& lo) {
    __nv_bfloat16 ha = __float2bfloat16(a);
    __nv_bfloat16 hb = __float2bfloat16(b);
    __nv_bfloat16 la = __float2bfloat16(a - __bfloat162float(ha));
    __nv_bfloat16 lb = __float2bfloat16(b - __bfloat162float(hb));
    hi = packbf(ha, hb);
    lo = packbf(la, lb);
}

// ---------------------------------------------------------------------------
// Split kernel: 8 segments (4 weights + 4 quarters of x), one launch
// ---------------------------------------------------------------------------
struct SplitAll {
    const float* in[8];
    __nv_bfloat16* hi[8];
    __nv_bfloat16* lo[8];
};

__global__ void __launch_bounds__(256)
split8_kernel(SplitAll sb, int n4)
{
    int i = blockIdx.x * blockDim.x + threadIdx.x;
    if (i >= n4) return;
    const float* in = sb.in[blockIdx.y];
    __nv_bfloat16* hi = sb.hi[blockIdx.y];
    __nv_bfloat16* lo = sb.lo[blockIdx.y];
    float4 v = ((const float4*)in)[i];
    uint32_t h01, l01, h23, l23;
    split2(v.x, v.y, h01, l01);
    split2(v.z, v.w, h23, l23);
    ((uint32_t*)hi)[2 * i]     = h01;
    ((uint32_t*)hi)[2 * i + 1] = h23;
    ((uint32_t*)lo)[2 * i]     = l01;
    ((uint32_t*)lo)[2 * i + 1] = l23;
}

// ---------------------------------------------------------------------------
// HMMA GEMM body: C = A[M,K] @ B[N,K]^T + bias. hi/lo split (3 MMAs).
// CTA tile 128x128, K-chunk 32, double-buffered cp.async, ldmatrix frags.
// ONE barrier per chunk: wait -> sync -> prefetch(next) -> compute.
// ---------------------------------------------------------------------------
#define SSTR  20                     // u32 per smem row
#define GARR  (128 * SSTR)           // u32 per array (2560)
#define GARRB (GARR * 4)             // bytes per array (10240)
#define GBUFB (4 * GARRB)            // bytes per buffer (40960)
#define GEMM_SMEM (2 * GBUFB)        // 81920

template<int BF16OUT>
__device__ __forceinline__ void
gemm_body(uint32_t* sg,
          const __nv_bfloat16* __restrict__ Ah, const __nv_bfloat16* __restrict__ Al,
          const __nv_bfloat16* __restrict__ Bh, const __nv_bfloat16* __restrict__ Bl,
          const float* __restrict__ bias, float* __restrict__ C,
          __nv_bfloat16* __restrict__ Ch, __nv_bfloat16* __restrict__ Cl,
          int M, int N, int K)
{
    const uint32_t sbase = smem_u32(sg);

    const int tid  = threadIdx.x;
    const int lane = tid & 31;
    const int warp = tid >> 5;
    const int wm   = (warp >> 1) * 32;
    const int wn   = (warp & 1) * 64;
    const int m0   = blockIdx.y * 128;
    const int n0   = blockIdx.x * 128;

    uint32_t s_off[2];
    size_t gA[2], gB[2];
    #pragma unroll
    for (int t = 0; t < 2; t++) {
        int f   = tid + t * 256;
        int row = f >> 2;
        int c4  = (f & 3) * 4;
        s_off[t] = (uint32_t)(row * SSTR + c4) * 4;
        gA[t] = (size_t)(m0 + row) * K + c4 * 2;
        gB[t] = (size_t)(n0 + row) * K + c4 * 2;
    }

    const int arow  = (lane & 7) + ((lane >> 3) & 1) * 8;
    const int acol  = (lane >> 4) * 4;
    const int brow  = (lane & 7) + (lane >> 4) * 8;
    const int bcol4 = ((lane >> 3) & 1) * 4;

    uint32_t aoff[2], boff[4];
    #pragma unroll
    for (int mt = 0; mt < 2; mt++)
        aoff[mt] = (uint32_t)((wm + mt * 16 + arow) * SSTR + acol) * 4;
    #pragma unroll
    for (int np = 0; np < 4; np++)
        boff[np] = (uint32_t)((wn + np * 16 + brow) * SSTR + bcol4) * 4;

    const int fr = lane >> 2;
    const int fc = lane & 3;

    float acc[2][8][4];
    #pragma unroll
    for (int mt = 0; mt < 2; mt++)
        #pragma unroll
        for (int nt = 0; nt < 8; nt++)
            #pragma unroll
            for (int j = 0; j < 4; j++) acc[mt][nt][j] = 0.f;

    const int nchunks = K / 32;

    // prefetch chunk 0 -> buffer 0
    #pragma unroll
    for (int t = 0; t < 2; t++) {
        cpa16(sbase + 0 * GARRB + s_off[t], Ah + gA[t]);
        cpa16(sbase + 1 * GARRB + s_off[t], Al + gA[t]);
        cpa16(sbase + 2 * GARRB + s_off[t], Bh + gB[t]);
        cpa16(sbase + 3 * GARRB + s_off[t], Bl + gB[t]);
    }
    cpa_commit();

    for (int kc = 0; kc < nchunks; kc++) {
        cpa_wait<0>();        // chunk kc resident
        __syncthreads();      // all warps: done reading buf[(kc+1)&1] (iter kc-1)

        if (kc + 1 < nchunks) {
            const uint32_t bb = sbase + ((kc + 1) & 1) * GBUFB;
            const int ko = (kc + 1) * 32;
            #pragma unroll
            for (int t = 0; t < 2; t++) {
                cpa16(bb + 0 * GARRB + s_off[t], Ah + gA[t] + ko);
                cpa16(bb + 1 * GARRB + s_off[t], Al + gA[t] + ko);
                cpa16(bb + 2 * GARRB + s_off[t], Bh + gB[t] + ko);
                cpa16(bb + 3 * GARRB + s_off[t], Bl + gB[t] + ko);
            }
            cpa_commit();
        }

        const uint32_t cb  = sbase + (kc & 1) * GBUFB;
        const uint32_t aAh = cb, aAl = cb + GARRB;
        const uint32_t aBh = cb + 2 * GARRB, aBl = cb + 3 * GARRB;

        #pragma unroll
        for (int ks = 0; ks < 2; ks++) {
            const uint32_t kbb = (uint32_t)(ks * 8) * 4;
            uint32_t afh[2][4], afl[2][4];
            #pragma unroll
            for (int mt = 0; mt < 2; mt++) {
                ldm_x4(afh[mt], aAh + aoff[mt] + kbb);
                ldm_x4(afl[mt], aAl + aoff[mt] + kbb);
            }
            #pragma unroll
            for (int np = 0; np < 4; np++) {
                uint32_t b4h[4], b4l[4];
                ldm_x4(b4h, aBh + boff[np] + kbb);
                ldm_x4(b4l, aBl + boff[np] + kbb);
                #pragma unroll
                for (int hf = 0; hf < 2; hf++) {
                    const int nt = np * 2 + hf;
                    #pragma unroll
                    for (int mt = 0; mt < 2; mt++) {
                        mma16816(acc[mt][nt], afh[mt], &b4h[hf * 2]);
                        mma16816(acc[mt][nt], afh[mt], &b4l[hf * 2]);
                        mma16816(acc[mt][nt], afl[mt], &b4h[hf * 2]);
                    }
                }
            }
        }
    }

    #pragma unroll
    for (int mt = 0; mt < 2; mt++) {
        #pragma unroll
        for (int nt = 0; nt < 8; nt++) {
            int row = m0 + wm + mt * 16 + fr;
            int col = n0 + wn + nt * 8 + fc * 2;
            float b0 = __ldg(&bias[col]);
            float b1 = __ldg(&bias[col + 1]);
            float c0 = acc[mt][nt][0] + b0, c1 = acc[mt][nt][1] + b1;
            float c2 = acc[mt][nt][2] + b0, c3 = acc[mt][nt][3] + b1;
            if (BF16OUT) {
                uint32_t hi, lo;
                split2(c0, c1, hi, lo);
                *(uint32_t*)&Ch[(size_t)row * N + col] = hi;
                *(uint32_t*)&Cl[(size_t)row * N + col] = lo;
                split2(c2, c3, hi, lo);
                *(uint32_t*)&Ch[(size_t)(row + 8) * N + col] = hi;
                *(uint32_t*)&Cl[(size_t)(row + 8) * N + col] = lo;
            } else {
                *(float2*)&C[(size_t)row * N + col]       = make_float2(c0, c1);
                *(float2*)&C[(size_t)(row + 8) * N + col] = make_float2(c2, c3);
            }
        }
    }
}

struct GemmBatch {
    const __nv_bfloat16* Bh[3];
    const __nv_bfloat16* Bl[3];
    const float* bias[3];
    __nv_bfloat16* Ch[3];
    __nv_bfloat16* Cl[3];
};

__global__ void __launch_bounds__(256, 2)
gemm_qkv(GemmBatch gb, const __nv_bfloat16* __restrict__ Ah,
         const __nv_bfloat16* __restrict__ Al)
{
    extern __shared__ uint32_t sg[];
    const int z = blockIdx.z;
    gemm_body<1>(sg, Ah, Al, gb.Bh[z], gb.Bl[z], gb.bias[z],
                 nullptr, gb.Ch[z], gb.Cl[z], MROWS, CDIM, CDIM);
}

__global__ void __launch_bounds__(256, 2)
gemm_o(const __nv_bfloat16* __restrict__ Ah, const __nv_bfloat16* __restrict__ Al,
       const __nv_bfloat16* __restrict__ Bh, const __nv_bfloat16* __restrict__ Bl,
       const float* __restrict__ bias, float* __restrict__ C)
{
    extern __shared__ uint32_t sg[];
    gemm_body<0>(sg, Ah, Al, Bh, Bl, bias, C, nullptr, nullptr,
                 MROWS, CDIM, CDIM);
}

// ---------------------------------------------------------------------------
// HMMA flash attention (causal). Pre-split bf16 in/out. 128-row q tile/CTA,
// Bc=64, double-buffered cp.async KV, ldmatrix frags, longest-qt-first.
// ONE barrier per kv tile -> warps skew across softmax/MMA phases.
// ---------------------------------------------------------------------------
#define QSTR 36
#define QARR (128 * QSTR)              // 4608 u32
#define KARR (64 * QSTR)               // 2304 u32
#define KBUF (4 * KARR)                // u32 per kv buffer
#define ATTN_SMEM ((2 * QARR + 2 * KBUF) * 4)   // 110592 B

__global__ void __launch_bounds__(256, 2)
attn_mma(const __nv_bfloat16* __restrict__ Qh, const __nv_bfloat16* __restrict__ Ql,
         const __nv_bfloat16* __restrict__ Kh, const __nv_bfloat16* __restrict__ Kl,
         const __nv_bfloat16* __restrict__ Vh, const __nv_bfloat16* __restrict__ Vl,
         __nv_bfloat16* __restrict__ Yh, __nv_bfloat16* __restrict__ Yl)
{
    extern __shared__ uint32_t s32[];
    const uint32_t sbase = smem_u32(s32);
    const uint32_t aQh = sbase;
    const uint32_t aQl = sbase + QARR * 4;

    const int qt = gridDim.x - 1 - blockIdx.x;   // longest-first
    const int bh = blockIdx.y;
    const int b  = bh >> 4;
    const int h  = bh & 15;
    const size_t headoff = (size_t)b * TSEQ * CDIM + (size_t)h * HDIM;

    const int tid  = threadIdx.x;
    const int lane = tid & 31;
    const int warp = tid >> 5;
    const int fr   = lane >> 2;
    const int fc   = lane & 3;
    const int wm   = warp * 16;

    const int arow  = (lane & 7) + ((lane >> 3) & 1) * 8;
    const int acol  = (lane >> 4) * 4;
    const int brow  = (lane & 7) + (lane >> 4) * 8;
    const int bcol4 = ((lane >> 3) & 1) * 4;
    const uint32_t qoff = (uint32_t)((wm + arow) * QSTR + acol) * 4;
    uint32_t koff[4], voff[4];
    #pragma unroll
    for (int np = 0; np < 4; np++) {
        koff[np] = (uint32_t)((np * 16 + brow) * QSTR + bcol4) * 4;
        voff[np] = (uint32_t)(arow * QSTR + (np * 2 + (lane >> 4)) * 4) * 4;
    }

    // Q tile via cp.async (same group as KV tile 0)
    #pragma unroll
    for (int t = 0; t < 4; t++) {
        int f  = tid + t * 256;
        int r  = f >> 3;
        int c8 = f & 7;
        size_t g = headoff + (size_t)(qt * 128 + r) * CDIM + c8 * 8;
        uint32_t so = (uint32_t)(r * QSTR + c8 * 4) * 4;
        cpa16(aQh + so, Qh + g);
        cpa16(aQl + so, Ql + g);
    }

    uint32_t kvso[2];
    size_t kvg[2];
    #pragma unroll
    for (int t = 0; t < 2; t++) {
        int f  = tid + t * 256;
        int r  = f >> 3;
        int c8 = f & 7;
        kvso[t] = (uint32_t)(r * QSTR + c8 * 4) * 4;
        kvg[t]  = headoff + (size_t)r * CDIM + c8 * 8;
    }
    const uint32_t kvbase = sbase + 2 * QARR * 4;

    const int ktmax = 2 * qt + 1;

    // prefetch kv tile 0 -> buffer 0 (with Q, one group)
    #pragma unroll
    for (int t = 0; t < 2; t++) {
        cpa16(kvbase + 0 * KARR * 4 + kvso[t], Kh + kvg[t]);
        cpa16(kvbase + 1 * KARR * 4 + kvso[t], Kl + kvg[t]);
        cpa16(kvbase + 2 * KARR * 4 + kvso[t], Vh + kvg[t]);
        cpa16(kvbase + 3 * KARR * 4 + kvso[t], Vl + kvg[t]);
    }
    cpa_commit();

    const float scale = 0.125f;
    float o[8][4];
    #pragma unroll
    for (int nt = 0; nt < 8; nt++)
        #pragma unroll
        for (int j = 0; j < 4; j++) o[nt][j] = 0.f;
    float mA = -INFINITY, mB = -INFINITY, lA = 0.f, lB = 0.f;

    const int rowAg = qt * 128 + wm + fr;
    const int rowBg = rowAg + 8;

    for (int kt = 0; kt <= ktmax; kt++) {
        cpa_wait<0>();        // tile kt (and Q on kt=0) resident
        __syncthreads();      // all warps done reading buf[(kt+1)&1] (iter kt-1)

        if (kt < ktmax) {
            const uint32_t bb = kvbase + ((kt + 1) & 1) * KBUF * 4;
            const size_t go = (size_t)(kt + 1) * 64 * CDIM;
            #pragma unroll
            for (int t = 0; t < 2; t++) {
                cpa16(bb + 0 * KARR * 4 + kvso[t], Kh + kvg[t] + go);
                cpa16(bb + 1 * KARR * 4 + kvso[t], Kl + kvg[t] + go);
                cpa16(bb + 2 * KARR * 4 + kvso[t], Vh + kvg[t] + go);
                cpa16(bb + 3 * KARR * 4 + kvso[t], Vl + kvg[t] + go);
            }
            cpa_commit();
        }

        const uint32_t cb  = kvbase + (kt & 1) * KBUF * 4;
        const uint32_t aKh = cb, aKl = cb + KARR * 4;
        const uint32_t aVh = cb + 2 * KARR * 4, aVl = cb + 3 * KARR * 4;

        // S = Q K^T
        float sacc[8][4];
        #pragma unroll
        for (int nt = 0; nt < 8; nt++)
            #pragma unroll
            for (int j = 0; j < 4; j++) sacc[nt][j] = 0.f;

        #pragma unroll
        for (int ks = 0; ks < 4; ks++) {
            const uint32_t kbb = (uint32_t)(ks * 8) * 4;
            uint32_t ah[4], al[4];
            ldm_x4(ah, aQh + qoff + kbb);
            ldm_x4(al, aQl + qoff + kbb);
            #pragma unroll
            for (int np = 0; np < 4; np++) {
                uint32_t k4h[4], k4l[4];
                ldm_x4(k4h, aKh + koff[np] + kbb);
                ldm_x4(k4l, aKl + koff[np] + kbb);
                #pragma unroll
                for (int hf = 0; hf < 2; hf++) {
                    const int nt = np * 2 + hf;
                    mma16816(sacc[nt], ah, &k4h[hf * 2]);
                    mma16816(sacc[nt], ah, &k4l[hf * 2]);
                    mma16816(sacc[nt], al, &k4h[hf * 2]);
                }
            }
        }

        // scale + causal mask
        const bool diag = (kt >= 2 * qt);
        #pragma unroll
        for (int nt = 0; nt < 8; nt++) {
            #pragma unroll
            for (int j = 0; j < 4; j++) sacc[nt][j] *= scale;
            if (diag) {
                int col0 = kt * 64 + nt * 8 + 2 * fc;
                if (col0     > rowAg) sacc[nt][0] = -INFINITY;
                if (col0 + 1 > rowAg) sacc[nt][1] = -INFINITY;
                if (col0     > rowBg) sacc[nt][2] = -INFINITY;
                if (col0 + 1 > rowBg) sacc[nt][3] = -INFINITY;
            }
        }

        // online softmax
        float mxA = -INFINITY, mxB = -INFINITY;
        #pragma unroll
        for (int nt = 0; nt < 8; nt++) {
            mxA = fmaxf(mxA, fmaxf(sacc[nt][0], sacc[nt][1]));
            mxB = fmaxf(mxB, fmaxf(sacc[nt][2], sacc[nt][3]));
        }
        mxA = fmaxf(mxA, __shfl_xor_sync(0xffffffffu, mxA, 1));
        mxA = fmaxf(mxA, __shfl_xor_sync(0xffffffffu, mxA, 2));
        mxB = fmaxf(mxB, __shfl_xor_sync(0xffffffffu, mxB, 1));
        mxB = fmaxf(mxB, __shfl_xor_sync(0xffffffffu, mxB, 2));

        float mnA = fmaxf(mA, mxA), mnB = fmaxf(mB, mxB);
        float aA = __expf(mA - mnA), aB = __expf(mB - mnB);
        mA = mnA; mB = mnB;

        float lsA = 0.f, lsB = 0.f;
        #pragma unroll
        for (int nt = 0; nt < 8; nt++) {
            sacc[nt][0] = __expf(sacc[nt][0] - mnA);
            sacc[nt][1] = __expf(sacc[nt][1] - mnA);
            sacc[nt][2] = __expf(sacc[nt][2] - mnB);
            sacc[nt][3] = __expf(sacc[nt][3] - mnB);
            lsA += sacc[nt][0] + sacc[nt][1];
            lsB += sacc[nt][2] + sacc[nt][3];
        }
        lsA += __shfl_xor_sync(0xffffffffu, lsA, 1);
        lsA += __shfl_xor_sync(0xffffffffu, lsA, 2);
        lsB += __shfl_xor_sync(0xffffffffu, lsB, 1);
        lsB += __shfl_xor_sync(0xffffffffu, lsB, 2);
        lA = lA * aA + lsA;
        lB = lB * aB + lsB;

        #pragma unroll
        for (int nt = 0; nt < 8; nt++) {
            o[nt][0] *= aA; o[nt][1] *= aA;
            o[nt][2] *= aB; o[nt][3] *= aB;
        }

        // O += P V
        #pragma unroll
        for (int ks = 0; ks < 4; ks++) {
            uint32_t ph[4], pl[4];
            split2(sacc[2 * ks][0],     sacc[2 * ks][1],     ph[0], pl[0]);
            split2(sacc[2 * ks][2],     sacc[2 * ks][3],     ph[1], pl[1]);
            split2(sacc[2 * ks + 1][0], sacc[2 * ks + 1][1], ph[2], pl[2]);
            split2(sacc[2 * ks + 1][2], sacc[2 * ks + 1][3], ph[3], pl[3]);
            const uint32_t ro = (uint32_t)(ks * 16 * QSTR) * 4;
            #pragma unroll
            for (int np = 0; np < 4; np++) {
                uint32_t v4h[4], v4l[4];
                ldm_x4_trans(v4h, aVh + ro + voff[np]);
                ldm_x4_trans(v4l, aVl + ro + voff[np]);
                #pragma unroll
                for (int hf = 0; hf < 2; hf++) {
                    const int nt = np * 2 + hf;
                    mma16816(o[nt], ph, &v4h[hf * 2]);
                    mma16816(o[nt], ph, &v4l[hf * 2]);
                    mma16816(o[nt], pl, &v4h[hf * 2]);
                }
            }
        }
    }

    // normalize + write hi/lo bf16
    float liA = 1.0f / lA, liB = 1.0f / lB;
    #pragma unroll
    for (int nt = 0; nt < 8; nt++) {
        int col = nt * 8 + 2 * fc;
        size_t gA = headoff + (size_t)rowAg * CDIM + col;
        size_t gB = headoff + (size_t)rowBg * CDIM + col;
        uint32_t hi, lo;
        split2(o[nt][0] * liA, o[nt][1] * liA, hi, lo);
        *(uint32_t*)&Yh[gA] = hi;
        *(uint32_t*)&Yl[gA] = lo;
        split2(o[nt][2] * liB, o[nt][3] * liB, hi, lo);
        *(uint32_t*)&Yh[gB] = hi;
        *(uint32_t*)&Yl[gB] = lo;
    }
}

// ---------------------------------------------------------------------------
// Launch
// ---------------------------------------------------------------------------
extern "C" void kernel_launch(void* const* d_in, const int* in_sizes, int n_in,
                              void* d_out, int out_size)
{
    const float* x  = (const float*)d_in[0];
    const float* Wq = (const float*)d_in[1];
    const float* bq = (const float*)d_in[2];
    const float* Wk = (const float*)d_in[3];
    const float* bk = (const float*)d_in[4];
    const float* Wv = (const float*)d_in[5];
    const float* bv = (const float*)d_in[6];
    const float* Wo = (const float*)d_in[7];
    const float* bo = (const float*)d_in[8];
    float* out = (float*)d_out;

    __nv_bfloat16 *xh, *xl, *qh, *ql, *kh, *kl, *vh, *vl, *yh, *yl;
    __nv_bfloat16 *wqh, *wql, *wkh, *wkl, *wvh, *wvl, *woh, *wol;
    cudaGetSymbolAddress((void**)&xh, g_xh);
    cudaGetSymbolAddress((void**)&xl, g_xl);
    cudaGetSymbolAddress((void**)&qh, g_qh);
    cudaGetSymbolAddress((void**)&ql, g_ql);
    cudaGetSymbolAddress((void**)&kh, g_kh);
    cudaGetSymbolAddress((void**)&kl, g_kl);
    cudaGetSymbolAddress((void**)&vh, g_vh);
    cudaGetSymbolAddress((void**)&vl, g_vl);
    cudaGetSymbolAddress((void**)&yh, g_yh);
    cudaGetSymbolAddress((void**)&yl, g_yl);
    cudaGetSymbolAddress((void**)&wqh, g_wqh);
    cudaGetSymbolAddress((void**)&wql, g_wql);
    cudaGetSymbolAddress((void**)&wkh, g_wkh);
    cudaGetSymbolAddress((void**)&wkl, g_wkl);
    cudaGetSymbolAddress((void**)&wvh, g_wvh);
    cudaGetSymbolAddress((void**)&wvl, g_wvl);
    cudaGetSymbolAddress((void**)&woh, g_woh);
    cudaGetSymbolAddress((void**)&wol, g_wol);

    cudaFuncSetAttribute(attn_mma,
                         cudaFuncAttributeMaxDynamicSharedMemorySize, ATTN_SMEM);
    cudaFuncSetAttribute(gemm_qkv,
                         cudaFuncAttributeMaxDynamicSharedMemorySize, GEMM_SMEM);
    cudaFuncSetAttribute(gemm_o,
                         cudaFuncAttributeMaxDynamicSharedMemorySize, GEMM_SMEM);

    const int nw4 = CDIM * CDIM / 4;   // 262144 float4 per weight / x-quarter
    const int xq  = CDIM * CDIM;       // elements per x quarter

    // 1) all splits in one launch: 4 weights + 4 quarters of x
    SplitAll sa;
    sa.in[0] = Wq; sa.hi[0] = wqh; sa.lo[0] = wql;
    sa.in[1] = Wk; sa.hi[1] = wkh; sa.lo[1] = wkl;
    sa.in[2] = Wv; sa.hi[2] = wvh; sa.lo[2] = wvl;
    sa.in[3] = Wo; sa.hi[3] = woh; sa.lo[3] = wol;
    for (int q = 0; q < 4; q++) {
        sa.in[4 + q] = x + (size_t)q * xq;
        sa.hi[4 + q] = xh + (size_t)q * xq;
        sa.lo[4 + q] = xl + (size_t)q * xq;
    }
    dim3 sgrid(nw4 / 256, 8);
    split8_kernel<<<sgrid, 256>>>(sa, nw4);

    // 2) merged Q/K/V projection
    GemmBatch gb;
    gb.Bh[0] = wqh; gb.Bl[0] = wql; gb.bias[0] = bq; gb.Ch[0] = qh; gb.Cl[0] = ql;
    gb.Bh[1] = wkh; gb.Bl[1] = wkl; gb.bias[1] = bk; gb.Ch[1] = kh; gb.Cl[1] = kl;
    gb.Bh[2] = wvh; gb.Bl[2] = wvl; gb.bias[2] = bv; gb.Ch[2] = vh; gb.Cl[2] = vl;
    dim3 qkvgrid(CDIM / 128, MROWS / 128, 3);   // (8, 32, 3)
    gemm_qkv<<<qkvgrid, 256, GEMM_SMEM>>>(gb, xh, xl);

    // 3) attention
    dim3 agrid(TSEQ / 128, BATCH * NHEAD);  // (16, 32)
    attn_mma<<<agrid, 256, ATTN_SMEM>>>(qh, ql, kh, kl, vh, vl, yh, yl);

    // 4) output projection
    dim3 ogrid(CDIM / 128, MROWS / 128);    // (8, 32)
    gemm_o<<<ogrid, 256, GEMM_SMEM>>>(yh, yl, woh, wol, bo, out);
}

// round 10
// speedup vs baseline: 5.3973x; 1.4235x over previous
#include <cuda_runtime.h>
#include <cuda_fp16.h>
#include <math.h>
#include <stdint.h>

// Problem constants
#define BATCH 2
#define TSEQ  2048
#define CDIM  1024
#define NHEAD 16
#define HDIM  64
#define MROWS (BATCH * TSEQ)   // 4096

// ---------------------------------------------------------------------------
// Scratch (allocation-free: __device__ globals)
// ---------------------------------------------------------------------------
__device__ __align__(16) __half g_xh[MROWS * CDIM];
__device__ __align__(16) __half g_xl[MROWS * CDIM];
__device__ __align__(16) __half g_qh[MROWS * CDIM];
__device__ __align__(16) __half g_ql[MROWS * CDIM];
__device__ __align__(16) __half g_kh[MROWS * CDIM];
__device__ __align__(16) __half g_vh[MROWS * CDIM];
__device__ __align__(16) __half g_yh[MROWS * CDIM];
__device__ __align__(16) __half g_yl[MROWS * CDIM];
__device__ __align__(16) __half g_wqh[CDIM * CDIM];
__device__ __align__(16) __half g_wkh[CDIM * CDIM];
__device__ __align__(16) __half g_wvh[CDIM * CDIM];
__device__ __align__(16) __half g_woh[CDIM * CDIM];

// ---------------------------------------------------------------------------
// PTX helpers (baseline PTX, valid for compute_103)
// ---------------------------------------------------------------------------
__device__ __forceinline__ void mma16816(float* c, const uint32_t* a,
                                         const uint32_t* b) {
    asm volatile(
        "mma.sync.aligned.m16n8k16.row.col.f32.f16.f16.f32 "
        "{%0,%1,%2,%3}, {%4,%5,%6,%7}, {%8,%9}, {%0,%1,%2,%3};"
        : "+f"(c[0]), "+f"(c[1]), "+f"(c[2]), "+f"(c[3])
        : "r"(a[0]), "r"(a[1]), "r"(a[2]), "r"(a[3]), "r"(b[0]), "r"(b[1]));
}

__device__ __forceinline__ void ldm_x4(uint32_t* r, uint32_t saddr) {
    asm volatile(
        "ldmatrix.sync.aligned.m8n8.x4.shared.b16 {%0,%1,%2,%3}, [%4];"
        : "=r"(r[0]), "=r"(r[1]), "=r"(r[2]), "=r"(r[3]) : "r"(saddr));
}

__device__ __forceinline__ void ldm_x4_trans(uint32_t* r, uint32_t saddr) {
    asm volatile(
        "ldmatrix.sync.aligned.m8n8.x4.trans.shared.b16 {%0,%1,%2,%3}, [%4];"
        : "=r"(r[0]), "=r"(r[1]), "=r"(r[2]), "=r"(r[3]) : "r"(saddr));
}

__device__ __forceinline__ uint32_t smem_u32(const void* p) {
    uint32_t a;
    asm("{ .reg .u64 t; cvta.to.shared.u64 t, %1; cvt.u32.u64 %0, t; }"
        : "=r"(a) : "l"(p));
    return a;
}

__device__ __forceinline__ void cpa16(uint32_t s, const void* g) {
    asm volatile("cp.async.cg.shared.global [%0], [%1], 16;"
                 :: "r"(s), "l"(g));
}
__device__ __forceinline__ void cpa_commit() {
    asm volatile("cp.async.commit_group;");
}
template<int N> __device__ __forceinline__ void cpa_wait() {
    asm volatile("cp.async.wait_group %0;" :: "n"(N));
}

__device__ __forceinline__ uint32_t packh(__half a, __half b) {
    __half2 t = __halves2half2(a, b);
    return *(uint32_t*)&t;
}

// split two fp32 -> packed hi fp16x2 + packed lo fp16x2
__device__ __forceinline__ void split2h(float a, float b,
                                        uint32_t& hi, uint32_t& lo) {
    __half ha = __float2half_rn(a);
    __half hb = __float2half_rn(b);
    __half la = __float2half_rn(a - __half2float(ha));
    __half lb = __float2half_rn(b - __half2float(hb));
    hi = packh(ha, hb);
    lo = packh(la, lb);
}

__device__ __forceinline__ uint32_t cvt2h(float a, float b) {
    return packh(__float2half_rn(a), __float2half_rn(b));
}

// ---------------------------------------------------------------------------
// Split kernel: 8 segments. y<4: weights (hi only). y>=4: x quarters (hi+lo).
// ---------------------------------------------------------------------------
struct SplitAll {
    const float* in[8];
    __half* hi[8];
    __half* lo[8];   // nullptr -> convert only
};

__global__ void __launch_bounds__(256)
split8_kernel(SplitAll sb, int n4)
{
    int i = blockIdx.x * blockDim.x + threadIdx.x;
    if (i >= n4) return;
    const float* in = sb.in[blockIdx.y];
    __half* hi = sb.hi[blockIdx.y];
    __half* lo = sb.lo[blockIdx.y];
    float4 v = ((const float4*)in)[i];
    if (lo) {
        uint32_t h01, l01, h23, l23;
        split2h(v.x, v.y, h01, l01);
        split2h(v.z, v.w, h23, l23);
        ((uint32_t*)hi)[2 * i]     = h01;
        ((uint32_t*)hi)[2 * i + 1] = h23;
        ((uint32_t*)lo)[2 * i]     = l01;
        ((uint32_t*)lo)[2 * i + 1] = l23;
    } else {
        ((uint32_t*)hi)[2 * i]     = cvt2h(v.x, v.y);
        ((uint32_t*)hi)[2 * i + 1] = cvt2h(v.z, v.w);
    }
}

// ---------------------------------------------------------------------------
// HMMA GEMM body: C = A[M,K] @ B[N,K]^T + bias.
// A = Ah + Al (fp16 split), B = Bh only -> 2 MMAs (err ~2^-12 from B residue).
// CTA tile 128x128, K-chunk 32, double-buffered cp.async, ldmatrix frags,
// ONE barrier per chunk.
// OUT: 0 = fp32 C; 1 = fp16 split Ch+Cl; 2 = fp16 hi Ch only.
// ---------------------------------------------------------------------------
#define SSTR  20                     // u32 per smem row
#define GARRB (128 * SSTR * 4)       // bytes per array (10240)
#define GBUFB (3 * GARRB)            // bytes per buffer (30720)
#define GEMM_SMEM (2 * GBUFB)        // 61440

template<int OUT>
__device__ __forceinline__ void
gemm_body(uint32_t* sg,
          const __half* __restrict__ Ah, const __half* __restrict__ Al,
          const __half* __restrict__ Bh,
          const float* __restrict__ bias, float* __restrict__ C,
          __half* __restrict__ Ch, __half* __restrict__ Cl,
          int M, int N, int K)
{
    const uint32_t sbase = smem_u32(sg);

    const int tid  = threadIdx.x;
    const int lane = tid & 31;
    const int warp = tid >> 5;
    const int wm   = (warp >> 1) * 32;
    const int wn   = (warp & 1) * 64;
    const int m0   = blockIdx.y * 128;
    const int n0   = blockIdx.x * 128;

    uint32_t s_off[2];
    size_t gA[2], gB[2];
    #pragma unroll
    for (int t = 0; t < 2; t++) {
        int f   = tid + t * 256;
        int row = f >> 2;
        int c4  = (f & 3) * 4;
        s_off[t] = (uint32_t)(row * SSTR + c4) * 4;
        gA[t] = (size_t)(m0 + row) * K + c4 * 2;
        gB[t] = (size_t)(n0 + row) * K + c4 * 2;
    }

    const int arow  = (lane & 7) + ((lane >> 3) & 1) * 8;
    const int acol  = (lane >> 4) * 4;
    const int brow  = (lane & 7) + (lane >> 4) * 8;
    const int bcol4 = ((lane >> 3) & 1) * 4;

    uint32_t aoff[2], boff[4];
    #pragma unroll
    for (int mt = 0; mt < 2; mt++)
        aoff[mt] = (uint32_t)((wm + mt * 16 + arow) * SSTR + acol) * 4;
    #pragma unroll
    for (int np = 0; np < 4; np++)
        boff[np] = (uint32_t)((wn + np * 16 + brow) * SSTR + bcol4) * 4;

    const int fr = lane >> 2;
    const int fc = lane & 3;

    float acc[2][8][4];
    #pragma unroll
    for (int mt = 0; mt < 2; mt++)
        #pragma unroll
        for (int nt = 0; nt < 8; nt++)
            #pragma unroll
            for (int j = 0; j < 4; j++) acc[mt][nt][j] = 0.f;

    const int nchunks = K / 32;

    // prefetch chunk 0 -> buffer 0
    #pragma unroll
    for (int t = 0; t < 2; t++) {
        cpa16(sbase + 0 * GARRB + s_off[t], Ah + gA[t]);
        cpa16(sbase + 1 * GARRB + s_off[t], Al + gA[t]);
        cpa16(sbase + 2 * GARRB + s_off[t], Bh + gB[t]);
    }
    cpa_commit();

    for (int kc = 0; kc < nchunks; kc++) {
        cpa_wait<0>();
        __syncthreads();

        if (kc + 1 < nchunks) {
            const uint32_t bb = sbase + ((kc + 1) & 1) * GBUFB;
            const int ko = (kc + 1) * 32;
            #pragma unroll
            for (int t = 0; t < 2; t++) {
                cpa16(bb + 0 * GARRB + s_off[t], Ah + gA[t] + ko);
                cpa16(bb + 1 * GARRB + s_off[t], Al + gA[t] + ko);
                cpa16(bb + 2 * GARRB + s_off[t], Bh + gB[t] + ko);
            }
            cpa_commit();
        }

        const uint32_t cb  = sbase + (kc & 1) * GBUFB;
        const uint32_t aAh = cb, aAl = cb + GARRB, aBh = cb + 2 * GARRB;

        #pragma unroll
        for (int ks = 0; ks < 2; ks++) {
            const uint32_t kbb = (uint32_t)(ks * 8) * 4;
            uint32_t afh[2][4], afl[2][4];
            #pragma unroll
            for (int mt = 0; mt < 2; mt++) {
                ldm_x4(afh[mt], aAh + aoff[mt] + kbb);
                ldm_x4(afl[mt], aAl + aoff[mt] + kbb);
            }
            #pragma unroll
            for (int np = 0; np < 4; np++) {
                uint32_t b4h[4];
                ldm_x4(b4h, aBh + boff[np] + kbb);
                #pragma unroll
                for (int hf = 0; hf < 2; hf++) {
                    const int nt = np * 2 + hf;
                    #pragma unroll
                    for (int mt = 0; mt < 2; mt++) {
                        mma16816(acc[mt][nt], afh[mt], &b4h[hf * 2]);
                        mma16816(acc[mt][nt], afl[mt], &b4h[hf * 2]);
                    }
                }
            }
        }
    }

    #pragma unroll
    for (int mt = 0; mt < 2; mt++) {
        #pragma unroll
        for (int nt = 0; nt < 8; nt++) {
            int row = m0 + wm + mt * 16 + fr;
            int col = n0 + wn + nt * 8 + fc * 2;
            float b0 = __ldg(&bias[col]);
            float b1 = __ldg(&bias[col + 1]);
            float c0 = acc[mt][nt][0] + b0, c1 = acc[mt][nt][1] + b1;
            float c2 = acc[mt][nt][2] + b0, c3 = acc[mt][nt][3] + b1;
            if (OUT == 1) {
                uint32_t hi, lo;
                split2h(c0, c1, hi, lo);
                *(uint32_t*)&Ch[(size_t)row * N + col] = hi;
                *(uint32_t*)&Cl[(size_t)row * N + col] = lo;
                split2h(c2, c3, hi, lo);
                *(uint32_t*)&Ch[(size_t)(row + 8) * N + col] = hi;
                *(uint32_t*)&Cl[(size_t)(row + 8) * N + col] = lo;
            } else if (OUT == 2) {
                *(uint32_t*)&Ch[(size_t)row * N + col]       = cvt2h(c0, c1);
                *(uint32_t*)&Ch[(size_t)(row + 8) * N + col] = cvt2h(c2, c3);
            } else {
                *(float2*)&C[(size_t)row * N + col]       = make_float2(c0, c1);
                *(float2*)&C[(size_t)(row + 8) * N + col] = make_float2(c2, c3);
            }
        }
    }
}

struct GemmBatch {
    const __half* Bh[3];
    const float* bias[3];
    __half* Ch[3];
    __half* Cl[3];
};

// merged Q/K/V projection: z=0 -> split out (Q), z=1,2 -> hi-only out (K,V)
__global__ void __launch_bounds__(256, 2)
gemm_qkv(GemmBatch gb, const __half* __restrict__ Ah,
         const __half* __restrict__ Al)
{
    extern __shared__ uint32_t sg[];
    const int z = blockIdx.z;
    if (z == 0)
        gemm_body<1>(sg, Ah, Al, gb.Bh[0], gb.bias[0], nullptr,
                     gb.Ch[0], gb.Cl[0], MROWS, CDIM, CDIM);
    else
        gemm_body<2>(sg, Ah, Al, gb.Bh[z], gb.bias[z], nullptr,
                     gb.Ch[z], nullptr, MROWS, CDIM, CDIM);
}

__global__ void __launch_bounds__(256, 2)
gemm_o(const __half* __restrict__ Ah, const __half* __restrict__ Al,
       const __half* __restrict__ Bh,
       const float* __restrict__ bias, float* __restrict__ C)
{
    extern __shared__ uint32_t sg[];
    gemm_body<0>(sg, Ah, Al, Bh, bias, C, nullptr, nullptr,
                 MROWS, CDIM, CDIM);
}

// ---------------------------------------------------------------------------
// HMMA flash attention (causal). fp16: Q split (qh,ql), K/V hi only.
// S = qh*K + ql*K (2 MMAs); P split in regs; PV = ph*V + pl*V (2 MMAs).
// 128-row q tile/CTA, Bc=64, double-buffered cp.async KV, ldmatrix frags,
// longest-qt-first, ONE barrier per kv tile.
// ---------------------------------------------------------------------------
#define QSTR 36
#define QARR (128 * QSTR)              // 4608 u32
#define KARR (64 * QSTR)               // 2304 u32
#define KBUF (2 * KARR)                // u32 per kv buffer (kh + vh)
#define ATTN_SMEM ((2 * QARR + 2 * KBUF) * 4)   // 73728 B

__global__ void __launch_bounds__(256, 2)
attn_mma(const __half* __restrict__ Qh, const __half* __restrict__ Ql,
         const __half* __restrict__ Kh, const __half* __restrict__ Vh,
         __half* __restrict__ Yh, __half* __restrict__ Yl)
{
    extern __shared__ uint32_t s32[];
    const uint32_t sbase = smem_u32(s32);
    const uint32_t aQh = sbase;
    const uint32_t aQl = sbase + QARR * 4;

    const int qt = gridDim.x - 1 - blockIdx.x;   // longest-first
    const int bh = blockIdx.y;
    const int b  = bh >> 4;
    const int h  = bh & 15;
    const size_t headoff = (size_t)b * TSEQ * CDIM + (size_t)h * HDIM;

    const int tid  = threadIdx.x;
    const int lane = tid & 31;
    const int warp = tid >> 5;
    const int fr   = lane >> 2;
    const int fc   = lane & 3;
    const int wm   = warp * 16;

    const int arow  = (lane & 7) + ((lane >> 3) & 1) * 8;
    const int acol  = (lane >> 4) * 4;
    const int brow  = (lane & 7) + (lane >> 4) * 8;
    const int bcol4 = ((lane >> 3) & 1) * 4;
    const uint32_t qoff = (uint32_t)((wm + arow) * QSTR + acol) * 4;
    uint32_t koff[4], voff[4];
    #pragma unroll
    for (int np = 0; np < 4; np++) {
        koff[np] = (uint32_t)((np * 16 + brow) * QSTR + bcol4) * 4;
        voff[np] = (uint32_t)(arow * QSTR + (np * 2 + (lane >> 4)) * 4) * 4;
    }

    // Q tile via cp.async (with KV tile 0, one group)
    #pragma unroll
    for (int t = 0; t < 4; t++) {
        int f  = tid + t * 256;
        int r  = f >> 3;
        int c8 = f & 7;
        size_t g = headoff + (size_t)(qt * 128 + r) * CDIM + c8 * 8;
        uint32_t so = (uint32_t)(r * QSTR + c8 * 4) * 4;
        cpa16(aQh + so, Qh + g);
        cpa16(aQl + so, Ql + g);
    }

    uint32_t kvso[2];
    size_t kvg[2];
    #pragma unroll
    for (int t = 0; t < 2; t++) {
        int f  = tid + t * 256;
        int r  = f >> 3;
        int c8 = f & 7;
        kvso[t] = (uint32_t)(r * QSTR + c8 * 4) * 4;
        kvg[t]  = headoff + (size_t)r * CDIM + c8 * 8;
    }
    const uint32_t kvbase = sbase + 2 * QARR * 4;

    const int ktmax = 2 * qt + 1;

    // prefetch kv tile 0 -> buffer 0
    #pragma unroll
    for (int t = 0; t < 2; t++) {
        cpa16(kvbase + 0 * KARR * 4 + kvso[t], Kh + kvg[t]);
        cpa16(kvbase + 1 * KARR * 4 + kvso[t], Vh + kvg[t]);
    }
    cpa_commit();

    const float scale = 0.125f;
    float o[8][4];
    #pragma unroll
    for (int nt = 0; nt < 8; nt++)
        #pragma unroll
        for (int j = 0; j < 4; j++) o[nt][j] = 0.f;
    float mA = -INFINITY, mB = -INFINITY, lA = 0.f, lB = 0.f;

    const int rowAg = qt * 128 + wm + fr;
    const int rowBg = rowAg + 8;

    for (int kt = 0; kt <= ktmax; kt++) {
        cpa_wait<0>();
        __syncthreads();

        if (kt < ktmax) {
            const uint32_t bb = kvbase + ((kt + 1) & 1) * KBUF * 4;
            const size_t go = (size_t)(kt + 1) * 64 * CDIM;
            #pragma unroll
            for (int t = 0; t < 2; t++) {
                cpa16(bb + 0 * KARR * 4 + kvso[t], Kh + kvg[t] + go);
                cpa16(bb + 1 * KARR * 4 + kvso[t], Vh + kvg[t] + go);
            }
            cpa_commit();
        }

        const uint32_t cb  = kvbase + (kt & 1) * KBUF * 4;
        const uint32_t aKh = cb, aVh = cb + KARR * 4;

        // S = Q K^T (2 MMAs per fragment)
        float sacc[8][4];
        #pragma unroll
        for (int nt = 0; nt < 8; nt++)
            #pragma unroll
            for (int j = 0; j < 4; j++) sacc[nt][j] = 0.f;

        #pragma unroll
        for (int ks = 0; ks < 4; ks++) {
            const uint32_t kbb = (uint32_t)(ks * 8) * 4;
            uint32_t ah[4], al[4];
            ldm_x4(ah, aQh + qoff + kbb);
            ldm_x4(al, aQl + qoff + kbb);
            #pragma unroll
            for (int np = 0; np < 4; np++) {
                uint32_t k4h[4];
                ldm_x4(k4h, aKh + koff[np] + kbb);
                #pragma unroll
                for (int hf = 0; hf < 2; hf++) {
                    const int nt = np * 2 + hf;
                    mma16816(sacc[nt], ah, &k4h[hf * 2]);
                    mma16816(sacc[nt], al, &k4h[hf * 2]);
                }
            }
        }

        // scale + causal mask
        const bool diag = (kt >= 2 * qt);
        #pragma unroll
        for (int nt = 0; nt < 8; nt++) {
            #pragma unroll
            for (int j = 0; j < 4; j++) sacc[nt][j] *= scale;
            if (diag) {
                int col0 = kt * 64 + nt * 8 + 2 * fc;
                if (col0     > rowAg) sacc[nt][0] = -INFINITY;
                if (col0 + 1 > rowAg) sacc[nt][1] = -INFINITY;
                if (col0     > rowBg) sacc[nt][2] = -INFINITY;
                if (col0 + 1 > rowBg) sacc[nt][3] = -INFINITY;
            }
        }

        // online softmax
        float mxA = -INFINITY, mxB = -INFINITY;
        #pragma unroll
        for (int nt = 0; nt < 8; nt++) {
            mxA = fmaxf(mxA, fmaxf(sacc[nt][0], sacc[nt][1]));
            mxB = fmaxf(mxB, fmaxf(sacc[nt][2], sacc[nt][3]));
        }
        mxA = fmaxf(mxA, __shfl_xor_sync(0xffffffffu, mxA, 1));
        mxA = fmaxf(mxA, __shfl_xor_sync(0xffffffffu, mxA, 2));
        mxB = fmaxf(mxB, __shfl_xor_sync(0xffffffffu, mxB, 1));
        mxB = fmaxf(mxB, __shfl_xor_sync(0xffffffffu, mxB, 2));

        float mnA = fmaxf(mA, mxA), mnB = fmaxf(mB, mxB);
        float aA = __expf(mA - mnA), aB = __expf(mB - mnB);
        mA = mnA; mB = mnB;

        float lsA = 0.f, lsB = 0.f;
        #pragma unroll
        for (int nt = 0; nt < 8; nt++) {
            sacc[nt][0] = __expf(sacc[nt][0] - mnA);
            sacc[nt][1] = __expf(sacc[nt][1] - mnA);
            sacc[nt][2] = __expf(sacc[nt][2] - mnB);
            sacc[nt][3] = __expf(sacc[nt][3] - mnB);
            lsA += sacc[nt][0] + sacc[nt][1];
            lsB += sacc[nt][2] + sacc[nt][3];
        }
        lsA += __shfl_xor_sync(0xffffffffu, lsA, 1);
        lsA += __shfl_xor_sync(0xffffffffu, lsA, 2);
        lsB += __shfl_xor_sync(0xffffffffu, lsB, 1);
        lsB += __shfl_xor_sync(0xffffffffu, lsB, 2);
        lA = lA * aA + lsA;
        lB = lB * aB + lsB;

        #pragma unroll
        for (int nt = 0; nt < 8; nt++) {
            o[nt][0] *= aA; o[nt][1] *= aA;
            o[nt][2] *= aB; o[nt][3] *= aB;
        }

        // O += P V (P split in regs, V hi only -> 2 MMAs)
        #pragma unroll
        for (int ks = 0; ks < 4; ks++) {
            uint32_t ph[4], pl[4];
            split2h(sacc[2 * ks][0],     sacc[2 * ks][1],     ph[0], pl[0]);
            split2h(sacc[2 * ks][2],     sacc[2 * ks][3],     ph[1], pl[1]);
            split2h(sacc[2 * ks + 1][0], sacc[2 * ks + 1][1], ph[2], pl[2]);
            split2h(sacc[2 * ks + 1][2], sacc[2 * ks + 1][3], ph[3], pl[3]);
            const uint32_t ro = (uint32_t)(ks * 16 * QSTR) * 4;
            #pragma unroll
            for (int np = 0; np < 4; np++) {
                uint32_t v4h[4];
                ldm_x4_trans(v4h, aVh + ro + voff[np]);
                #pragma unroll
                for (int hf = 0; hf < 2; hf++) {
                    const int nt = np * 2 + hf;
                    mma16816(o[nt], ph, &v4h[hf * 2]);
                    mma16816(o[nt], pl, &v4h[hf * 2]);
                }
            }
        }
    }

    // normalize + write hi/lo fp16
    float liA = 1.0f / lA, liB = 1.0f / lB;
    #pragma unroll
    for (int nt = 0; nt < 8; nt++) {
        int col = nt * 8 + 2 * fc;
        size_t gA = headoff + (size_t)rowAg * CDIM + col;
        size_t gB = headoff + (size_t)rowBg * CDIM + col;
        uint32_t hi, lo;
        split2h(o[nt][0] * liA, o[nt][1] * liA, hi, lo);
        *(uint32_t*)&Yh[gA] = hi;
        *(uint32_t*)&Yl[gA] = lo;
        split2h(o[nt][2] * liB, o[nt][3] * liB, hi, lo);
        *(uint32_t*)&Yh[gB] = hi;
        *(uint32_t*)&Yl[gB] = lo;
    }
}

// ---------------------------------------------------------------------------
// Launch
// ---------------------------------------------------------------------------
extern "C" void kernel_launch(void* const* d_in, const int* in_sizes, int n_in,
                              void* d_out, int out_size)
{
    const float* x  = (const float*)d_in[0];
    const float* Wq = (const float*)d_in[1];
    const float* bq = (const float*)d_in[2];
    const float* Wk = (const float*)d_in[3];
    const float* bk = (const float*)d_in[4];
    const float* Wv = (const float*)d_in[5];
    const float* bv = (const float*)d_in[6];
    const float* Wo = (const float*)d_in[7];
    const float* bo = (const float*)d_in[8];
    float* out = (float*)d_out;

    __half *xh, *xl, *qh, *ql, *kh, *vh, *yh, *yl;
    __half *wqh, *wkh, *wvh, *woh;
    cudaGetSymbolAddress((void**)&xh, g_xh);
    cudaGetSymbolAddress((void**)&xl, g_xl);
    cudaGetSymbolAddress((void**)&qh, g_qh);
    cudaGetSymbolAddress((void**)&ql, g_ql);
    cudaGetSymbolAddress((void**)&kh, g_kh);
    cudaGetSymbolAddress((void**)&vh, g_vh);
    cudaGetSymbolAddress((void**)&yh, g_yh);
    cudaGetSymbolAddress((void**)&yl, g_yl);
    cudaGetSymbolAddress((void**)&wqh, g_wqh);
    cudaGetSymbolAddress((void**)&wkh, g_wkh);
    cudaGetSymbolAddress((void**)&wvh, g_wvh);
    cudaGetSymbolAddress((void**)&woh, g_woh);

    cudaFuncSetAttribute(attn_mma,
                         cudaFuncAttributeMaxDynamicSharedMemorySize, ATTN_SMEM);
    cudaFuncSetAttribute(gemm_qkv,
                         cudaFuncAttributeMaxDynamicSharedMemorySize, GEMM_SMEM);
    cudaFuncSetAttribute(gemm_o,
                         cudaFuncAttributeMaxDynamicSharedMemorySize, GEMM_SMEM);

    const int nw4 = CDIM * CDIM / 4;   // float4 per weight / x-quarter
    const int xq  = CDIM * CDIM;       // elements per x quarter

    // 1) all splits/converts in one launch
    SplitAll sa;
    sa.in[0] = Wq; sa.hi[0] = wqh; sa.lo[0] = nullptr;
    sa.in[1] = Wk; sa.hi[1] = wkh; sa.lo[1] = nullptr;
    sa.in[2] = Wv; sa.hi[2] = wvh; sa.lo[2] = nullptr;
    sa.in[3] = Wo; sa.hi[3] = woh; sa.lo[3] = nullptr;
    for (int q = 0; q < 4; q++) {
        sa.in[4 + q] = x + (size_t)q * xq;
        sa.hi[4 + q] = xh + (size_t)q * xq;
        sa.lo[4 + q] = xl + (size_t)q * xq;
    }
    dim3 sgrid(nw4 / 256, 8);
    split8_kernel<<<sgrid, 256>>>(sa, nw4);

    // 2) merged Q/K/V projection
    GemmBatch gb;
    gb.Bh[0] = wqh; gb.bias[0] = bq; gb.Ch[0] = qh; gb.Cl[0] = ql;
    gb.Bh[1] = wkh; gb.bias[1] = bk; gb.Ch[1] = kh; gb.Cl[1] = nullptr;
    gb.Bh[2] = wvh; gb.bias[2] = bv; gb.Ch[2] = vh; gb.Cl[2] = nullptr;
    dim3 qkvgrid(CDIM / 128, MROWS / 128, 3);   // (8, 32, 3)
    gemm_qkv<<<qkvgrid, 256, GEMM_SMEM>>>(gb, xh, xl);

    // 3) attention
    dim3 agrid(TSEQ / 128, BATCH * NHEAD);  // (16, 32)
    attn_mma<<<agrid, 256, ATTN_SMEM>>>(qh, ql, kh, vh, yh, yl);

    // 4) output projection
    dim3 ogrid(CDIM / 128, MROWS / 128);    // (8, 32)
    gemm_o<<<ogrid, 256, GEMM_SMEM>>>(yh, yl, woh, bo, out);
}

// round 11
// speedup vs baseline: 6.2373x; 1.1556x over previous
#include <cuda_runtime.h>
#include <cuda_fp16.h>
#include <math.h>
#include <stdint.h>

// Problem constants
#define BATCH 2
#define TSEQ  2048
#define CDIM  1024
#define NHEAD 16
#define HDIM  64
#define MROWS (BATCH * TSEQ)   // 4096

// ---------------------------------------------------------------------------
// Scratch (allocation-free: __device__ globals)
// ---------------------------------------------------------------------------
__device__ __align__(16) __half g_xh[MROWS * CDIM];
__device__ __align__(16) __half g_xl[MROWS * CDIM];
__device__ __align__(16) __half g_qh[MROWS * CDIM];
__device__ __align__(16) __half g_ql[MROWS * CDIM];
__device__ __align__(16) __half g_kh[MROWS * CDIM];
__device__ __align__(16) __half g_vh[MROWS * CDIM];
__device__ __align__(16) __half g_yh[MROWS * CDIM];
__device__ __align__(16) __half g_yl[MROWS * CDIM];
__device__ __align__(16) __half g_wqh[CDIM * CDIM];
__device__ __align__(16) __half g_wkh[CDIM * CDIM];
__device__ __align__(16) __half g_wvh[CDIM * CDIM];
__device__ __align__(16) __half g_woh[CDIM * CDIM];

// ---------------------------------------------------------------------------
// PTX helpers (baseline PTX, valid for compute_103)
// ---------------------------------------------------------------------------
__device__ __forceinline__ void mma16816(float* c, const uint32_t* a,
                                         const uint32_t* b) {
    asm volatile(
        "mma.sync.aligned.m16n8k16.row.col.f32.f16.f16.f32 "
        "{%0,%1,%2,%3}, {%4,%5,%6,%7}, {%8,%9}, {%0,%1,%2,%3};"
        : "+f"(c[0]), "+f"(c[1]), "+f"(c[2]), "+f"(c[3])
        : "r"(a[0]), "r"(a[1]), "r"(a[2]), "r"(a[3]), "r"(b[0]), "r"(b[1]));
}

__device__ __forceinline__ void ldm_x4(uint32_t* r, uint32_t saddr) {
    asm volatile(
        "ldmatrix.sync.aligned.m8n8.x4.shared.b16 {%0,%1,%2,%3}, [%4];"
        : "=r"(r[0]), "=r"(r[1]), "=r"(r[2]), "=r"(r[3]) : "r"(saddr));
}

__device__ __forceinline__ void ldm_x4_trans(uint32_t* r, uint32_t saddr) {
    asm volatile(
        "ldmatrix.sync.aligned.m8n8.x4.trans.shared.b16 {%0,%1,%2,%3}, [%4];"
        : "=r"(r[0]), "=r"(r[1]), "=r"(r[2]), "=r"(r[3]) : "r"(saddr));
}

__device__ __forceinline__ uint32_t smem_u32(const void* p) {
    uint32_t a;
    asm("{ .reg .u64 t; cvta.to.shared.u64 t, %1; cvt.u32.u64 %0, t; }"
        : "=r"(a) : "l"(p));
    return a;
}

__device__ __forceinline__ void cpa16(uint32_t s, const void* g) {
    asm volatile("cp.async.cg.shared.global [%0], [%1], 16;"
                 :: "r"(s), "l"(g));
}
__device__ __forceinline__ void cpa_commit() {
    asm volatile("cp.async.commit_group;");
}
template<int N> __device__ __forceinline__ void cpa_wait() {
    asm volatile("cp.async.wait_group %0;" :: "n"(N));
}

__device__ __forceinline__ uint32_t packh(__half a, __half b) {
    __half2 t = __halves2half2(a, b);
    return *(uint32_t*)&t;
}

// split two fp32 -> packed hi fp16x2 + packed lo fp16x2
__device__ __forceinline__ void split2h(float a, float b,
                                        uint32_t& hi, uint32_t& lo) {
    __half ha = __float2half_rn(a);
    __half hb = __float2half_rn(b);
    __half la = __float2half_rn(a - __half2float(ha));
    __half lb = __float2half_rn(b - __half2float(hb));
    hi = packh(ha, hb);
    lo = packh(la, lb);
}

__device__ __forceinline__ uint32_t cvt2h(float a, float b) {
    return packh(__float2half_rn(a), __float2half_rn(b));
}

// ---------------------------------------------------------------------------
// Split kernel: 8 segments. y<4: weights (hi only). y>=4: x quarters (hi+lo).
// ---------------------------------------------------------------------------
struct SplitAll {
    const float* in[8];
    __half* hi[8];
    __half* lo[8];   // nullptr -> convert only
};

__global__ void __launch_bounds__(256)
split8_kernel(SplitAll sb, int n4)
{
    int i = blockIdx.x * blockDim.x + threadIdx.x;
    if (i >= n4) return;
    const float* in = sb.in[blockIdx.y];
    __half* hi = sb.hi[blockIdx.y];
    __half* lo = sb.lo[blockIdx.y];
    float4 v = ((const float4*)in)[i];
    if (lo) {
        uint32_t h01, l01, h23, l23;
        split2h(v.x, v.y, h01, l01);
        split2h(v.z, v.w, h23, l23);
        ((uint32_t*)hi)[2 * i]     = h01;
        ((uint32_t*)hi)[2 * i + 1] = h23;
        ((uint32_t*)lo)[2 * i]     = l01;
        ((uint32_t*)lo)[2 * i + 1] = l23;
    } else {
        ((uint32_t*)hi)[2 * i]     = cvt2h(v.x, v.y);
        ((uint32_t*)hi)[2 * i + 1] = cvt2h(v.z, v.w);
    }
}

// ---------------------------------------------------------------------------
// HMMA GEMM body: C = A[M,K] @ B[N,K]^T + bias.
// A = Ah + Al (fp16 split), B = Bh only -> 2 MMAs.
// CTA tile 128x128, K-chunk 64 (16 barriers), double-buffered cp.async,
// ldmatrix frags, ONE barrier per chunk.
// OUT: 0 = fp32 C; 1 = fp16 split Ch+Cl; 2 = fp16 hi Ch only.
// ---------------------------------------------------------------------------
#define SSTR  36                     // u32 per smem row (64 fp16 + pad)
#define GARRB (128 * SSTR * 4)       // bytes per array (18432)
#define GBUFB (3 * GARRB)            // bytes per buffer (55296)
#define GEMM_SMEM (2 * GBUFB)        // 110592

template<int OUT>
__device__ __forceinline__ void
gemm_body(uint32_t* sg,
          const __half* __restrict__ Ah, const __half* __restrict__ Al,
          const __half* __restrict__ Bh,
          const float* __restrict__ bias, float* __restrict__ C,
          __half* __restrict__ Ch, __half* __restrict__ Cl,
          int M, int N, int K)
{
    const uint32_t sbase = smem_u32(sg);

    const int tid  = threadIdx.x;
    const int lane = tid & 31;
    const int warp = tid >> 5;
    const int wm   = (warp >> 1) * 32;
    const int wn   = (warp & 1) * 64;
    const int m0   = blockIdx.y * 128;
    const int n0   = blockIdx.x * 128;

    // cp.async slots: 4 per array; f = tid + t*256, row = f>>3, c8 = f&7
    uint32_t s_off[4];
    size_t gA[4], gB[4];
    #pragma unroll
    for (int t = 0; t < 4; t++) {
        int f   = tid + t * 256;
        int row = f >> 3;
        int c8  = f & 7;
        s_off[t] = (uint32_t)(row * SSTR + c8 * 4) * 4;
        gA[t] = (size_t)(m0 + row) * K + c8 * 8;
        gB[t] = (size_t)(n0 + row) * K + c8 * 8;
    }

    const int arow  = (lane & 7) + ((lane >> 3) & 1) * 8;
    const int acol  = (lane >> 4) * 4;
    const int brow  = (lane & 7) + (lane >> 4) * 8;
    const int bcol4 = ((lane >> 3) & 1) * 4;

    uint32_t aoff[2], boff[4];
    #pragma unroll
    for (int mt = 0; mt < 2; mt++)
        aoff[mt] = (uint32_t)((wm + mt * 16 + arow) * SSTR + acol) * 4;
    #pragma unroll
    for (int np = 0; np < 4; np++)
        boff[np] = (uint32_t)((wn + np * 16 + brow) * SSTR + bcol4) * 4;

    const int fr = lane >> 2;
    const int fc = lane & 3;

    float acc[2][8][4];
    #pragma unroll
    for (int mt = 0; mt < 2; mt++)
        #pragma unroll
        for (int nt = 0; nt < 8; nt++)
            #pragma unroll
            for (int j = 0; j < 4; j++) acc[mt][nt][j] = 0.f;

    const int nchunks = K / 64;   // 16

    // prefetch chunk 0 -> buffer 0
    #pragma unroll
    for (int t = 0; t < 4; t++) {
        cpa16(sbase + 0 * GARRB + s_off[t], Ah + gA[t]);
        cpa16(sbase + 1 * GARRB + s_off[t], Al + gA[t]);
        cpa16(sbase + 2 * GARRB + s_off[t], Bh + gB[t]);
    }
    cpa_commit();

    for (int kc = 0; kc < nchunks; kc++) {
        cpa_wait<0>();
        __syncthreads();

        if (kc + 1 < nchunks) {
            const uint32_t bb = sbase + ((kc + 1) & 1) * GBUFB;
            const int ko = (kc + 1) * 64;
            #pragma unroll
            for (int t = 0; t < 4; t++) {
                cpa16(bb + 0 * GARRB + s_off[t], Ah + gA[t] + ko);
                cpa16(bb + 1 * GARRB + s_off[t], Al + gA[t] + ko);
                cpa16(bb + 2 * GARRB + s_off[t], Bh + gB[t] + ko);
            }
            cpa_commit();
        }

        const uint32_t cb  = sbase + (kc & 1) * GBUFB;
        const uint32_t aAh = cb, aAl = cb + GARRB, aBh = cb + 2 * GARRB;

        #pragma unroll
        for (int ks = 0; ks < 4; ks++) {
            const uint32_t kbb = (uint32_t)(ks * 8) * 4;
            uint32_t afh[2][4], afl[2][4];
            #pragma unroll
            for (int mt = 0; mt < 2; mt++) {
                ldm_x4(afh[mt], aAh + aoff[mt] + kbb);
                ldm_x4(afl[mt], aAl + aoff[mt] + kbb);
            }
            #pragma unroll
            for (int np = 0; np < 4; np++) {
                uint32_t b4h[4];
                ldm_x4(b4h, aBh + boff[np] + kbb);
                #pragma unroll
                for (int hf = 0; hf < 2; hf++) {
                    const int nt = np * 2 + hf;
                    #pragma unroll
                    for (int mt = 0; mt < 2; mt++) {
                        mma16816(acc[mt][nt], afh[mt], &b4h[hf * 2]);
                        mma16816(acc[mt][nt], afl[mt], &b4h[hf * 2]);
                    }
                }
            }
        }
    }

    #pragma unroll
    for (int mt = 0; mt < 2; mt++) {
        #pragma unroll
        for (int nt = 0; nt < 8; nt++) {
            int row = m0 + wm + mt * 16 + fr;
            int col = n0 + wn + nt * 8 + fc * 2;
            float b0 = __ldg(&bias[col]);
            float b1 = __ldg(&bias[col + 1]);
            float c0 = acc[mt][nt][0] + b0, c1 = acc[mt][nt][1] + b1;
            float c2 = acc[mt][nt][2] + b0, c3 = acc[mt][nt][3] + b1;
            if (OUT == 1) {
                uint32_t hi, lo;
                split2h(c0, c1, hi, lo);
                *(uint32_t*)&Ch[(size_t)row * N + col] = hi;
                *(uint32_t*)&Cl[(size_t)row * N + col] = lo;
                split2h(c2, c3, hi, lo);
                *(uint32_t*)&Ch[(size_t)(row + 8) * N + col] = hi;
                *(uint32_t*)&Cl[(size_t)(row + 8) * N + col] = lo;
            } else if (OUT == 2) {
                *(uint32_t*)&Ch[(size_t)row * N + col]       = cvt2h(c0, c1);
                *(uint32_t*)&Ch[(size_t)(row + 8) * N + col] = cvt2h(c2, c3);
            } else {
                *(float2*)&C[(size_t)row * N + col]       = make_float2(c0, c1);
                *(float2*)&C[(size_t)(row + 8) * N + col] = make_float2(c2, c3);
            }
        }
    }
}

struct GemmBatch {
    const __half* Bh[3];
    const float* bias[3];
    __half* Ch[3];
    __half* Cl[3];
};

__global__ void __launch_bounds__(256, 2)
gemm_qkv(GemmBatch gb, const __half* __restrict__ Ah,
         const __half* __restrict__ Al)
{
    extern __shared__ uint32_t sg[];
    const int z = blockIdx.z;
    if (z == 0)
        gemm_body<1>(sg, Ah, Al, gb.Bh[0], gb.bias[0], nullptr,
                     gb.Ch[0], gb.Cl[0], MROWS, CDIM, CDIM);
    else
        gemm_body<2>(sg, Ah, Al, gb.Bh[z], gb.bias[z], nullptr,
                     gb.Ch[z], nullptr, MROWS, CDIM, CDIM);
}

__global__ void __launch_bounds__(256, 2)
gemm_o(const __half* __restrict__ Ah, const __half* __restrict__ Al,
       const __half* __restrict__ Bh,
       const float* __restrict__ bias, float* __restrict__ C)
{
    extern __shared__ uint32_t sg[];
    gemm_body<0>(sg, Ah, Al, Bh, bias, C, nullptr, nullptr,
                 MROWS, CDIM, CDIM);
}

// ---------------------------------------------------------------------------
// HMMA flash attention (causal). fp16: Q split (qh,ql), K/V hi only.
// S = qh*K + ql*K (2 MMAs); PV = ph*V only (1 MMA; P residue ~2^-11 rms ok).
// 128-row q tile/CTA, Bc=64, double-buffered cp.async KV, ldmatrix frags,
// longest-qt-first, ONE barrier per kv tile.
// ---------------------------------------------------------------------------
#define QSTR 36
#define QARR (128 * QSTR)              // 4608 u32
#define KARR (64 * QSTR)               // 2304 u32
#define KBUF (2 * KARR)                // u32 per kv buffer (kh + vh)
#define ATTN_SMEM ((2 * QARR + 2 * KBUF) * 4)   // 73728 B

__global__ void __launch_bounds__(256, 2)
attn_mma(const __half* __restrict__ Qh, const __half* __restrict__ Ql,
         const __half* __restrict__ Kh, const __half* __restrict__ Vh,
         __half* __restrict__ Yh, __half* __restrict__ Yl)
{
    extern __shared__ uint32_t s32[];
    const uint32_t sbase = smem_u32(s32);
    const uint32_t aQh = sbase;
    const uint32_t aQl = sbase + QARR * 4;

    const int qt = gridDim.x - 1 - blockIdx.x;   // longest-first
    const int bh = blockIdx.y;
    const int b  = bh >> 4;
    const int h  = bh & 15;
    const size_t headoff = (size_t)b * TSEQ * CDIM + (size_t)h * HDIM;

    const int tid  = threadIdx.x;
    const int lane = tid & 31;
    const int warp = tid >> 5;
    const int fr   = lane >> 2;
    const int fc   = lane & 3;
    const int wm   = warp * 16;

    const int arow  = (lane & 7) + ((lane >> 3) & 1) * 8;
    const int acol  = (lane >> 4) * 4;
    const int brow  = (lane & 7) + (lane >> 4) * 8;
    const int bcol4 = ((lane >> 3) & 1) * 4;
    const uint32_t qoff = (uint32_t)((wm + arow) * QSTR + acol) * 4;
    uint32_t koff[4], voff[4];
    #pragma unroll
    for (int np = 0; np < 4; np++) {
        koff[np] = (uint32_t)((np * 16 + brow) * QSTR + bcol4) * 4;
        voff[np] = (uint32_t)(arow * QSTR + (np * 2 + (lane >> 4)) * 4) * 4;
    }

    // Q tile via cp.async (with KV tile 0, one group)
    #pragma unroll
    for (int t = 0; t < 4; t++) {
        int f  = tid + t * 256;
        int r  = f >> 3;
        int c8 = f & 7;
        size_t g = headoff + (size_t)(qt * 128 + r) * CDIM + c8 * 8;
        uint32_t so = (uint32_t)(r * QSTR + c8 * 4) * 4;
        cpa16(aQh + so, Qh + g);
        cpa16(aQl + so, Ql + g);
    }

    uint32_t kvso[2];
    size_t kvg[2];
    #pragma unroll
    for (int t = 0; t < 2; t++) {
        int f  = tid + t * 256;
        int r  = f >> 3;
        int c8 = f & 7;
        kvso[t] = (uint32_t)(r * QSTR + c8 * 4) * 4;
        kvg[t]  = headoff + (size_t)r * CDIM + c8 * 8;
    }
    const uint32_t kvbase = sbase + 2 * QARR * 4;

    const int ktmax = 2 * qt + 1;

    // prefetch kv tile 0 -> buffer 0
    #pragma unroll
    for (int t = 0; t < 2; t++) {
        cpa16(kvbase + 0 * KARR * 4 + kvso[t], Kh + kvg[t]);
        cpa16(kvbase + 1 * KARR * 4 + kvso[t], Vh + kvg[t]);
    }
    cpa_commit();

    const float scale = 0.125f;
    float o[8][4];
    #pragma unroll
    for (int nt = 0; nt < 8; nt++)
        #pragma unroll
        for (int j = 0; j < 4; j++) o[nt][j] = 0.f;
    float mA = -INFINITY, mB = -INFINITY, lA = 0.f, lB = 0.f;

    const int rowAg = qt * 128 + wm + fr;
    const int rowBg = rowAg + 8;

    for (int kt = 0; kt <= ktmax; kt++) {
        cpa_wait<0>();
        __syncthreads();

        if (kt < ktmax) {
            const uint32_t bb = kvbase + ((kt + 1) & 1) * KBUF * 4;
            const size_t go = (size_t)(kt + 1) * 64 * CDIM;
            #pragma unroll
            for (int t = 0; t < 2; t++) {
                cpa16(bb + 0 * KARR * 4 + kvso[t], Kh + kvg[t] + go);
                cpa16(bb + 1 * KARR * 4 + kvso[t], Vh + kvg[t] + go);
            }
            cpa_commit();
        }

        const uint32_t cb  = kvbase + (kt & 1) * KBUF * 4;
        const uint32_t aKh = cb, aVh = cb + KARR * 4;

        // S = Q K^T (2 MMAs per fragment)
        float sacc[8][4];
        #pragma unroll
        for (int nt = 0; nt < 8; nt++)
            #pragma unroll
            for (int j = 0; j < 4; j++) sacc[nt][j] = 0.f;

        #pragma unroll
        for (int ks = 0; ks < 4; ks++) {
            const uint32_t kbb = (uint32_t)(ks * 8) * 4;
            uint32_t ah[4], al[4];
            ldm_x4(ah, aQh + qoff + kbb);
            ldm_x4(al, aQl + qoff + kbb);
            #pragma unroll
            for (int np = 0; np < 4; np++) {
                uint32_t k4h[4];
                ldm_x4(k4h, aKh + koff[np] + kbb);
                #pragma unroll
                for (int hf = 0; hf < 2; hf++) {
                    const int nt = np * 2 + hf;
                    mma16816(sacc[nt], ah, &k4h[hf * 2]);
                    mma16816(sacc[nt], al, &k4h[hf * 2]);
                }
            }
        }

        // scale + causal mask
        const bool diag = (kt >= 2 * qt);
        #pragma unroll
        for (int nt = 0; nt < 8; nt++) {
            #pragma unroll
            for (int j = 0; j < 4; j++) sacc[nt][j] *= scale;
            if (diag) {
                int col0 = kt * 64 + nt * 8 + 2 * fc;
                if (col0     > rowAg) sacc[nt][0] = -INFINITY;
                if (col0 + 1 > rowAg) sacc[nt][1] = -INFINITY;
                if (col0     > rowBg) sacc[nt][2] = -INFINITY;
                if (col0 + 1 > rowBg) sacc[nt][3] = -INFINITY;
            }
        }

        // online softmax
        float mxA = -INFINITY, mxB = -INFINITY;
        #pragma unroll
        for (int nt = 0; nt < 8; nt++) {
            mxA = fmaxf(mxA, fmaxf(sacc[nt][0], sacc[nt][1]));
            mxB = fmaxf(mxB, fmaxf(sacc[nt][2], sacc[nt][3]));
        }
        mxA = fmaxf(mxA, __shfl_xor_sync(0xffffffffu, mxA, 1));
        mxA = fmaxf(mxA, __shfl_xor_sync(0xffffffffu, mxA, 2));
        mxB = fmaxf(mxB, __shfl_xor_sync(0xffffffffu, mxB, 1));
        mxB = fmaxf(mxB, __shfl_xor_sync(0xffffffffu, mxB, 2));

        float mnA = fmaxf(mA, mxA), mnB = fmaxf(mB, mxB);
        float aA = __expf(mA - mnA), aB = __expf(mB - mnB);
        mA = mnA; mB = mnB;

        float lsA = 0.f, lsB = 0.f;
        #pragma unroll
        for (int nt = 0; nt < 8; nt++) {
            sacc[nt][0] = __expf(sacc[nt][0] - mnA);
            sacc[nt][1] = __expf(sacc[nt][1] - mnA);
            sacc[nt][2] = __expf(sacc[nt][2] - mnB);
            sacc[nt][3] = __expf(sacc[nt][3] - mnB);
            lsA += sacc[nt][0] + sacc[nt][1];
            lsB += sacc[nt][2] + sacc[nt][3];
        }
        lsA += __shfl_xor_sync(0xffffffffu, lsA, 1);
        lsA += __shfl_xor_sync(0xffffffffu, lsA, 2);
        lsB += __shfl_xor_sync(0xffffffffu, lsB, 1);
        lsB += __shfl_xor_sync(0xffffffffu, lsB, 2);
        lA = lA * aA + lsA;
        lB = lB * aB + lsB;

        #pragma unroll
        for (int nt = 0; nt < 8; nt++) {
            o[nt][0] *= aA; o[nt][1] *= aA;
            o[nt][2] *= aB; o[nt][3] *= aB;
        }

        // O += P V (P hi only -> 1 MMA)
        #pragma unroll
        for (int ks = 0; ks < 4; ks++) {
            uint32_t ph[4];
            ph[0] = cvt2h(sacc[2 * ks][0],     sacc[2 * ks][1]);
            ph[1] = cvt2h(sacc[2 * ks][2],     sacc[2 * ks][3]);
            ph[2] = cvt2h(sacc[2 * ks + 1][0], sacc[2 * ks + 1][1]);
            ph[3] = cvt2h(sacc[2 * ks + 1][2], sacc[2 * ks + 1][3]);
            const uint32_t ro = (uint32_t)(ks * 16 * QSTR) * 4;
            #pragma unroll
            for (int np = 0; np < 4; np++) {
                uint32_t v4h[4];
                ldm_x4_trans(v4h, aVh + ro + voff[np]);
                #pragma unroll
                for (int hf = 0; hf < 2; hf++) {
                    const int nt = np * 2 + hf;
                    mma16816(o[nt], ph, &v4h[hf * 2]);
                }
            }
        }
    }

    // normalize + write hi/lo fp16
    float liA = 1.0f / lA, liB = 1.0f / lB;
    #pragma unroll
    for (int nt = 0; nt < 8; nt++) {
        int col = nt * 8 + 2 * fc;
        size_t gA = headoff + (size_t)rowAg * CDIM + col;
        size_t gB = headoff + (size_t)rowBg * CDIM + col;
        uint32_t hi, lo;
        split2h(o[nt][0] * liA, o[nt][1] * liA, hi, lo);
        *(uint32_t*)&Yh[gA] = hi;
        *(uint32_t*)&Yl[gA] = lo;
        split2h(o[nt][2] * liB, o[nt][3] * liB, hi, lo);
        *(uint32_t*)&Yh[gB] = hi;
        *(uint32_t*)&Yl[gB] = lo;
    }
}

// ---------------------------------------------------------------------------
// Launch
// ---------------------------------------------------------------------------
extern "C" void kernel_launch(void* const* d_in, const int* in_sizes, int n_in,
                              void* d_out, int out_size)
{
    const float* x  = (const float*)d_in[0];
    const float* Wq = (const float*)d_in[1];
    const float* bq = (const float*)d_in[2];
    const float* Wk = (const float*)d_in[3];
    const float* bk = (const float*)d_in[4];
    const float* Wv = (const float*)d_in[5];
    const float* bv = (const float*)d_in[6];
    const float* Wo = (const float*)d_in[7];
    const float* bo = (const float*)d_in[8];
    float* out = (float*)d_out;

    __half *xh, *xl, *qh, *ql, *kh, *vh, *yh, *yl;
    __half *wqh, *wkh, *wvh, *woh;
    cudaGetSymbolAddress((void**)&xh, g_xh);
    cudaGetSymbolAddress((void**)&xl, g_xl);
    cudaGetSymbolAddress((void**)&qh, g_qh);
    cudaGetSymbolAddress((void**)&ql, g_ql);
    cudaGetSymbolAddress((void**)&kh, g_kh);
    cudaGetSymbolAddress((void**)&vh, g_vh);
    cudaGetSymbolAddress((void**)&yh, g_yh);
    cudaGetSymbolAddress((void**)&yl, g_yl);
    cudaGetSymbolAddress((void**)&wqh, g_wqh);
    cudaGetSymbolAddress((void**)&wkh, g_wkh);
    cudaGetSymbolAddress((void**)&wvh, g_wvh);
    cudaGetSymbolAddress((void**)&woh, g_woh);

    cudaFuncSetAttribute(attn_mma,
                         cudaFuncAttributeMaxDynamicSharedMemorySize, ATTN_SMEM);
    cudaFuncSetAttribute(gemm_qkv,
                         cudaFuncAttributeMaxDynamicSharedMemorySize, GEMM_SMEM);
    cudaFuncSetAttribute(gemm_o,
                         cudaFuncAttributeMaxDynamicSharedMemorySize, GEMM_SMEM);

    const int nw4 = CDIM * CDIM / 4;   // float4 per weight / x-quarter
    const int xq  = CDIM * CDIM;       // elements per x quarter

    // 1) all splits/converts in one launch
    SplitAll sa;
    sa.in[0] = Wq; sa.hi[0] = wqh; sa.lo[0] = nullptr;
    sa.in[1] = Wk; sa.hi[1] = wkh; sa.lo[1] = nullptr;
    sa.in[2] = Wv; sa.hi[2] = wvh; sa.lo[2] = nullptr;
    sa.in[3] = Wo; sa.hi[3] = woh; sa.lo[3] = nullptr;
    for (int q = 0; q < 4; q++) {
        sa.in[4 + q] = x + (size_t)q * xq;
        sa.hi[4 + q] = xh + (size_t)q * xq;
        sa.lo[4 + q] = xl + (size_t)q * xq;
    }
    dim3 sgrid(nw4 / 256, 8);
    split8_kernel<<<sgrid, 256>>>(sa, nw4);

    // 2) merged Q/K/V projection
    GemmBatch gb;
    gb.Bh[0] = wqh; gb.bias[0] = bq; gb.Ch[0] = qh; gb.Cl[0] = ql;
    gb.Bh[1] = wkh; gb.bias[1] = bk; gb.Ch[1] = kh; gb.Cl[1] = nullptr;
    gb.Bh[2] = wvh; gb.bias[2] = bv; gb.Ch[2] = vh; gb.Cl[2] = nullptr;
    dim3 qkvgrid(CDIM / 128, MROWS / 128, 3);   // (8, 32, 3)
    gemm_qkv<<<qkvgrid, 256, GEMM_SMEM>>>(gb, xh, xl);

    // 3) attention
    dim3 agrid(TSEQ / 128, BATCH * NHEAD);  // (16, 32)
    attn_mma<<<agrid, 256, ATTN_SMEM>>>(qh, ql, kh, vh, yh, yl);

    // 4) output projection
    dim3 ogrid(CDIM / 128, MROWS / 128);    // (8, 32)
    gemm_o<<<ogrid, 256, GEMM_SMEM>>>(yh, yl, woh, bo, out);
}

// round 12
// speedup vs baseline: 7.5141x; 1.2047x over previous
#include <cuda_runtime.h>
#include <cuda_fp16.h>
#include <math.h>
#include <stdint.h>

// Problem constants
#define BATCH 2
#define TSEQ  2048
#define CDIM  1024
#define NHEAD 16
#define HDIM  64
#define MROWS (BATCH * TSEQ)   // 4096

// ---------------------------------------------------------------------------
// Scratch (allocation-free: __device__ globals)
// ---------------------------------------------------------------------------
__device__ __align__(16) __half g_xh[MROWS * CDIM];
__device__ __align__(16) __half g_qh[MROWS * CDIM];
__device__ __align__(16) __half g_kh[MROWS * CDIM];
__device__ __align__(16) __half g_vh[MROWS * CDIM];
__device__ __align__(16) __half g_yh[MROWS * CDIM];
__device__ __align__(16) __half g_yl[MROWS * CDIM];
__device__ __align__(16) __half g_wqh[CDIM * CDIM];
__device__ __align__(16) __half g_wkh[CDIM * CDIM];
__device__ __align__(16) __half g_wvh[CDIM * CDIM];
__device__ __align__(16) __half g_woh[CDIM * CDIM];

// ---------------------------------------------------------------------------
// PTX helpers (baseline PTX, valid for compute_103)
// ---------------------------------------------------------------------------
__device__ __forceinline__ void mma16816(float* c, const uint32_t* a,
                                         const uint32_t* b) {
    asm volatile(
        "mma.sync.aligned.m16n8k16.row.col.f32.f16.f16.f32 "
        "{%0,%1,%2,%3}, {%4,%5,%6,%7}, {%8,%9}, {%0,%1,%2,%3};"
        : "+f"(c[0]), "+f"(c[1]), "+f"(c[2]), "+f"(c[3])
        : "r"(a[0]), "r"(a[1]), "r"(a[2]), "r"(a[3]), "r"(b[0]), "r"(b[1]));
}

__device__ __forceinline__ void ldm_x4(uint32_t* r, uint32_t saddr) {
    asm volatile(
        "ldmatrix.sync.aligned.m8n8.x4.shared.b16 {%0,%1,%2,%3}, [%4];"
        : "=r"(r[0]), "=r"(r[1]), "=r"(r[2]), "=r"(r[3]) : "r"(saddr));
}

__device__ __forceinline__ void ldm_x4_trans(uint32_t* r, uint32_t saddr) {
    asm volatile(
        "ldmatrix.sync.aligned.m8n8.x4.trans.shared.b16 {%0,%1,%2,%3}, [%4];"
        : "=r"(r[0]), "=r"(r[1]), "=r"(r[2]), "=r"(r[3]) : "r"(saddr));
}

__device__ __forceinline__ uint32_t smem_u32(const void* p) {
    uint32_t a;
    asm("{ .reg .u64 t; cvta.to.shared.u64 t, %1; cvt.u32.u64 %0, t; }"
        : "=r"(a) : "l"(p));
    return a;
}

__device__ __forceinline__ void cpa16(uint32_t s, const void* g) {
    asm volatile("cp.async.cg.shared.global [%0], [%1], 16;"
                 :: "r"(s), "l"(g));
}
__device__ __forceinline__ void cpa_commit() {
    asm volatile("cp.async.commit_group;");
}
template<int N> __device__ __forceinline__ void cpa_wait() {
    asm volatile("cp.async.wait_group %0;" :: "n"(N));
}

__device__ __forceinline__ uint32_t packh(__half a, __half b) {
    __half2 t = __halves2half2(a, b);
    return *(uint32_t*)&t;
}

__device__ __forceinline__ void split2h(float a, float b,
                                        uint32_t& hi, uint32_t& lo) {
    __half ha = __float2half_rn(a);
    __half hb = __float2half_rn(b);
    __half la = __float2half_rn(a - __half2float(ha));
    __half lb = __float2half_rn(b - __half2float(hb));
    hi = packh(ha, hb);
    lo = packh(la, lb);
}

__device__ __forceinline__ uint32_t cvt2h(float a, float b) {
    return packh(__float2half_rn(a), __float2half_rn(b));
}

// ---------------------------------------------------------------------------
// Convert kernel: 8 segments (4 weights + 4 quarters of x), fp32 -> fp16
// ---------------------------------------------------------------------------
struct CvtAll {
    const float* in[8];
    __half* out[8];
};

__global__ void __launch_bounds__(256)
cvt8_kernel(CvtAll cb, int n4)
{
    int i = blockIdx.x * blockDim.x + threadIdx.x;
    if (i >= n4) return;
    const float* in = cb.in[blockIdx.y];
    __half* out = cb.out[blockIdx.y];
    float4 v = ((const float4*)in)[i];
    ((uint32_t*)out)[2 * i]     = cvt2h(v.x, v.y);
    ((uint32_t*)out)[2 * i + 1] = cvt2h(v.z, v.w);
}

// ---------------------------------------------------------------------------
// HMMA GEMM body: C = A[M,K] @ B[N,K]^T + bias.
// ASPLIT=1: A = Ah + Al (2 MMAs). ASPLIT=0: A = Ah (1 MMA).
// CTA tile 128x128, K-chunk 64, double-buffered cp.async, ldmatrix frags,
// ONE barrier per chunk.
// OUT: 0 = fp32 C; 2 = fp16 Ch only.
// ---------------------------------------------------------------------------
#define SSTR  36                     // u32 per smem row (64 fp16 + pad)
#define GARRB (128 * SSTR * 4)       // bytes per array (18432)

template<int ASPLIT, int OUT>
__device__ __forceinline__ void
gemm_body(uint32_t* sg,
          const __half* __restrict__ Ah, const __half* __restrict__ Al,
          const __half* __restrict__ Bh,
          const float* __restrict__ bias, float* __restrict__ C,
          __half* __restrict__ Ch,
          int M, int N, int K)
{
    const uint32_t sbase = smem_u32(sg);
    const uint32_t GBUFB = (2 + ASPLIT) * GARRB;

    const int tid  = threadIdx.x;
    const int lane = tid & 31;
    const int warp = tid >> 5;
    const int wm   = (warp >> 1) * 32;
    const int wn   = (warp & 1) * 64;
    const int m0   = blockIdx.y * 128;
    const int n0   = blockIdx.x * 128;

    uint32_t s_off[4];
    size_t gA[4], gB[4];
    #pragma unroll
    for (int t = 0; t < 4; t++) {
        int f   = tid + t * 256;
        int row = f >> 3;
        int c8  = f & 7;
        s_off[t] = (uint32_t)(row * SSTR + c8 * 4) * 4;
        gA[t] = (size_t)(m0 + row) * K + c8 * 8;
        gB[t] = (size_t)(n0 + row) * K + c8 * 8;
    }

    const int arow  = (lane & 7) + ((lane >> 3) & 1) * 8;
    const int acol  = (lane >> 4) * 4;
    const int brow  = (lane & 7) + (lane >> 4) * 8;
    const int bcol4 = ((lane >> 3) & 1) * 4;

    uint32_t aoff[2], boff[4];
    #pragma unroll
    for (int mt = 0; mt < 2; mt++)
        aoff[mt] = (uint32_t)((wm + mt * 16 + arow) * SSTR + acol) * 4;
    #pragma unroll
    for (int np = 0; np < 4; np++)
        boff[np] = (uint32_t)((wn + np * 16 + brow) * SSTR + bcol4) * 4;

    const int fr = lane >> 2;
    const int fc = lane & 3;

    float acc[2][8][4];
    #pragma unroll
    for (int mt = 0; mt < 2; mt++)
        #pragma unroll
        for (int nt = 0; nt < 8; nt++)
            #pragma unroll
            for (int j = 0; j < 4; j++) acc[mt][nt][j] = 0.f;

    const int nchunks = K / 64;   // 16

    // prefetch chunk 0 -> buffer 0 (array order: Ah, Bh, [Al])
    #pragma unroll
    for (int t = 0; t < 4; t++) {
        cpa16(sbase + 0 * GARRB + s_off[t], Ah + gA[t]);
        cpa16(sbase + 1 * GARRB + s_off[t], Bh + gB[t]);
        if (ASPLIT) cpa16(sbase + 2 * GARRB + s_off[t], Al + gA[t]);
    }
    cpa_commit();

    for (int kc = 0; kc < nchunks; kc++) {
        cpa_wait<0>();
        __syncthreads();

        if (kc + 1 < nchunks) {
            const uint32_t bb = sbase + ((kc + 1) & 1) * GBUFB;
            const int ko = (kc + 1) * 64;
            #pragma unroll
            for (int t = 0; t < 4; t++) {
                cpa16(bb + 0 * GARRB + s_off[t], Ah + gA[t] + ko);
                cpa16(bb + 1 * GARRB + s_off[t], Bh + gB[t] + ko);
                if (ASPLIT) cpa16(bb + 2 * GARRB + s_off[t], Al + gA[t] + ko);
            }
            cpa_commit();
        }

        const uint32_t cb  = sbase + (kc & 1) * GBUFB;
        const uint32_t aAh = cb, aBh = cb + GARRB, aAl = cb + 2 * GARRB;

        #pragma unroll
        for (int ks = 0; ks < 4; ks++) {
            const uint32_t kbb = (uint32_t)(ks * 8) * 4;
            uint32_t afh[2][4], afl[2][4];
            #pragma unroll
            for (int mt = 0; mt < 2; mt++) {
                ldm_x4(afh[mt], aAh + aoff[mt] + kbb);
                if (ASPLIT) ldm_x4(afl[mt], aAl + aoff[mt] + kbb);
            }
            #pragma unroll
            for (int np = 0; np < 4; np++) {
                uint32_t b4h[4];
                ldm_x4(b4h, aBh + boff[np] + kbb);
                #pragma unroll
                for (int hf = 0; hf < 2; hf++) {
                    const int nt = np * 2 + hf;
                    #pragma unroll
                    for (int mt = 0; mt < 2; mt++) {
                        mma16816(acc[mt][nt], afh[mt], &b4h[hf * 2]);
                        if (ASPLIT) mma16816(acc[mt][nt], afl[mt], &b4h[hf * 2]);
                    }
                }
            }
        }
    }

    #pragma unroll
    for (int mt = 0; mt < 2; mt++) {
        #pragma unroll
        for (int nt = 0; nt < 8; nt++) {
            int row = m0 + wm + mt * 16 + fr;
            int col = n0 + wn + nt * 8 + fc * 2;
            float b0 = __ldg(&bias[col]);
            float b1 = __ldg(&bias[col + 1]);
            float c0 = acc[mt][nt][0] + b0, c1 = acc[mt][nt][1] + b1;
            float c2 = acc[mt][nt][2] + b0, c3 = acc[mt][nt][3] + b1;
            if (OUT == 2) {
                *(uint32_t*)&Ch[(size_t)row * N + col]       = cvt2h(c0, c1);
                *(uint32_t*)&Ch[(size_t)(row + 8) * N + col] = cvt2h(c2, c3);
            } else {
                *(float2*)&C[(size_t)row * N + col]       = make_float2(c0, c1);
                *(float2*)&C[(size_t)(row + 8) * N + col] = make_float2(c2, c3);
            }
        }
    }
}

#define GEMM_SMEM_QKV (2 * 2 * GARRB)   // 73728
#define GEMM_SMEM_O   (2 * 3 * GARRB)   // 110592

struct GemmBatch {
    const __half* Bh[3];
    const float* bias[3];
    __half* Ch[3];
};

// merged Q/K/V projection, A = xh only, fp16 hi output
__global__ void __launch_bounds__(256, 2)
gemm_qkv(GemmBatch gb, const __half* __restrict__ Ah)
{
    extern __shared__ uint32_t sg[];
    const int z = blockIdx.z;
    gemm_body<0, 2>(sg, Ah, nullptr, gb.Bh[z], gb.bias[z], nullptr,
                    gb.Ch[z], MROWS, CDIM, CDIM);
}

// output projection, A = yh + yl (split), fp32 output
__global__ void __launch_bounds__(256, 2)
gemm_o(const __half* __restrict__ Ah, const __half* __restrict__ Al,
       const __half* __restrict__ Bh,
       const float* __restrict__ bias, float* __restrict__ C)
{
    extern __shared__ uint32_t sg[];
    gemm_body<1, 0>(sg, Ah, Al, Bh, bias, C, nullptr, MROWS, CDIM, CDIM);
}

// ---------------------------------------------------------------------------
// HMMA flash attention (causal). All-fp16 operands, fp32 softmax/accum.
// S = qh*K (1 MMA); PV = ph*V (1 MMA). Output y split (hi+lo) for gemm_o.
// 128-row q tile/CTA, Bc=64, double-buffered cp.async KV, ldmatrix frags,
// longest-qt-first, ONE barrier per kv tile.
// ---------------------------------------------------------------------------
#define QSTR 36
#define QARR (128 * QSTR)              // 4608 u32
#define KARR (64 * QSTR)               // 2304 u32
#define KBUF (2 * KARR)                // u32 per kv buffer (kh + vh)
#define ATTN_SMEM ((QARR + 2 * KBUF) * 4)   // 55296 B

__global__ void __launch_bounds__(256, 2)
attn_mma(const __half* __restrict__ Qh,
         const __half* __restrict__ Kh, const __half* __restrict__ Vh,
         __half* __restrict__ Yh, __half* __restrict__ Yl)
{
    extern __shared__ uint32_t s32[];
    const uint32_t sbase = smem_u32(s32);
    const uint32_t aQh = sbase;

    const int qt = gridDim.x - 1 - blockIdx.x;   // longest-first
    const int bh = blockIdx.y;
    const int b  = bh >> 4;
    const int h  = bh & 15;
    const size_t headoff = (size_t)b * TSEQ * CDIM + (size_t)h * HDIM;

    const int tid  = threadIdx.x;
    const int lane = tid & 31;
    const int warp = tid >> 5;
    const int fr   = lane >> 2;
    const int fc   = lane & 3;
    const int wm   = warp * 16;

    const int arow  = (lane & 7) + ((lane >> 3) & 1) * 8;
    const int acol  = (lane >> 4) * 4;
    const int brow  = (lane & 7) + (lane >> 4) * 8;
    const int bcol4 = ((lane >> 3) & 1) * 4;
    const uint32_t qoff = (uint32_t)((wm + arow) * QSTR + acol) * 4;
    uint32_t koff[4], voff[4];
    #pragma unroll
    for (int np = 0; np < 4; np++) {
        koff[np] = (uint32_t)((np * 16 + brow) * QSTR + bcol4) * 4;
        voff[np] = (uint32_t)(arow * QSTR + (np * 2 + (lane >> 4)) * 4) * 4;
    }

    // Q tile via cp.async (with KV tile 0, one group)
    #pragma unroll
    for (int t = 0; t < 4; t++) {
        int f  = tid + t * 256;
        int r  = f >> 3;
        int c8 = f & 7;
        size_t g = headoff + (size_t)(qt * 128 + r) * CDIM + c8 * 8;
        uint32_t so = (uint32_t)(r * QSTR + c8 * 4) * 4;
        cpa16(aQh + so, Qh + g);
    }

    uint32_t kvso[2];
    size_t kvg[2];
    #pragma unroll
    for (int t = 0; t < 2; t++) {
        int f  = tid + t * 256;
        int r  = f >> 3;
        int c8 = f & 7;
        kvso[t] = (uint32_t)(r * QSTR + c8 * 4) * 4;
        kvg[t]  = headoff + (size_t)r * CDIM + c8 * 8;
    }
    const uint32_t kvbase = sbase + QARR * 4;

    const int ktmax = 2 * qt + 1;

    // prefetch kv tile 0 -> buffer 0
    #pragma unroll
    for (int t = 0; t < 2; t++) {
        cpa16(kvbase + 0 * KARR * 4 + kvso[t], Kh + kvg[t]);
        cpa16(kvbase + 1 * KARR * 4 + kvso[t], Vh + kvg[t]);
    }
    cpa_commit();

    const float scale = 0.125f;
    float o[8][4];
    #pragma unroll
    for (int nt = 0; nt < 8; nt++)
        #pragma unroll
        for (int j = 0; j < 4; j++) o[nt][j] = 0.f;
    float mA = -INFINITY, mB = -INFINITY, lA = 0.f, lB = 0.f;

    const int rowAg = qt * 128 + wm + fr;
    const int rowBg = rowAg + 8;

    for (int kt = 0; kt <= ktmax; kt++) {
        cpa_wait<0>();
        __syncthreads();

        if (kt < ktmax) {
            const uint32_t bb = kvbase + ((kt + 1) & 1) * KBUF * 4;
            const size_t go = (size_t)(kt + 1) * 64 * CDIM;
            #pragma unroll
            for (int t = 0; t < 2; t++) {
                cpa16(bb + 0 * KARR * 4 + kvso[t], Kh + kvg[t] + go);
                cpa16(bb + 1 * KARR * 4 + kvso[t], Vh + kvg[t] + go);
            }
            cpa_commit();
        }

        const uint32_t cb  = kvbase + (kt & 1) * KBUF * 4;
        const uint32_t aKh = cb, aVh = cb + KARR * 4;

        // S = Q K^T (1 MMA per fragment)
        float sacc[8][4];
        #pragma unroll
        for (int nt = 0; nt < 8; nt++)
            #pragma unroll
            for (int j = 0; j < 4; j++) sacc[nt][j] = 0.f;

        #pragma unroll
        for (int ks = 0; ks < 4; ks++) {
            const uint32_t kbb = (uint32_t)(ks * 8) * 4;
            uint32_t ah[4];
            ldm_x4(ah, aQh + qoff + kbb);
            #pragma unroll
            for (int np = 0; np < 4; np++) {
                uint32_t k4h[4];
                ldm_x4(k4h, aKh + koff[np] + kbb);
                #pragma unroll
                for (int hf = 0; hf < 2; hf++) {
                    const int nt = np * 2 + hf;
                    mma16816(sacc[nt], ah, &k4h[hf * 2]);
                }
            }
        }

        // scale + causal mask
        const bool diag = (kt >= 2 * qt);
        #pragma unroll
        for (int nt = 0; nt < 8; nt++) {
            #pragma unroll
            for (int j = 0; j < 4; j++) sacc[nt][j] *= scale;
            if (diag) {
                int col0 = kt * 64 + nt * 8 + 2 * fc;
                if (col0     > rowAg) sacc[nt][0] = -INFINITY;
                if (col0 + 1 > rowAg) sacc[nt][1] = -INFINITY;
                if (col0     > rowBg) sacc[nt][2] = -INFINITY;
                if (col0 + 1 > rowBg) sacc[nt][3] = -INFINITY;
            }
        }

        // online softmax
        float mxA = -INFINITY, mxB = -INFINITY;
        #pragma unroll
        for (int nt = 0; nt < 8; nt++) {
            mxA = fmaxf(mxA, fmaxf(sacc[nt][0], sacc[nt][1]));
            mxB = fmaxf(mxB, fmaxf(sacc[nt][2], sacc[nt][3]));
        }
        mxA = fmaxf(mxA, __shfl_xor_sync(0xffffffffu, mxA, 1));
        mxA = fmaxf(mxA, __shfl_xor_sync(0xffffffffu, mxA, 2));
        mxB = fmaxf(mxB, __shfl_xor_sync(0xffffffffu, mxB, 1));
        mxB = fmaxf(mxB, __shfl_xor_sync(0xffffffffu, mxB, 2));

        float mnA = fmaxf(mA, mxA), mnB = fmaxf(mB, mxB);
        float aA = __expf(mA - mnA), aB = __expf(mB - mnB);
        mA = mnA; mB = mnB;

        float lsA = 0.f, lsB = 0.f;
        #pragma unroll
        for (int nt = 0; nt < 8; nt++) {
            sacc[nt][0] = __expf(sacc[nt][0] - mnA);
            sacc[nt][1] = __expf(sacc[nt][1] - mnA);
            sacc[nt][2] = __expf(sacc[nt][2] - mnB);
            sacc[nt][3] = __expf(sacc[nt][3] - mnB);
            lsA += sacc[nt][0] + sacc[nt][1];
            lsB += sacc[nt][2] + sacc[nt][3];
        }
        lsA += __shfl_xor_sync(0xffffffffu, lsA, 1);
        lsA += __shfl_xor_sync(0xffffffffu, lsA, 2);
        lsB += __shfl_xor_sync(0xffffffffu, lsB, 1);
        lsB += __shfl_xor_sync(0xffffffffu, lsB, 2);
        lA = lA * aA + lsA;
        lB = lB * aB + lsB;

        #pragma unroll
        for (int nt = 0; nt < 8; nt++) {
            o[nt][0] *= aA; o[nt][1] *= aA;
            o[nt][2] *= aB; o[nt][3] *= aB;
        }

        // O += P V (1 MMA per fragment)
        #pragma unroll
        for (int ks = 0; ks < 4; ks++) {
            uint32_t ph[4];
            ph[0] = cvt2h(sacc[2 * ks][0],     sacc[2 * ks][1]);
            ph[1] = cvt2h(sacc[2 * ks][2],     sacc[2 * ks][3]);
            ph[2] = cvt2h(sacc[2 * ks + 1][0], sacc[2 * ks + 1][1]);
            ph[3] = cvt2h(sacc[2 * ks + 1][2], sacc[2 * ks + 1][3]);
            const uint32_t ro = (uint32_t)(ks * 16 * QSTR) * 4;
            #pragma unroll
            for (int np = 0; np < 4; np++) {
                uint32_t v4h[4];
                ldm_x4_trans(v4h, aVh + ro + voff[np]);
                #pragma unroll
                for (int hf = 0; hf < 2; hf++) {
                    const int nt = np * 2 + hf;
                    mma16816(o[nt], ph, &v4h[hf * 2]);
                }
            }
        }
    }

    // normalize + write hi/lo fp16
    float liA = 1.0f / lA, liB = 1.0f / lB;
    #pragma unroll
    for (int nt = 0; nt < 8; nt++) {
        int col = nt * 8 + 2 * fc;
        size_t gA = headoff + (size_t)rowAg * CDIM + col;
        size_t gB = headoff + (size_t)rowBg * CDIM + col;
        uint32_t hi, lo;
        split2h(o[nt][0] * liA, o[nt][1] * liA, hi, lo);
        *(uint32_t*)&Yh[gA] = hi;
        *(uint32_t*)&Yl[gA] = lo;
        split2h(o[nt][2] * liB, o[nt][3] * liB, hi, lo);
        *(uint32_t*)&Yh[gB] = hi;
        *(uint32_t*)&Yl[gB] = lo;
    }
}

// ---------------------------------------------------------------------------
// Launch
// ---------------------------------------------------------------------------
extern "C" void kernel_launch(void* const* d_in, const int* in_sizes, int n_in,
                              void* d_out, int out_size)
{
    const float* x  = (const float*)d_in[0];
    const float* Wq = (const float*)d_in[1];
    const float* bq = (const float*)d_in[2];
    const float* Wk = (const float*)d_in[3];
    const float* bk = (const float*)d_in[4];
    const float* Wv = (const float*)d_in[5];
    const float* bv = (const float*)d_in[6];
    const float* Wo = (const float*)d_in[7];
    const float* bo = (const float*)d_in[8];
    float* out = (float*)d_out;

    __half *xh, *qh, *kh, *vh, *yh, *yl;
    __half *wqh, *wkh, *wvh, *woh;
    cudaGetSymbolAddress((void**)&xh, g_xh);
    cudaGetSymbolAddress((void**)&qh, g_qh);
    cudaGetSymbolAddress((void**)&kh, g_kh);
    cudaGetSymbolAddress((void**)&vh, g_vh);
    cudaGetSymbolAddress((void**)&yh, g_yh);
    cudaGetSymbolAddress((void**)&yl, g_yl);
    cudaGetSymbolAddress((void**)&wqh, g_wqh);
    cudaGetSymbolAddress((void**)&wkh, g_wkh);
    cudaGetSymbolAddress((void**)&wvh, g_wvh);
    cudaGetSymbolAddress((void**)&woh, g_woh);

    cudaFuncSetAttribute(attn_mma,
                         cudaFuncAttributeMaxDynamicSharedMemorySize, ATTN_SMEM);
    cudaFuncSetAttribute(gemm_qkv,
                         cudaFuncAttributeMaxDynamicSharedMemorySize, GEMM_SMEM_QKV);
    cudaFuncSetAttribute(gemm_o,
                         cudaFuncAttributeMaxDynamicSharedMemorySize, GEMM_SMEM_O);

    const int nw4 = CDIM * CDIM / 4;   // float4 per weight / x-quarter
    const int xq  = CDIM * CDIM;       // elements per x quarter

    // 1) all fp32->fp16 converts in one launch
    CvtAll ca;
    ca.in[0] = Wq; ca.out[0] = wqh;
    ca.in[1] = Wk; ca.out[1] = wkh;
    ca.in[2] = Wv; ca.out[2] = wvh;
    ca.in[3] = Wo; ca.out[3] = woh;
    for (int q = 0; q < 4; q++) {
        ca.in[4 + q]  = x + (size_t)q * xq;
        ca.out[4 + q] = xh + (size_t)q * xq;
    }
    dim3 cgrid(nw4 / 256, 8);
    cvt8_kernel<<<cgrid, 256>>>(ca, nw4);

    // 2) merged Q/K/V projection (A = xh only)
    GemmBatch gb;
    gb.Bh[0] = wqh; gb.bias[0] = bq; gb.Ch[0] = qh;
    gb.Bh[1] = wkh; gb.bias[1] = bk; gb.Ch[1] = kh;
    gb.Bh[2] = wvh; gb.bias[2] = bv; gb.Ch[2] = vh;
    dim3 qkvgrid(CDIM / 128, MROWS / 128, 3);   // (8, 32, 3)
    gemm_qkv<<<qkvgrid, 256, GEMM_SMEM_QKV>>>(gb, xh);

    // 3) attention
    dim3 agrid(TSEQ / 128, BATCH * NHEAD);  // (16, 32)
    attn_mma<<<agrid, 256, ATTN_SMEM>>>(qh, kh, vh, yh, yl);

    // 4) output projection (A = yh + yl split)
    dim3 ogrid(CDIM / 128, MROWS / 128);    // (8, 32)
    gemm_o<<<ogrid, 256, GEMM_SMEM_O>>>(yh, yl, woh, bo, out);
}

// round 13
// speedup vs baseline: 8.1832x; 1.0890x over previous
#include <cuda_runtime.h>
#include <cuda_fp16.h>
#include <math.h>
#include <stdint.h>

// Problem constants
#define BATCH 2
#define TSEQ  2048
#define CDIM  1024
#define NHEAD 16
#define HDIM  64
#define MROWS (BATCH * TSEQ)   // 4096

// ---------------------------------------------------------------------------
// Scratch (allocation-free: __device__ globals)
// ---------------------------------------------------------------------------
__device__ __align__(16) __half g_xh[MROWS * CDIM];
__device__ __align__(16) __half g_qh[MROWS * CDIM];
__device__ __align__(16) __half g_kh[MROWS * CDIM];
__device__ __align__(16) __half g_vh[MROWS * CDIM];
__device__ __align__(16) __half g_yh[MROWS * CDIM];
__device__ __align__(16) __half g_wqh[CDIM * CDIM];
__device__ __align__(16) __half g_wkh[CDIM * CDIM];
__device__ __align__(16) __half g_wvh[CDIM * CDIM];
__device__ __align__(16) __half g_woh[CDIM * CDIM];

// ---------------------------------------------------------------------------
// PTX helpers (baseline PTX, valid for compute_103)
// ---------------------------------------------------------------------------
__device__ __forceinline__ void mma16816(float* c, const uint32_t* a,
                                         const uint32_t* b) {
    asm volatile(
        "mma.sync.aligned.m16n8k16.row.col.f32.f16.f16.f32 "
        "{%0,%1,%2,%3}, {%4,%5,%6,%7}, {%8,%9}, {%0,%1,%2,%3};"
        : "+f"(c[0]), "+f"(c[1]), "+f"(c[2]), "+f"(c[3])
        : "r"(a[0]), "r"(a[1]), "r"(a[2]), "r"(a[3]), "r"(b[0]), "r"(b[1]));
}

__device__ __forceinline__ void ldm_x4(uint32_t* r, uint32_t saddr) {
    asm volatile(
        "ldmatrix.sync.aligned.m8n8.x4.shared.b16 {%0,%1,%2,%3}, [%4];"
        : "=r"(r[0]), "=r"(r[1]), "=r"(r[2]), "=r"(r[3]) : "r"(saddr));
}

__device__ __forceinline__ void ldm_x4_trans(uint32_t* r, uint32_t saddr) {
    asm volatile(
        "ldmatrix.sync.aligned.m8n8.x4.trans.shared.b16 {%0,%1,%2,%3}, [%4];"
        : "=r"(r[0]), "=r"(r[1]), "=r"(r[2]), "=r"(r[3]) : "r"(saddr));
}

__device__ __forceinline__ uint32_t smem_u32(const void* p) {
    uint32_t a;
    asm("{ .reg .u64 t; cvta.to.shared.u64 t, %1; cvt.u32.u64 %0, t; }"
        : "=r"(a) : "l"(p));
    return a;
}

__device__ __forceinline__ void cpa16(uint32_t s, const void* g) {
    asm volatile("cp.async.cg.shared.global [%0], [%1], 16;"
                 :: "r"(s), "l"(g));
}
__device__ __forceinline__ void cpa_commit() {
    asm volatile("cp.async.commit_group;");
}
template<int N> __device__ __forceinline__ void cpa_wait() {
    asm volatile("cp.async.wait_group %0;" :: "n"(N));
}

__device__ __forceinline__ uint32_t packh(__half a, __half b) {
    __half2 t = __halves2half2(a, b);
    return *(uint32_t*)&t;
}

__device__ __forceinline__ uint32_t cvt2h(float a, float b) {
    return packh(__float2half_rn(a), __float2half_rn(b));
}

// ---------------------------------------------------------------------------
// Convert kernel: 8 segments (4 weights + 4 quarters of x), fp32 -> fp16
// ---------------------------------------------------------------------------
struct CvtAll {
    const float* in[8];
    __half* out[8];
};

__global__ void __launch_bounds__(256)
cvt8_kernel(CvtAll cb, int n4)
{
    int i = blockIdx.x * blockDim.x + threadIdx.x;
    if (i >= n4) return;
    const float* in = cb.in[blockIdx.y];
    __half* out = cb.out[blockIdx.y];
    float4 v = ((const float4*)in)[i];
    ((uint32_t*)out)[2 * i]     = cvt2h(v.x, v.y);
    ((uint32_t*)out)[2 * i + 1] = cvt2h(v.z, v.w);
}

// ---------------------------------------------------------------------------
// HMMA GEMM body: C = A[M,K] @ B[N,K]^T + bias. A, B fp16 (1 MMA per frag).
// CTA tile 128x128, K-chunk 64, double-buffered cp.async, ldmatrix frags,
// ONE barrier per chunk.
// OUT: 0 = fp32 C; 2 = fp16 Ch.
// ---------------------------------------------------------------------------
#define SSTR  36                     // u32 per smem row (64 fp16 + pad)
#define GARRB (128 * SSTR * 4)       // bytes per array (18432)
#define GBUFB (2 * GARRB)            // bytes per buffer
#define GEMM_SMEM (2 * GBUFB)        // 73728

template<int OUT>
__device__ __forceinline__ void
gemm_body(uint32_t* sg,
          const __half* __restrict__ Ah, const __half* __restrict__ Bh,
          const float* __restrict__ bias, float* __restrict__ C,
          __half* __restrict__ Ch,
          int M, int N, int K)
{
    const uint32_t sbase = smem_u32(sg);

    const int tid  = threadIdx.x;
    const int lane = tid & 31;
    const int warp = tid >> 5;
    const int wm   = (warp >> 1) * 32;
    const int wn   = (warp & 1) * 64;
    const int m0   = blockIdx.y * 128;
    const int n0   = blockIdx.x * 128;

    uint32_t s_off[4];
    size_t gA[4], gB[4];
    #pragma unroll
    for (int t = 0; t < 4; t++) {
        int f   = tid + t * 256;
        int row = f >> 3;
        int c8  = f & 7;
        s_off[t] = (uint32_t)(row * SSTR + c8 * 4) * 4;
        gA[t] = (size_t)(m0 + row) * K + c8 * 8;
        gB[t] = (size_t)(n0 + row) * K + c8 * 8;
    }

    const int arow  = (lane & 7) + ((lane >> 3) & 1) * 8;
    const int acol  = (lane >> 4) * 4;
    const int brow  = (lane & 7) + (lane >> 4) * 8;
    const int bcol4 = ((lane >> 3) & 1) * 4;

    uint32_t aoff[2], boff[4];
    #pragma unroll
    for (int mt = 0; mt < 2; mt++)
        aoff[mt] = (uint32_t)((wm + mt * 16 + arow) * SSTR + acol) * 4;
    #pragma unroll
    for (int np = 0; np < 4; np++)
        boff[np] = (uint32_t)((wn + np * 16 + brow) * SSTR + bcol4) * 4;

    const int fr = lane >> 2;
    const int fc = lane & 3;

    float acc[2][8][4];
    #pragma unroll
    for (int mt = 0; mt < 2; mt++)
        #pragma unroll
        for (int nt = 0; nt < 8; nt++)
            #pragma unroll
            for (int j = 0; j < 4; j++) acc[mt][nt][j] = 0.f;

    const int nchunks = K / 64;   // 16

    // prefetch chunk 0 -> buffer 0 (arrays: Ah, Bh)
    #pragma unroll
    for (int t = 0; t < 4; t++) {
        cpa16(sbase + 0 * GARRB + s_off[t], Ah + gA[t]);
        cpa16(sbase + 1 * GARRB + s_off[t], Bh + gB[t]);
    }
    cpa_commit();

    for (int kc = 0; kc < nchunks; kc++) {
        cpa_wait<0>();
        __syncthreads();

        if (kc + 1 < nchunks) {
            const uint32_t bb = sbase + ((kc + 1) & 1) * GBUFB;
            const int ko = (kc + 1) * 64;
            #pragma unroll
            for (int t = 0; t < 4; t++) {
                cpa16(bb + 0 * GARRB + s_off[t], Ah + gA[t] + ko);
                cpa16(bb + 1 * GARRB + s_off[t], Bh + gB[t] + ko);
            }
            cpa_commit();
        }

        const uint32_t cb  = sbase + (kc & 1) * GBUFB;
        const uint32_t aAh = cb, aBh = cb + GARRB;

        #pragma unroll
        for (int ks = 0; ks < 4; ks++) {
            const uint32_t kbb = (uint32_t)(ks * 8) * 4;
            uint32_t afh[2][4];
            #pragma unroll
            for (int mt = 0; mt < 2; mt++)
                ldm_x4(afh[mt], aAh + aoff[mt] + kbb);
            #pragma unroll
            for (int np = 0; np < 4; np++) {
                uint32_t b4h[4];
                ldm_x4(b4h, aBh + boff[np] + kbb);
                #pragma unroll
                for (int hf = 0; hf < 2; hf++) {
                    const int nt = np * 2 + hf;
                    #pragma unroll
                    for (int mt = 0; mt < 2; mt++)
                        mma16816(acc[mt][nt], afh[mt], &b4h[hf * 2]);
                }
            }
        }
    }

    #pragma unroll
    for (int mt = 0; mt < 2; mt++) {
        #pragma unroll
        for (int nt = 0; nt < 8; nt++) {
            int row = m0 + wm + mt * 16 + fr;
            int col = n0 + wn + nt * 8 + fc * 2;
            float b0 = __ldg(&bias[col]);
            float b1 = __ldg(&bias[col + 1]);
            float c0 = acc[mt][nt][0] + b0, c1 = acc[mt][nt][1] + b1;
            float c2 = acc[mt][nt][2] + b0, c3 = acc[mt][nt][3] + b1;
            if (OUT == 2) {
                *(uint32_t*)&Ch[(size_t)row * N + col]       = cvt2h(c0, c1);
                *(uint32_t*)&Ch[(size_t)(row + 8) * N + col] = cvt2h(c2, c3);
            } else {
                *(float2*)&C[(size_t)row * N + col]       = make_float2(c0, c1);
                *(float2*)&C[(size_t)(row + 8) * N + col] = make_float2(c2, c3);
            }
        }
    }
}

struct GemmBatch {
    const __half* Bh[3];
    const float* bias[3];
    __half* Ch[3];
};

// merged Q/K/V projection, fp16 output
__global__ void __launch_bounds__(256, 2)
gemm_qkv(GemmBatch gb, const __half* __restrict__ Ah)
{
    extern __shared__ uint32_t sg[];
    const int z = blockIdx.z;
    gemm_body<2>(sg, Ah, gb.Bh[z], gb.bias[z], nullptr, gb.Ch[z],
                 MROWS, CDIM, CDIM);
}

// output projection, fp32 output
__global__ void __launch_bounds__(256, 2)
gemm_o(const __half* __restrict__ Ah, const __half* __restrict__ Bh,
       const float* __restrict__ bias, float* __restrict__ C)
{
    extern __shared__ uint32_t sg[];
    gemm_body<0>(sg, Ah, Bh, bias, C, nullptr, MROWS, CDIM, CDIM);
}

// ---------------------------------------------------------------------------
// HMMA flash attention (causal). All-fp16 operands, fp32 softmax/accum.
// S = qh*K (1 MMA); PV = ph*V (1 MMA). Output yh fp16.
// 128-row q tile/CTA, Bc=64, double-buffered cp.async KV, ldmatrix frags,
// longest-qt-first, ONE barrier per kv tile.
// ---------------------------------------------------------------------------
#define QSTR 36
#define QARR (128 * QSTR)              // 4608 u32
#define KARR (64 * QSTR)               // 2304 u32
#define KBUF (2 * KARR)                // u32 per kv buffer (kh + vh)
#define ATTN_SMEM ((QARR + 2 * KBUF) * 4)   // 55296 B

__global__ void __launch_bounds__(256, 2)
attn_mma(const __half* __restrict__ Qh,
         const __half* __restrict__ Kh, const __half* __restrict__ Vh,
         __half* __restrict__ Yh)
{
    extern __shared__ uint32_t s32[];
    const uint32_t sbase = smem_u32(s32);
    const uint32_t aQh = sbase;

    const int qt = gridDim.x - 1 - blockIdx.x;   // longest-first
    const int bh = blockIdx.y;
    const int b  = bh >> 4;
    const int h  = bh & 15;
    const size_t headoff = (size_t)b * TSEQ * CDIM + (size_t)h * HDIM;

    const int tid  = threadIdx.x;
    const int lane = tid & 31;
    const int warp = tid >> 5;
    const int fr   = lane >> 2;
    const int fc   = lane & 3;
    const int wm   = warp * 16;

    const int arow  = (lane & 7) + ((lane >> 3) & 1) * 8;
    const int acol  = (lane >> 4) * 4;
    const int brow  = (lane & 7) + (lane >> 4) * 8;
    const int bcol4 = ((lane >> 3) & 1) * 4;
    const uint32_t qoff = (uint32_t)((wm + arow) * QSTR + acol) * 4;
    uint32_t koff[4], voff[4];
    #pragma unroll
    for (int np = 0; np < 4; np++) {
        koff[np] = (uint32_t)((np * 16 + brow) * QSTR + bcol4) * 4;
        voff[np] = (uint32_t)(arow * QSTR + (np * 2 + (lane >> 4)) * 4) * 4;
    }

    // Q tile via cp.async (with KV tile 0, one group)
    #pragma unroll
    for (int t = 0; t < 4; t++) {
        int f  = tid + t * 256;
        int r  = f >> 3;
        int c8 = f & 7;
        size_t g = headoff + (size_t)(qt * 128 + r) * CDIM + c8 * 8;
        uint32_t so = (uint32_t)(r * QSTR + c8 * 4) * 4;
        cpa16(aQh + so, Qh + g);
    }

    uint32_t kvso[2];
    size_t kvg[2];
    #pragma unroll
    for (int t = 0; t < 2; t++) {
        int f  = tid + t * 256;
        int r  = f >> 3;
        int c8 = f & 7;
        kvso[t] = (uint32_t)(r * QSTR + c8 * 4) * 4;
        kvg[t]  = headoff + (size_t)r * CDIM + c8 * 8;
    }
    const uint32_t kvbase = sbase + QARR * 4;

    const int ktmax = 2 * qt + 1;

    // prefetch kv tile 0 -> buffer 0
    #pragma unroll
    for (int t = 0; t < 2; t++) {
        cpa16(kvbase + 0 * KARR * 4 + kvso[t], Kh + kvg[t]);
        cpa16(kvbase + 1 * KARR * 4 + kvso[t], Vh + kvg[t]);
    }
    cpa_commit();

    const float scale = 0.125f;
    float o[8][4];
    #pragma unroll
    for (int nt = 0; nt < 8; nt++)
        #pragma unroll
        for (int j = 0; j < 4; j++) o[nt][j] = 0.f;
    float mA = -INFINITY, mB = -INFINITY, lA = 0.f, lB = 0.f;

    const int rowAg = qt * 128 + wm + fr;
    const int rowBg = rowAg + 8;

    for (int kt = 0; kt <= ktmax; kt++) {
        cpa_wait<0>();
        __syncthreads();

        if (kt < ktmax) {
            const uint32_t bb = kvbase + ((kt + 1) & 1) * KBUF * 4;
            const size_t go = (size_t)(kt + 1) * 64 * CDIM;
            #pragma unroll
            for (int t = 0; t < 2; t++) {
                cpa16(bb + 0 * KARR * 4 + kvso[t], Kh + kvg[t] + go);
                cpa16(bb + 1 * KARR * 4 + kvso[t], Vh + kvg[t] + go);
            }
            cpa_commit();
        }

        const uint32_t cb  = kvbase + (kt & 1) * KBUF * 4;
        const uint32_t aKh = cb, aVh = cb + KARR * 4;

        // S = Q K^T (1 MMA per fragment)
        float sacc[8][4];
        #pragma unroll
        for (int nt = 0; nt < 8; nt++)
            #pragma unroll
            for (int j = 0; j < 4; j++) sacc[nt][j] = 0.f;

        #pragma unroll
        for (int ks = 0; ks < 4; ks++) {
            const uint32_t kbb = (uint32_t)(ks * 8) * 4;
            uint32_t ah[4];
            ldm_x4(ah, aQh + qoff + kbb);
            #pragma unroll
            for (int np = 0; np < 4; np++) {
                uint32_t k4h[4];
                ldm_x4(k4h, aKh + koff[np] + kbb);
                #pragma unroll
                for (int hf = 0; hf < 2; hf++) {
                    const int nt = np * 2 + hf;
                    mma16816(sacc[nt], ah, &k4h[hf * 2]);
                }
            }
        }

        // scale + causal mask
        const bool diag = (kt >= 2 * qt);
        #pragma unroll
        for (int nt = 0; nt < 8; nt++) {
            #pragma unroll
            for (int j = 0; j < 4; j++) sacc[nt][j] *= scale;
            if (diag) {
                int col0 = kt * 64 + nt * 8 + 2 * fc;
                if (col0     > rowAg) sacc[nt][0] = -INFINITY;
                if (col0 + 1 > rowAg) sacc[nt][1] = -INFINITY;
                if (col0     > rowBg) sacc[nt][2] = -INFINITY;
                if (col0 + 1 > rowBg) sacc[nt][3] = -INFINITY;
            }
        }

        // online softmax
        float mxA = -INFINITY, mxB = -INFINITY;
        #pragma unroll
        for (int nt = 0; nt < 8; nt++) {
            mxA = fmaxf(mxA, fmaxf(sacc[nt][0], sacc[nt][1]));
            mxB = fmaxf(mxB, fmaxf(sacc[nt][2], sacc[nt][3]));
        }
        mxA = fmaxf(mxA, __shfl_xor_sync(0xffffffffu, mxA, 1));
        mxA = fmaxf(mxA, __shfl_xor_sync(0xffffffffu, mxA, 2));
        mxB = fmaxf(mxB, __shfl_xor_sync(0xffffffffu, mxB, 1));
        mxB = fmaxf(mxB, __shfl_xor_sync(0xffffffffu, mxB, 2));

        float mnA = fmaxf(mA, mxA), mnB = fmaxf(mB, mxB);
        float aA = __expf(mA - mnA), aB = __expf(mB - mnB);
        mA = mnA; mB = mnB;

        float lsA = 0.f, lsB = 0.f;
        #pragma unroll
        for (int nt = 0; nt < 8; nt++) {
            sacc[nt][0] = __expf(sacc[nt][0] - mnA);
            sacc[nt][1] = __expf(sacc[nt][1] - mnA);
            sacc[nt][2] = __expf(sacc[nt][2] - mnB);
            sacc[nt][3] = __expf(sacc[nt][3] - mnB);
            lsA += sacc[nt][0] + sacc[nt][1];
            lsB += sacc[nt][2] + sacc[nt][3];
        }
        lsA += __shfl_xor_sync(0xffffffffu, lsA, 1);
        lsA += __shfl_xor_sync(0xffffffffu, lsA, 2);
        lsB += __shfl_xor_sync(0xffffffffu, lsB, 1);
        lsB += __shfl_xor_sync(0xffffffffu, lsB, 2);
        lA = lA * aA + lsA;
        lB = lB * aB + lsB;

        #pragma unroll
        for (int nt = 0; nt < 8; nt++) {
            o[nt][0] *= aA; o[nt][1] *= aA;
            o[nt][2] *= aB; o[nt][3] *= aB;
        }

        // O += P V (1 MMA per fragment)
        #pragma unroll
        for (int ks = 0; ks < 4; ks++) {
            uint32_t ph[4];
            ph[0] = cvt2h(sacc[2 * ks][0],     sacc[2 * ks][1]);
            ph[1] = cvt2h(sacc[2 * ks][2],     sacc[2 * ks][3]);
            ph[2] = cvt2h(sacc[2 * ks + 1][0], sacc[2 * ks + 1][1]);
            ph[3] = cvt2h(sacc[2 * ks + 1][2], sacc[2 * ks + 1][3]);
            const uint32_t ro = (uint32_t)(ks * 16 * QSTR) * 4;
            #pragma unroll
            for (int np = 0; np < 4; np++) {
                uint32_t v4h[4];
                ldm_x4_trans(v4h, aVh + ro + voff[np]);
                #pragma unroll
                for (int hf = 0; hf < 2; hf++) {
                    const int nt = np * 2 + hf;
                    mma16816(o[nt], ph, &v4h[hf * 2]);
                }
            }
        }
    }

    // normalize + write yh fp16
    float liA = 1.0f / lA, liB = 1.0f / lB;
    #pragma unroll
    for (int nt = 0; nt < 8; nt++) {
        int col = nt * 8 + 2 * fc;
        size_t gA = headoff + (size_t)rowAg * CDIM + col;
        size_t gB = headoff + (size_t)rowBg * CDIM + col;
        *(uint32_t*)&Yh[gA] = cvt2h(o[nt][0] * liA, o[nt][1] * liA);
        *(uint32_t*)&Yh[gB] = cvt2h(o[nt][2] * liB, o[nt][3] * liB);
    }
}

// ---------------------------------------------------------------------------
// Launch
// ---------------------------------------------------------------------------
extern "C" void kernel_launch(void* const* d_in, const int* in_sizes, int n_in,
                              void* d_out, int out_size)
{
    const float* x  = (const float*)d_in[0];
    const float* Wq = (const float*)d_in[1];
    const float* bq = (const float*)d_in[2];
    const float* Wk = (const float*)d_in[3];
    const float* bk = (const float*)d_in[4];
    const float* Wv = (const float*)d_in[5];
    const float* bv = (const float*)d_in[6];
    const float* Wo = (const float*)d_in[7];
    const float* bo = (const float*)d_in[8];
    float* out = (float*)d_out;

    __half *xh, *qh, *kh, *vh, *yh;
    __half *wqh, *wkh, *wvh, *woh;
    cudaGetSymbolAddress((void**)&xh, g_xh);
    cudaGetSymbolAddress((void**)&qh, g_qh);
    cudaGetSymbolAddress((void**)&kh, g_kh);
    cudaGetSymbolAddress((void**)&vh, g_vh);
    cudaGetSymbolAddress((void**)&yh, g_yh);
    cudaGetSymbolAddress((void**)&wqh, g_wqh);
    cudaGetSymbolAddress((void**)&wkh, g_wkh);
    cudaGetSymbolAddress((void**)&wvh, g_wvh);
    cudaGetSymbolAddress((void**)&woh, g_woh);

    cudaFuncSetAttribute(attn_mma,
                         cudaFuncAttributeMaxDynamicSharedMemorySize, ATTN_SMEM);
    cudaFuncSetAttribute(gemm_qkv,
                         cudaFuncAttributeMaxDynamicSharedMemorySize, GEMM_SMEM);
    cudaFuncSetAttribute(gemm_o,
                         cudaFuncAttributeMaxDynamicSharedMemorySize, GEMM_SMEM);

    const int nw4 = CDIM * CDIM / 4;   // float4 per weight / x-quarter
    const int xq  = CDIM * CDIM;       // elements per x quarter

    // 1) all fp32->fp16 converts in one launch
    CvtAll ca;
    ca.in[0] = Wq; ca.out[0] = wqh;
    ca.in[1] = Wk; ca.out[1] = wkh;
    ca.in[2] = Wv; ca.out[2] = wvh;
    ca.in[3] = Wo; ca.out[3] = woh;
    for (int q = 0; q < 4; q++) {
        ca.in[4 + q]  = x + (size_t)q * xq;
        ca.out[4 + q] = xh + (size_t)q * xq;
    }
    dim3 cgrid(nw4 / 256, 8);
    cvt8_kernel<<<cgrid, 256>>>(ca, nw4);

    // 2) merged Q/K/V projection
    GemmBatch gb;
    gb.Bh[0] = wqh; gb.bias[0] = bq; gb.Ch[0] = qh;
    gb.Bh[1] = wkh; gb.bias[1] = bk; gb.Ch[1] = kh;
    gb.Bh[2] = wvh; gb.bias[2] = bv; gb.Ch[2] = vh;
    dim3 qkvgrid(CDIM / 128, MROWS / 128, 3);   // (8, 32, 3)
    gemm_qkv<<<qkvgrid, 256, GEMM_SMEM>>>(gb, xh);

    // 3) attention
    dim3 agrid(TSEQ / 128, BATCH * NHEAD);  // (16, 32)
    attn_mma<<<agrid, 256, ATTN_SMEM>>>(qh, kh, vh, yh);

    // 4) output projection
    dim3 ogrid(CDIM / 128, MROWS / 128);    // (8, 32)
    gemm_o<<<ogrid, 256, GEMM_SMEM>>>(yh, woh, bo, out);
}

// round 14
// speedup vs baseline: 8.5981x; 1.0507x over previous
#include <cuda_runtime.h>
#include <cuda_fp16.h>
#include <math.h>
#include <stdint.h>

// Problem constants
#define BATCH 2
#define TSEQ  2048
#define CDIM  1024
#define NHEAD 16
#define HDIM  64
#define MROWS (BATCH * TSEQ)   // 4096

// ---------------------------------------------------------------------------
// Scratch (allocation-free: __device__ globals)
// ---------------------------------------------------------------------------
__device__ __align__(16) __half g_xh[MROWS * CDIM];
__device__ __align__(16) __half g_qh[MROWS * CDIM];
__device__ __align__(16) __half g_kh[MROWS * CDIM];
__device__ __align__(16) __half g_vh[MROWS * CDIM];
__device__ __align__(16) __half g_yh[MROWS * CDIM];
__device__ __align__(16) __half g_wqh[CDIM * CDIM];
__device__ __align__(16) __half g_wkh[CDIM * CDIM];
__device__ __align__(16) __half g_wvh[CDIM * CDIM];
__device__ __align__(16) __half g_woh[CDIM * CDIM];

// ---------------------------------------------------------------------------
// PTX helpers (baseline PTX, valid for compute_103)
// ---------------------------------------------------------------------------
__device__ __forceinline__ void mma16816(float* c, const uint32_t* a,
                                         const uint32_t* b) {
    asm volatile(
        "mma.sync.aligned.m16n8k16.row.col.f32.f16.f16.f32 "
        "{%0,%1,%2,%3}, {%4,%5,%6,%7}, {%8,%9}, {%0,%1,%2,%3};"
        : "+f"(c[0]), "+f"(c[1]), "+f"(c[2]), "+f"(c[3])
        : "r"(a[0]), "r"(a[1]), "r"(a[2]), "r"(a[3]), "r"(b[0]), "r"(b[1]));
}

__device__ __forceinline__ void ldm_x4(uint32_t* r, uint32_t saddr) {
    asm volatile(
        "ldmatrix.sync.aligned.m8n8.x4.shared.b16 {%0,%1,%2,%3}, [%4];"
        : "=r"(r[0]), "=r"(r[1]), "=r"(r[2]), "=r"(r[3]) : "r"(saddr));
}

__device__ __forceinline__ void ldm_x4_trans(uint32_t* r, uint32_t saddr) {
    asm volatile(
        "ldmatrix.sync.aligned.m8n8.x4.trans.shared.b16 {%0,%1,%2,%3}, [%4];"
        : "=r"(r[0]), "=r"(r[1]), "=r"(r[2]), "=r"(r[3]) : "r"(saddr));
}

__device__ __forceinline__ uint32_t smem_u32(const void* p) {
    uint32_t a;
    asm("{ .reg .u64 t; cvta.to.shared.u64 t, %1; cvt.u32.u64 %0, t; }"
        : "=r"(a) : "l"(p));
    return a;
}

__device__ __forceinline__ void cpa16(uint32_t s, const void* g) {
    asm volatile("cp.async.cg.shared.global [%0], [%1], 16;"
                 :: "r"(s), "l"(g));
}
__device__ __forceinline__ void cpa_commit() {
    asm volatile("cp.async.commit_group;");
}
template<int N> __device__ __forceinline__ void cpa_wait() {
    asm volatile("cp.async.wait_group %0;" :: "n"(N));
}

__device__ __forceinline__ uint32_t packh(__half a, __half b) {
    __half2 t = __halves2half2(a, b);
    return *(uint32_t*)&t;
}

__device__ __forceinline__ uint32_t cvt2h(float a, float b) {
    return packh(__float2half_rn(a), __float2half_rn(b));
}

// 2^x on packed fp16 pair (approx; baseline PTX sm_75+)
__device__ __forceinline__ uint32_t ex2h2(uint32_t x) {
    uint32_t r;
    asm("ex2.approx.f16x2 %0, %1;" : "=r"(r) : "r"(x));
    return r;
}

// ---------------------------------------------------------------------------
// Convert kernel: 8 segments (4 weights + 4 quarters of x), fp32 -> fp16
// ---------------------------------------------------------------------------
struct CvtAll {
    const float* in[8];
    __half* out[8];
};

__global__ void __launch_bounds__(256)
cvt8_kernel(CvtAll cb, int n4)
{
    int i = blockIdx.x * blockDim.x + threadIdx.x;
    if (i >= n4) return;
    const float* in = cb.in[blockIdx.y];
    __half* out = cb.out[blockIdx.y];
    float4 v = ((const float4*)in)[i];
    ((uint32_t*)out)[2 * i]     = cvt2h(v.x, v.y);
    ((uint32_t*)out)[2 * i + 1] = cvt2h(v.z, v.w);
}

// ---------------------------------------------------------------------------
// HMMA GEMM body: C = A[M,K] @ B[N,K]^T + bias. A, B fp16 (1 MMA per frag).
// CTA tile 128x128, K-chunk 64, double-buffered cp.async, ldmatrix frags,
// ONE barrier per chunk.
// OUT: 0 = fp32 C; 2 = fp16 Ch.
// ---------------------------------------------------------------------------
#define SSTR  36                     // u32 per smem row (64 fp16 + pad)
#define GARRB (128 * SSTR * 4)       // bytes per array (18432)
#define GBUFB (2 * GARRB)            // bytes per buffer
#define GEMM_SMEM (2 * GBUFB)        // 73728

template<int OUT>
__device__ __forceinline__ void
gemm_body(uint32_t* sg,
          const __half* __restrict__ Ah, const __half* __restrict__ Bh,
          const float* __restrict__ bias, float* __restrict__ C,
          __half* __restrict__ Ch,
          int M, int N, int K)
{
    const uint32_t sbase = smem_u32(sg);

    const int tid  = threadIdx.x;
    const int lane = tid & 31;
    const int warp = tid >> 5;
    const int wm   = (warp >> 1) * 32;
    const int wn   = (warp & 1) * 64;
    const int m0   = blockIdx.y * 128;
    const int n0   = blockIdx.x * 128;

    uint32_t s_off[4];
    size_t gA[4], gB[4];
    #pragma unroll
    for (int t = 0; t < 4; t++) {
        int f   = tid + t * 256;
        int row = f >> 3;
        int c8  = f & 7;
        s_off[t] = (uint32_t)(row * SSTR + c8 * 4) * 4;
        gA[t] = (size_t)(m0 + row) * K + c8 * 8;
        gB[t] = (size_t)(n0 + row) * K + c8 * 8;
    }

    const int arow  = (lane & 7) + ((lane >> 3) & 1) * 8;
    const int acol  = (lane >> 4) * 4;
    const int brow  = (lane & 7) + (lane >> 4) * 8;
    const int bcol4 = ((lane >> 3) & 1) * 4;

    uint32_t aoff[2], boff[4];
    #pragma unroll
    for (int mt = 0; mt < 2; mt++)
        aoff[mt] = (uint32_t)((wm + mt * 16 + arow) * SSTR + acol) * 4;
    #pragma unroll
    for (int np = 0; np < 4; np++)
        boff[np] = (uint32_t)((wn + np * 16 + brow) * SSTR + bcol4) * 4;

    const int fr = lane >> 2;
    const int fc = lane & 3;

    float acc[2][8][4];
    #pragma unroll
    for (int mt = 0; mt < 2; mt++)
        #pragma unroll
        for (int nt = 0; nt < 8; nt++)
            #pragma unroll
            for (int j = 0; j < 4; j++) acc[mt][nt][j] = 0.f;

    const int nchunks = K / 64;   // 16

    #pragma unroll
    for (int t = 0; t < 4; t++) {
        cpa16(sbase + 0 * GARRB + s_off[t], Ah + gA[t]);
        cpa16(sbase + 1 * GARRB + s_off[t], Bh + gB[t]);
    }
    cpa_commit();

    for (int kc = 0; kc < nchunks; kc++) {
        cpa_wait<0>();
        __syncthreads();

        if (kc + 1 < nchunks) {
            const uint32_t bb = sbase + ((kc + 1) & 1) * GBUFB;
            const int ko = (kc + 1) * 64;
            #pragma unroll
            for (int t = 0; t < 4; t++) {
                cpa16(bb + 0 * GARRB + s_off[t], Ah + gA[t] + ko);
                cpa16(bb + 1 * GARRB + s_off[t], Bh + gB[t] + ko);
            }
            cpa_commit();
        }

        const uint32_t cb  = sbase + (kc & 1) * GBUFB;
        const uint32_t aAh = cb, aBh = cb + GARRB;

        #pragma unroll
        for (int ks = 0; ks < 4; ks++) {
            const uint32_t kbb = (uint32_t)(ks * 8) * 4;
            uint32_t afh[2][4];
            #pragma unroll
            for (int mt = 0; mt < 2; mt++)
                ldm_x4(afh[mt], aAh + aoff[mt] + kbb);
            #pragma unroll
            for (int np = 0; np < 4; np++) {
                uint32_t b4h[4];
                ldm_x4(b4h, aBh + boff[np] + kbb);
                #pragma unroll
                for (int hf = 0; hf < 2; hf++) {
                    const int nt = np * 2 + hf;
                    #pragma unroll
                    for (int mt = 0; mt < 2; mt++)
                        mma16816(acc[mt][nt], afh[mt], &b4h[hf * 2]);
                }
            }
        }
    }

    #pragma unroll
    for (int mt = 0; mt < 2; mt++) {
        #pragma unroll
        for (int nt = 0; nt < 8; nt++) {
            int row = m0 + wm + mt * 16 + fr;
            int col = n0 + wn + nt * 8 + fc * 2;
            float b0 = __ldg(&bias[col]);
            float b1 = __ldg(&bias[col + 1]);
            float c0 = acc[mt][nt][0] + b0, c1 = acc[mt][nt][1] + b1;
            float c2 = acc[mt][nt][2] + b0, c3 = acc[mt][nt][3] + b1;
            if (OUT == 2) {
                *(uint32_t*)&Ch[(size_t)row * N + col]       = cvt2h(c0, c1);
                *(uint32_t*)&Ch[(size_t)(row + 8) * N + col] = cvt2h(c2, c3);
            } else {
                *(float2*)&C[(size_t)row * N + col]       = make_float2(c0, c1);
                *(float2*)&C[(size_t)(row + 8) * N + col] = make_float2(c2, c3);
            }
        }
    }
}

struct GemmBatch {
    const __half* Bh[3];
    const float* bias[3];
    __half* Ch[3];
};

__global__ void __launch_bounds__(256, 2)
gemm_qkv(GemmBatch gb, const __half* __restrict__ Ah)
{
    extern __shared__ uint32_t sg[];
    const int z = blockIdx.z;
    gemm_body<2>(sg, Ah, gb.Bh[z], gb.bias[z], nullptr, gb.Ch[z],
                 MROWS, CDIM, CDIM);
}

__global__ void __launch_bounds__(256, 2)
gemm_o(const __half* __restrict__ Ah, const __half* __restrict__ Bh,
       const float* __restrict__ bias, float* __restrict__ C)
{
    extern __shared__ uint32_t sg[];
    gemm_body<0>(sg, Ah, Bh, bias, C, nullptr, MROWS, CDIM, CDIM);
}

// ---------------------------------------------------------------------------
// HMMA flash attention (causal). fp16 operands, fp32 softmax stats.
// Base-2 softmax: t = S*scale*log2e; P = 2^(t-m) via ex2.approx.f16x2,
// producing PV A-fragments directly. Row sums via P x ones-MMA (fp32 accum,
// every output column = row sum -> no shuffles).
// 128-row q tile/CTA, Bc=64, double-buffered cp.async KV, ldmatrix frags,
// longest-qt-first, ONE barrier per kv tile.
// ---------------------------------------------------------------------------
#define QSTR 36
#define QARR (128 * QSTR)              // 4608 u32
#define KARR (64 * QSTR)               // 2304 u32
#define KBUF (2 * KARR)                // u32 per kv buffer (kh + vh)
#define ATTN_SMEM ((QARR + 2 * KBUF) * 4)   // 55296 B
#define ONE2 0x3C003C00u               // fp16x2 {1.0, 1.0}

__global__ void __launch_bounds__(256, 2)
attn_mma(const __half* __restrict__ Qh,
         const __half* __restrict__ Kh, const __half* __restrict__ Vh,
         __half* __restrict__ Yh)
{
    extern __shared__ uint32_t s32[];
    const uint32_t sbase = smem_u32(s32);
    const uint32_t aQh = sbase;

    const int qt = gridDim.x - 1 - blockIdx.x;   // longest-first
    const int bh = blockIdx.y;
    const int b  = bh >> 4;
    const int h  = bh & 15;
    const size_t headoff = (size_t)b * TSEQ * CDIM + (size_t)h * HDIM;

    const int tid  = threadIdx.x;
    const int lane = tid & 31;
    const int warp = tid >> 5;
    const int fr   = lane >> 2;
    const int fc   = lane & 3;
    const int wm   = warp * 16;

    const int arow  = (lane & 7) + ((lane >> 3) & 1) * 8;
    const int acol  = (lane >> 4) * 4;
    const int brow  = (lane & 7) + (lane >> 4) * 8;
    const int bcol4 = ((lane >> 3) & 1) * 4;
    const uint32_t qoff = (uint32_t)((wm + arow) * QSTR + acol) * 4;
    uint32_t koff[4], voff[4];
    #pragma unroll
    for (int np = 0; np < 4; np++) {
        koff[np] = (uint32_t)((np * 16 + brow) * QSTR + bcol4) * 4;
        voff[np] = (uint32_t)(arow * QSTR + (np * 2 + (lane >> 4)) * 4) * 4;
    }

    // Q tile via cp.async (with KV tile 0, one group)
    #pragma unroll
    for (int t = 0; t < 4; t++) {
        int f  = tid + t * 256;
        int r  = f >> 3;
        int c8 = f & 7;
        size_t g = headoff + (size_t)(qt * 128 + r) * CDIM + c8 * 8;
        uint32_t so = (uint32_t)(r * QSTR + c8 * 4) * 4;
        cpa16(aQh + so, Qh + g);
    }

    uint32_t kvso[2];
    size_t kvg[2];
    #pragma unroll
    for (int t = 0; t < 2; t++) {
        int f  = tid + t * 256;
        int r  = f >> 3;
        int c8 = f & 7;
        kvso[t] = (uint32_t)(r * QSTR + c8 * 4) * 4;
        kvg[t]  = headoff + (size_t)r * CDIM + c8 * 8;
    }
    const uint32_t kvbase = sbase + QARR * 4;

    const int ktmax = 2 * qt + 1;

    // prefetch kv tile 0 -> buffer 0
    #pragma unroll
    for (int t = 0; t < 2; t++) {
        cpa16(kvbase + 0 * KARR * 4 + kvso[t], Kh + kvg[t]);
        cpa16(kvbase + 1 * KARR * 4 + kvso[t], Vh + kvg[t]);
    }
    cpa_commit();

    // scale * log2(e): softmax computed in base-2 domain
    const float C2 = 0.125f * 1.4426950408889634f;
    float o[8][4];
    #pragma unroll
    for (int nt = 0; nt < 8; nt++)
        #pragma unroll
        for (int j = 0; j < 4; j++) o[nt][j] = 0.f;
    float mA = -INFINITY, mB = -INFINITY, lA = 0.f, lB = 0.f;

    const int rowAg = qt * 128 + wm + fr;
    const int rowBg = rowAg + 8;

    const uint32_t ones[2] = {ONE2, ONE2};

    for (int kt = 0; kt <= ktmax; kt++) {
        cpa_wait<0>();
        __syncthreads();

        if (kt < ktmax) {
            const uint32_t bb = kvbase + ((kt + 1) & 1) * KBUF * 4;
            const size_t go = (size_t)(kt + 1) * 64 * CDIM;
            #pragma unroll
            for (int t = 0; t < 2; t++) {
                cpa16(bb + 0 * KARR * 4 + kvso[t], Kh + kvg[t] + go);
                cpa16(bb + 1 * KARR * 4 + kvso[t], Vh + kvg[t] + go);
            }
            cpa_commit();
        }

        const uint32_t cb  = kvbase + (kt & 1) * KBUF * 4;
        const uint32_t aKh = cb, aVh = cb + KARR * 4;

        // S = Q K^T (1 MMA per fragment)
        float sacc[8][4];
        #pragma unroll
        for (int nt = 0; nt < 8; nt++)
            #pragma unroll
            for (int j = 0; j < 4; j++) sacc[nt][j] = 0.f;

        #pragma unroll
        for (int ks = 0; ks < 4; ks++) {
            const uint32_t kbb = (uint32_t)(ks * 8) * 4;
            uint32_t ah[4];
            ldm_x4(ah, aQh + qoff + kbb);
            #pragma unroll
            for (int np = 0; np < 4; np++) {
                uint32_t k4h[4];
                ldm_x4(k4h, aKh + koff[np] + kbb);
                #pragma unroll
                for (int hf = 0; hf < 2; hf++) {
                    const int nt = np * 2 + hf;
                    mma16816(sacc[nt], ah, &k4h[hf * 2]);
                }
            }
        }

        // scale (base-2) + causal mask
        const bool diag = (kt >= 2 * qt);
        #pragma unroll
        for (int nt = 0; nt < 8; nt++) {
            #pragma unroll
            for (int j = 0; j < 4; j++) sacc[nt][j] *= C2;
            if (diag) {
                int col0 = kt * 64 + nt * 8 + 2 * fc;
                if (col0     > rowAg) sacc[nt][0] = -INFINITY;
                if (col0 + 1 > rowAg) sacc[nt][1] = -INFINITY;
                if (col0     > rowBg) sacc[nt][2] = -INFINITY;
                if (col0 + 1 > rowBg) sacc[nt][3] = -INFINITY;
            }
        }

        // row max (base-2 domain)
        float mxA = -INFINITY, mxB = -INFINITY;
        #pragma unroll
        for (int nt = 0; nt < 8; nt++) {
            mxA = fmaxf(mxA, fmaxf(sacc[nt][0], sacc[nt][1]));
            mxB = fmaxf(mxB, fmaxf(sacc[nt][2], sacc[nt][3]));
        }
        mxA = fmaxf(mxA, __shfl_xor_sync(0xffffffffu, mxA, 1));
        mxA = fmaxf(mxA, __shfl_xor_sync(0xffffffffu, mxA, 2));
        mxB = fmaxf(mxB, __shfl_xor_sync(0xffffffffu, mxB, 1));
        mxB = fmaxf(mxB, __shfl_xor_sync(0xffffffffu, mxB, 2));

        float mnA = fmaxf(mA, mxA), mnB = fmaxf(mB, mxB);
        float aA = exp2f(mA - mnA), aB = exp2f(mB - mnB);
        mA = mnA; mB = mnB;

        // P = 2^(t - m) directly as fp16 PV A-fragments
        uint32_t pfrag[4][4];
        #pragma unroll
        for (int ks = 0; ks < 4; ks++) {
            pfrag[ks][0] = ex2h2(cvt2h(sacc[2*ks][0]   - mnA, sacc[2*ks][1]   - mnA));
            pfrag[ks][1] = ex2h2(cvt2h(sacc[2*ks][2]   - mnB, sacc[2*ks][3]   - mnB));
            pfrag[ks][2] = ex2h2(cvt2h(sacc[2*ks+1][0] - mnA, sacc[2*ks+1][1] - mnA));
            pfrag[ks][3] = ex2h2(cvt2h(sacc[2*ks+1][2] - mnB, sacc[2*ks+1][3] - mnB));
        }

        // row sums via ones-MMA: every output column = row sum
        float lacc[4] = {0.f, 0.f, 0.f, 0.f};
        #pragma unroll
        for (int ks = 0; ks < 4; ks++)
            mma16816(lacc, pfrag[ks], ones);
        lA = lA * aA + lacc[0];
        lB = lB * aB + lacc[2];

        #pragma unroll
        for (int nt = 0; nt < 8; nt++) {
            o[nt][0] *= aA; o[nt][1] *= aA;
            o[nt][2] *= aB; o[nt][3] *= aB;
        }

        // O += P V
        #pragma unroll
        for (int ks = 0; ks < 4; ks++) {
            const uint32_t ro = (uint32_t)(ks * 16 * QSTR) * 4;
            #pragma unroll
            for (int np = 0; np < 4; np++) {
                uint32_t v4h[4];
                ldm_x4_trans(v4h, aVh + ro + voff[np]);
                #pragma unroll
                for (int hf = 0; hf < 2; hf++) {
                    const int nt = np * 2 + hf;
                    mma16816(o[nt], pfrag[ks], &v4h[hf * 2]);
                }
            }
        }
    }

    // normalize + write yh fp16
    float liA = 1.0f / lA, liB = 1.0f / lB;
    #pragma unroll
    for (int nt = 0; nt < 8; nt++) {
        int col = nt * 8 + 2 * fc;
        size_t gA = headoff + (size_t)rowAg * CDIM + col;
        size_t gB = headoff + (size_t)rowBg * CDIM + col;
        *(uint32_t*)&Yh[gA] = cvt2h(o[nt][0] * liA, o[nt][1] * liA);
        *(uint32_t*)&Yh[gB] = cvt2h(o[nt][2] * liB, o[nt][3] * liB);
    }
}

// ---------------------------------------------------------------------------
// Launch
// ---------------------------------------------------------------------------
extern "C" void kernel_launch(void* const* d_in, const int* in_sizes, int n_in,
                              void* d_out, int out_size)
{
    const float* x  = (const float*)d_in[0];
    const float* Wq = (const float*)d_in[1];
    const float* bq = (const float*)d_in[2];
    const float* Wk = (const float*)d_in[3];
    const float* bk = (const float*)d_in[4];
    const float* Wv = (const float*)d_in[5];
    const float* bv = (const float*)d_in[6];
    const float* Wo = (const float*)d_in[7];
    const float* bo = (const float*)d_in[8];
    float* out = (float*)d_out;

    __half *xh, *qh, *kh, *vh, *yh;
    __half *wqh, *wkh, *wvh, *woh;
    cudaGetSymbolAddress((void**)&xh, g_xh);
    cudaGetSymbolAddress((void**)&qh, g_qh);
    cudaGetSymbolAddress((void**)&kh, g_kh);
    cudaGetSymbolAddress((void**)&vh, g_vh);
    cudaGetSymbolAddress((void**)&yh, g_yh);
    cudaGetSymbolAddress((void**)&wqh, g_wqh);
    cudaGetSymbolAddress((void**)&wkh, g_wkh);
    cudaGetSymbolAddress((void**)&wvh, g_wvh);
    cudaGetSymbolAddress((void**)&woh, g_woh);

    cudaFuncSetAttribute(attn_mma,
                         cudaFuncAttributeMaxDynamicSharedMemorySize, ATTN_SMEM);
    cudaFuncSetAttribute(gemm_qkv,
                         cudaFuncAttributeMaxDynamicSharedMemorySize, GEMM_SMEM);
    cudaFuncSetAttribute(gemm_o,
                         cudaFuncAttributeMaxDynamicSharedMemorySize, GEMM_SMEM);

    const int nw4 = CDIM * CDIM / 4;   // float4 per weight / x-quarter
    const int xq  = CDIM * CDIM;       // elements per x quarter

    // 1) all fp32->fp16 converts in one launch
    CvtAll ca;
    ca.in[0] = Wq; ca.out[0] = wqh;
    ca.in[1] = Wk; ca.out[1] = wkh;
    ca.in[2] = Wv; ca.out[2] = wvh;
    ca.in[3] = Wo; ca.out[3] = woh;
    for (int q = 0; q < 4; q++) {
        ca.in[4 + q]  = x + (size_t)q * xq;
        ca.out[4 + q] = xh + (size_t)q * xq;
    }
    dim3 cgrid(nw4 / 256, 8);
    cvt8_kernel<<<cgrid, 256>>>(ca, nw4);

    // 2) merged Q/K/V projection
    GemmBatch gb;
    gb.Bh[0] = wqh; gb.bias[0] = bq; gb.Ch[0] = qh;
    gb.Bh[1] = wkh; gb.bias[1] = bk; gb.Ch[1] = kh;
    gb.Bh[2] = wvh; gb.bias[2] = bv; gb.Ch[2] = vh;
    dim3 qkvgrid(CDIM / 128, MROWS / 128, 3);   // (8, 32, 3)
    gemm_qkv<<<qkvgrid, 256, GEMM_SMEM>>>(gb, xh);

    // 3) attention
    dim3 agrid(TSEQ / 128, BATCH * NHEAD);  // (16, 32)
    attn_mma<<<agrid, 256, ATTN_SMEM>>>(qh, kh, vh, yh);

    // 4) output projection
    dim3 ogrid(CDIM / 128, MROWS / 128);    // (8, 32)
    gemm_o<<<ogrid, 256, GEMM_SMEM>>>(yh, woh, bo, out);
}

// round 15
// speedup vs baseline: 8.6976x; 1.0116x over previous
#include <cuda_runtime.h>
#include <cuda_fp16.h>
#include <math.h>
#include <stdint.h>

// Problem constants
#define BATCH 2
#define TSEQ  2048
#define CDIM  1024
#define NHEAD 16
#define HDIM  64
#define MROWS (BATCH * TSEQ)   // 4096

// ---------------------------------------------------------------------------
// Scratch (allocation-free: __device__ globals)
// ---------------------------------------------------------------------------
__device__ __align__(16) __half g_xh[MROWS * CDIM];
__device__ __align__(16) __half g_qh[MROWS * CDIM];
__device__ __align__(16) __half g_kh[MROWS * CDIM];
__device__ __align__(16) __half g_vh[MROWS * CDIM];
__device__ __align__(16) __half g_yh[MROWS * CDIM];
__device__ __align__(16) __half g_wqh[CDIM * CDIM];
__device__ __align__(16) __half g_wkh[CDIM * CDIM];
__device__ __align__(16) __half g_wvh[CDIM * CDIM];
__device__ __align__(16) __half g_woh[CDIM * CDIM];

// ---------------------------------------------------------------------------
// PTX helpers (baseline PTX, valid for compute_103)
// ---------------------------------------------------------------------------
__device__ __forceinline__ void mma16816(float* c, const uint32_t* a,
                                         const uint32_t* b) {
    asm volatile(
        "mma.sync.aligned.m16n8k16.row.col.f32.f16.f16.f32 "
        "{%0,%1,%2,%3}, {%4,%5,%6,%7}, {%8,%9}, {%0,%1,%2,%3};"
        : "+f"(c[0]), "+f"(c[1]), "+f"(c[2]), "+f"(c[3])
        : "r"(a[0]), "r"(a[1]), "r"(a[2]), "r"(a[3]), "r"(b[0]), "r"(b[1]));
}

__device__ __forceinline__ void ldm_x4(uint32_t* r, uint32_t saddr) {
    asm volatile(
        "ldmatrix.sync.aligned.m8n8.x4.shared.b16 {%0,%1,%2,%3}, [%4];"
        : "=r"(r[0]), "=r"(r[1]), "=r"(r[2]), "=r"(r[3]) : "r"(saddr));
}

__device__ __forceinline__ void ldm_x4_trans(uint32_t* r, uint32_t saddr) {
    asm volatile(
        "ldmatrix.sync.aligned.m8n8.x4.trans.shared.b16 {%0,%1,%2,%3}, [%4];"
        : "=r"(r[0]), "=r"(r[1]), "=r"(r[2]), "=r"(r[3]) : "r"(saddr));
}

__device__ __forceinline__ uint32_t smem_u32(const void* p) {
    uint32_t a;
    asm("{ .reg .u64 t; cvta.to.shared.u64 t, %1; cvt.u32.u64 %0, t; }"
        : "=r"(a) : "l"(p));
    return a;
}

__device__ __forceinline__ void cpa16(uint32_t s, const void* g) {
    asm volatile("cp.async.cg.shared.global [%0], [%1], 16;"
                 :: "r"(s), "l"(g));
}
__device__ __forceinline__ void cpa_commit() {
    asm volatile("cp.async.commit_group;");
}
template<int N> __device__ __forceinline__ void cpa_wait() {
    asm volatile("cp.async.wait_group %0;" :: "n"(N));
}

__device__ __forceinline__ uint32_t packh(__half a, __half b) {
    __half2 t = __halves2half2(a, b);
    return *(uint32_t*)&t;
}

__device__ __forceinline__ uint32_t cvt2h(float a, float b) {
    return packh(__float2half_rn(a), __float2half_rn(b));
}

// 2^x on packed fp16 pair (approx; baseline PTX sm_75+)
__device__ __forceinline__ uint32_t ex2h2(uint32_t x) {
    uint32_t r;
    asm("ex2.approx.f16x2 %0, %1;" : "=r"(r) : "r"(x));
    return r;
}

// ---------------------------------------------------------------------------
// Convert kernel: 8 segments (4 weights + 4 quarters of x), fp32 -> fp16
// ---------------------------------------------------------------------------
struct CvtAll {
    const float* in[8];
    __half* out[8];
};

__global__ void __launch_bounds__(256)
cvt8_kernel(CvtAll cb, int n4)
{
    int i = blockIdx.x * blockDim.x + threadIdx.x;
    if (i >= n4) return;
    const float* in = cb.in[blockIdx.y];
    __half* out = cb.out[blockIdx.y];
    float4 v = ((const float4*)in)[i];
    ((uint32_t*)out)[2 * i]     = cvt2h(v.x, v.y);
    ((uint32_t*)out)[2 * i + 1] = cvt2h(v.z, v.w);
}

// ---------------------------------------------------------------------------
// HMMA GEMM body: C = A[M,K] @ B[N,K]^T + bias. A, B fp16 (1 MMA per frag).
// CTA tile 128x128, K-chunk 64, TRIPLE-buffered cp.async (wait_group 1),
// ldmatrix frags, ONE barrier per chunk.
// OUT: 0 = fp32 C; 2 = fp16 Ch.
// ---------------------------------------------------------------------------
#define SSTR  36                     // u32 per smem row (64 fp16 + pad)
#define GARRB (128 * SSTR * 4)       // bytes per array (18432)
#define GBUFB (2 * GARRB)            // bytes per buffer
#define GEMM_SMEM (3 * GBUFB)        // 110592

template<int OUT>
__device__ __forceinline__ void
gemm_body(uint32_t* sg,
          const __half* __restrict__ Ah, const __half* __restrict__ Bh,
          const float* __restrict__ bias, float* __restrict__ C,
          __half* __restrict__ Ch,
          int M, int N, int K)
{
    const uint32_t sbase = smem_u32(sg);

    const int tid  = threadIdx.x;
    const int lane = tid & 31;
    const int warp = tid >> 5;
    const int wm   = (warp >> 1) * 32;
    const int wn   = (warp & 1) * 64;
    const int m0   = blockIdx.y * 128;
    const int n0   = blockIdx.x * 128;

    uint32_t s_off[4];
    size_t gA[4], gB[4];
    #pragma unroll
    for (int t = 0; t < 4; t++) {
        int f   = tid + t * 256;
        int row = f >> 3;
        int c8  = f & 7;
        s_off[t] = (uint32_t)(row * SSTR + c8 * 4) * 4;
        gA[t] = (size_t)(m0 + row) * K + c8 * 8;
        gB[t] = (size_t)(n0 + row) * K + c8 * 8;
    }

    const int arow  = (lane & 7) + ((lane >> 3) & 1) * 8;
    const int acol  = (lane >> 4) * 4;
    const int brow  = (lane & 7) + (lane >> 4) * 8;
    const int bcol4 = ((lane >> 3) & 1) * 4;

    uint32_t aoff[2], boff[4];
    #pragma unroll
    for (int mt = 0; mt < 2; mt++)
        aoff[mt] = (uint32_t)((wm + mt * 16 + arow) * SSTR + acol) * 4;
    #pragma unroll
    for (int np = 0; np < 4; np++)
        boff[np] = (uint32_t)((wn + np * 16 + brow) * SSTR + bcol4) * 4;

    const int fr = lane >> 2;
    const int fc = lane & 3;

    float acc[2][8][4];
    #pragma unroll
    for (int mt = 0; mt < 2; mt++)
        #pragma unroll
        for (int nt = 0; nt < 8; nt++)
            #pragma unroll
            for (int j = 0; j < 4; j++) acc[mt][nt][j] = 0.f;

    const int nchunks = K / 64;   // 16

    // prefetch chunks 0,1 -> buffers 0,1 (two groups)
    #pragma unroll
    for (int pc = 0; pc < 2; pc++) {
        const uint32_t bb = sbase + pc * GBUFB;
        const int ko = pc * 64;
        #pragma unroll
        for (int t = 0; t < 4; t++) {
            cpa16(bb + 0 * GARRB + s_off[t], Ah + gA[t] + ko);
            cpa16(bb + 1 * GARRB + s_off[t], Bh + gB[t] + ko);
        }
        cpa_commit();
    }

    int buf = 0;
    for (int kc = 0; kc < nchunks; kc++) {
        cpa_wait<1>();        // chunk kc resident; kc+1 may be in flight
        __syncthreads();      // all warps done computing kc-1 (its buffer = kc+2's)

        if (kc + 2 < nchunks) {
            int pb = buf + 2; if (pb >= 3) pb -= 3;
            const uint32_t bb = sbase + pb * GBUFB;
            const int ko = (kc + 2) * 64;
            #pragma unroll
            for (int t = 0; t < 4; t++) {
                cpa16(bb + 0 * GARRB + s_off[t], Ah + gA[t] + ko);
                cpa16(bb + 1 * GARRB + s_off[t], Bh + gB[t] + ko);
            }
            cpa_commit();
        } else {
            cpa_commit();     // keep group count in step for wait<1>
        }

        const uint32_t cb  = sbase + buf * GBUFB;
        const uint32_t aAh = cb, aBh = cb + GARRB;

        #pragma unroll
        for (int ks = 0; ks < 4; ks++) {
            const uint32_t kbb = (uint32_t)(ks * 8) * 4;
            uint32_t afh[2][4];
            #pragma unroll
            for (int mt = 0; mt < 2; mt++)
                ldm_x4(afh[mt], aAh + aoff[mt] + kbb);
            #pragma unroll
            for (int np = 0; np < 4; np++) {
                uint32_t b4h[4];
                ldm_x4(b4h, aBh + boff[np] + kbb);
                #pragma unroll
                for (int hf = 0; hf < 2; hf++) {
                    const int nt = np * 2 + hf;
                    #pragma unroll
                    for (int mt = 0; mt < 2; mt++)
                        mma16816(acc[mt][nt], afh[mt], &b4h[hf * 2]);
                }
            }
        }
        buf++; if (buf == 3) buf = 0;
    }

    #pragma unroll
    for (int mt = 0; mt < 2; mt++) {
        #pragma unroll
        for (int nt = 0; nt < 8; nt++) {
            int row = m0 + wm + mt * 16 + fr;
            int col = n0 + wn + nt * 8 + fc * 2;
            float b0 = __ldg(&bias[col]);
            float b1 = __ldg(&bias[col + 1]);
            float c0 = acc[mt][nt][0] + b0, c1 = acc[mt][nt][1] + b1;
            float c2 = acc[mt][nt][2] + b0, c3 = acc[mt][nt][3] + b1;
            if (OUT == 2) {
                *(uint32_t*)&Ch[(size_t)row * N + col]       = cvt2h(c0, c1);
                *(uint32_t*)&Ch[(size_t)(row + 8) * N + col] = cvt2h(c2, c3);
            } else {
                *(float2*)&C[(size_t)row * N + col]       = make_float2(c0, c1);
                *(float2*)&C[(size_t)(row + 8) * N + col] = make_float2(c2, c3);
            }
        }
    }
}

struct GemmBatch {
    const __half* Bh[3];
    const float* bias[3];
    __half* Ch[3];
};

__global__ void __launch_bounds__(256, 2)
gemm_qkv(GemmBatch gb, const __half* __restrict__ Ah)
{
    extern __shared__ uint32_t sg[];
    const int z = blockIdx.z;
    gemm_body<2>(sg, Ah, gb.Bh[z], gb.bias[z], nullptr, gb.Ch[z],
                 MROWS, CDIM, CDIM);
}

__global__ void __launch_bounds__(256, 2)
gemm_o(const __half* __restrict__ Ah, const __half* __restrict__ Bh,
       const float* __restrict__ bias, float* __restrict__ C)
{
    extern __shared__ uint32_t sg[];
    gemm_body<0>(sg, Ah, Bh, bias, C, nullptr, MROWS, CDIM, CDIM);
}

// ---------------------------------------------------------------------------
// HMMA flash attention (causal). fp16 operands, fp32 softmax stats.
// Base-2 softmax via ex2.approx.f16x2; row sums via ones-MMA.
// Q fragments hoisted to registers (loaded once). TRIPLE-buffered KV.
// 128-row q tile/CTA, Bc=64, longest-qt-first, ONE barrier per kv tile.
// ---------------------------------------------------------------------------
#define QSTR 36
#define QARR (128 * QSTR)              // 4608 u32
#define KARR (64 * QSTR)               // 2304 u32
#define KBUF (2 * KARR)                // u32 per kv buffer (kh + vh)
#define ATTN_SMEM ((QARR + 3 * KBUF) * 4)   // 73728 B
#define ONE2 0x3C003C00u               // fp16x2 {1.0, 1.0}

__global__ void __launch_bounds__(256, 2)
attn_mma(const __half* __restrict__ Qh,
         const __half* __restrict__ Kh, const __half* __restrict__ Vh,
         __half* __restrict__ Yh)
{
    extern __shared__ uint32_t s32[];
    const uint32_t sbase = smem_u32(s32);
    const uint32_t aQh = sbase;

    const int qt = gridDim.x - 1 - blockIdx.x;   // longest-first
    const int bh = blockIdx.y;
    const int b  = bh >> 4;
    const int h  = bh & 15;
    const size_t headoff = (size_t)b * TSEQ * CDIM + (size_t)h * HDIM;

    const int tid  = threadIdx.x;
    const int lane = tid & 31;
    const int warp = tid >> 5;
    const int fr   = lane >> 2;
    const int fc   = lane & 3;
    const int wm   = warp * 16;

    const int arow  = (lane & 7) + ((lane >> 3) & 1) * 8;
    const int acol  = (lane >> 4) * 4;
    const int brow  = (lane & 7) + (lane >> 4) * 8;
    const int bcol4 = ((lane >> 3) & 1) * 4;
    const uint32_t qoff = (uint32_t)((wm + arow) * QSTR + acol) * 4;
    uint32_t koff[4], voff[4];
    #pragma unroll
    for (int np = 0; np < 4; np++) {
        koff[np] = (uint32_t)((np * 16 + brow) * QSTR + bcol4) * 4;
        voff[np] = (uint32_t)(arow * QSTR + (np * 2 + (lane >> 4)) * 4) * 4;
    }

    uint32_t kvso[2];
    size_t kvg[2];
    #pragma unroll
    for (int t = 0; t < 2; t++) {
        int f  = tid + t * 256;
        int r  = f >> 3;
        int c8 = f & 7;
        kvso[t] = (uint32_t)(r * QSTR + c8 * 4) * 4;
        kvg[t]  = headoff + (size_t)r * CDIM + c8 * 8;
    }
    const uint32_t kvbase = sbase + QARR * 4;

    const int ktmax = 2 * qt + 1;

    // group 0: Q tile + kv tile 0
    #pragma unroll
    for (int t = 0; t < 4; t++) {
        int f  = tid + t * 256;
        int r  = f >> 3;
        int c8 = f & 7;
        size_t g = headoff + (size_t)(qt * 128 + r) * CDIM + c8 * 8;
        uint32_t so = (uint32_t)(r * QSTR + c8 * 4) * 4;
        cpa16(aQh + so, Qh + g);
    }
    #pragma unroll
    for (int t = 0; t < 2; t++) {
        cpa16(kvbase + 0 * KARR * 4 + kvso[t], Kh + kvg[t]);
        cpa16(kvbase + 1 * KARR * 4 + kvso[t], Vh + kvg[t]);
    }
    cpa_commit();

    // group 1: kv tile 1 (ktmax >= 1 always)
    {
        const uint32_t bb = kvbase + KBUF * 4;
        const size_t go = (size_t)64 * CDIM;
        #pragma unroll
        for (int t = 0; t < 2; t++) {
            cpa16(bb + 0 * KARR * 4 + kvso[t], Kh + kvg[t] + go);
            cpa16(bb + 1 * KARR * 4 + kvso[t], Vh + kvg[t] + go);
        }
        cpa_commit();
    }

    const float C2 = 0.125f * 1.4426950408889634f;   // scale * log2(e)
    float o[8][4];
    #pragma unroll
    for (int nt = 0; nt < 8; nt++)
        #pragma unroll
        for (int j = 0; j < 4; j++) o[nt][j] = 0.f;
    float mA = -INFINITY, mB = -INFINITY, lA = 0.f, lB = 0.f;

    const int rowAg = qt * 128 + wm + fr;
    const int rowBg = rowAg + 8;

    const uint32_t ones[2] = {ONE2, ONE2};
    uint32_t qfrag[4][4];   // hoisted Q A-fragments (loaded at kt==0)

    int buf = 0;
    for (int kt = 0; kt <= ktmax; kt++) {
        cpa_wait<1>();        // tile kt (and Q on kt=0) resident
        __syncthreads();      // all warps done computing kt-1

        if (kt == 0) {
            #pragma unroll
            for (int ks = 0; ks < 4; ks++)
                ldm_x4(qfrag[ks], aQh + qoff + (uint32_t)(ks * 8) * 4);
        }

        if (kt + 2 <= ktmax) {
            int pb = buf + 2; if (pb >= 3) pb -= 3;
            const uint32_t bb = kvbase + pb * KBUF * 4;
            const size_t go = (size_t)(kt + 2) * 64 * CDIM;
            #pragma unroll
            for (int t = 0; t < 2; t++) {
                cpa16(bb + 0 * KARR * 4 + kvso[t], Kh + kvg[t] + go);
                cpa16(bb + 1 * KARR * 4 + kvso[t], Vh + kvg[t] + go);
            }
            cpa_commit();
        } else {
            cpa_commit();     // keep group count in step
        }

        const uint32_t cb  = kvbase + buf * KBUF * 4;
        const uint32_t aKh = cb, aVh = cb + KARR * 4;

        // S = Q K^T (Q from registers)
        float sacc[8][4];
        #pragma unroll
        for (int nt = 0; nt < 8; nt++)
            #pragma unroll
            for (int j = 0; j < 4; j++) sacc[nt][j] = 0.f;

        #pragma unroll
        for (int ks = 0; ks < 4; ks++) {
            const uint32_t kbb = (uint32_t)(ks * 8) * 4;
            #pragma unroll
            for (int np = 0; np < 4; np++) {
                uint32_t k4h[4];
                ldm_x4(k4h, aKh + koff[np] + kbb);
                #pragma unroll
                for (int hf = 0; hf < 2; hf++) {
                    const int nt = np * 2 + hf;
                    mma16816(sacc[nt], qfrag[ks], &k4h[hf * 2]);
                }
            }
        }

        // scale (base-2) + causal mask
        const bool diag = (kt >= 2 * qt);
        #pragma unroll
        for (int nt = 0; nt < 8; nt++) {
            #pragma unroll
            for (int j = 0; j < 4; j++) sacc[nt][j] *= C2;
            if (diag) {
                int col0 = kt * 64 + nt * 8 + 2 * fc;
                if (col0     > rowAg) sacc[nt][0] = -INFINITY;
                if (col0 + 1 > rowAg) sacc[nt][1] = -INFINITY;
                if (col0     > rowBg) sacc[nt][2] = -INFINITY;
                if (col0 + 1 > rowBg) sacc[nt][3] = -INFINITY;
            }
        }

        // row max (base-2 domain)
        float mxA = -INFINITY, mxB = -INFINITY;
        #pragma unroll
        for (int nt = 0; nt < 8; nt++) {
            mxA = fmaxf(mxA, fmaxf(sacc[nt][0], sacc[nt][1]));
            mxB = fmaxf(mxB, fmaxf(sacc[nt][2], sacc[nt][3]));
        }
        mxA = fmaxf(mxA, __shfl_xor_sync(0xffffffffu, mxA, 1));
        mxA = fmaxf(mxA, __shfl_xor_sync(0xffffffffu, mxA, 2));
        mxB = fmaxf(mxB, __shfl_xor_sync(0xffffffffu, mxB, 1));
        mxB = fmaxf(mxB, __shfl_xor_sync(0xffffffffu, mxB, 2));

        float mnA = fmaxf(mA, mxA), mnB = fmaxf(mB, mxB);
        float aA = exp2f(mA - mnA), aB = exp2f(mB - mnB);
        mA = mnA; mB = mnB;

        // P = 2^(t - m) as fp16 PV A-fragments
        uint32_t pfrag[4][4];
        #pragma unroll
        for (int ks = 0; ks < 4; ks++) {
            pfrag[ks][0] = ex2h2(cvt2h(sacc[2*ks][0]   - mnA, sacc[2*ks][1]   - mnA));
            pfrag[ks][1] = ex2h2(cvt2h(sacc[2*ks][2]   - mnB, sacc[2*ks][3]   - mnB));
            pfrag[ks][2] = ex2h2(cvt2h(sacc[2*ks+1][0] - mnA, sacc[2*ks+1][1] - mnA));
            pfrag[ks][3] = ex2h2(cvt2h(sacc[2*ks+1][2] - mnB, sacc[2*ks+1][3] - mnB));
        }

        // row sums via ones-MMA
        float lacc[4] = {0.f, 0.f, 0.f, 0.f};
        #pragma unroll
        for (int ks = 0; ks < 4; ks++)
            mma16816(lacc, pfrag[ks], ones);
        lA = lA * aA + lacc[0];
        lB = lB * aB + lacc[2];

        #pragma unroll
        for (int nt = 0; nt < 8; nt++) {
            o[nt][0] *= aA; o[nt][1] *= aA;
            o[nt][2] *= aB; o[nt][3] *= aB;
        }

        // O += P V
        #pragma unroll
        for (int ks = 0; ks < 4; ks++) {
            const uint32_t ro = (uint32_t)(ks * 16 * QSTR) * 4;
            #pragma unroll
            for (int np = 0; np < 4; np++) {
                uint32_t v4h[4];
                ldm_x4_trans(v4h, aVh + ro + voff[np]);
                #pragma unroll
                for (int hf = 0; hf < 2; hf++) {
                    const int nt = np * 2 + hf;
                    mma16816(o[nt], pfrag[ks], &v4h[hf * 2]);
                }
            }
        }
        buf++; if (buf == 3) buf = 0;
    }

    // normalize + write yh fp16
    float liA = 1.0f / lA, liB = 1.0f / lB;
    #pragma unroll
    for (int nt = 0; nt < 8; nt++) {
        int col = nt * 8 + 2 * fc;
        size_t gA = headoff + (size_t)rowAg * CDIM + col;
        size_t gB = headoff + (size_t)rowBg * CDIM + col;
        *(uint32_t*)&Yh[gA] = cvt2h(o[nt][0] * liA, o[nt][1] * liA);
        *(uint32_t*)&Yh[gB] = cvt2h(o[nt][2] * liB, o[nt][3] * liB);
    }
}

// ---------------------------------------------------------------------------
// Launch
// ---------------------------------------------------------------------------
extern "C" void kernel_launch(void* const* d_in, const int* in_sizes, int n_in,
                              void* d_out, int out_size)
{
    const float* x  = (const float*)d_in[0];
    const float* Wq = (const float*)d_in[1];
    const float* bq = (const float*)d_in[2];
    const float* Wk = (const float*)d_in[3];
    const float* bk = (const float*)d_in[4];
    const float* Wv = (const float*)d_in[5];
    const float* bv = (const float*)d_in[6];
    const float* Wo = (const float*)d_in[7];
    const float* bo = (const float*)d_in[8];
    float* out = (float*)d_out;

    __half *xh, *qh, *kh, *vh, *yh;
    __half *wqh, *wkh, *wvh, *woh;
    cudaGetSymbolAddress((void**)&xh, g_xh);
    cudaGetSymbolAddress((void**)&qh, g_qh);
    cudaGetSymbolAddress((void**)&kh, g_kh);
    cudaGetSymbolAddress((void**)&vh, g_vh);
    cudaGetSymbolAddress((void**)&yh, g_yh);
    cudaGetSymbolAddress((void**)&wqh, g_wqh);
    cudaGetSymbolAddress((void**)&wkh, g_wkh);
    cudaGetSymbolAddress((void**)&wvh, g_wvh);
    cudaGetSymbolAddress((void**)&woh, g_woh);

    cudaFuncSetAttribute(attn_mma,
                         cudaFuncAttributeMaxDynamicSharedMemorySize, ATTN_SMEM);
    cudaFuncSetAttribute(gemm_qkv,
                         cudaFuncAttributeMaxDynamicSharedMemorySize, GEMM_SMEM);
    cudaFuncSetAttribute(gemm_o,
                         cudaFuncAttributeMaxDynamicSharedMemorySize, GEMM_SMEM);

    const int nw4 = CDIM * CDIM / 4;   // float4 per weight / x-quarter
    const int xq  = CDIM * CDIM;       // elements per x quarter

    // 1) all fp32->fp16 converts in one launch
    CvtAll ca;
    ca.in[0] = Wq; ca.out[0] = wqh;
    ca.in[1] = Wk; ca.out[1] = wkh;
    ca.in[2] = Wv; ca.out[2] = wvh;
    ca.in[3] = Wo; ca.out[3] = woh;
    for (int q = 0; q < 4; q++) {
        ca.in[4 + q]  = x + (size_t)q * xq;
        ca.out[4 + q] = xh + (size_t)q * xq;
    }
    dim3 cgrid(nw4 / 256, 8);
    cvt8_kernel<<<cgrid, 256>>>(ca, nw4);

    // 2) merged Q/K/V projection
    GemmBatch gb;
    gb.Bh[0] = wqh; gb.bias[0] = bq; gb.Ch[0] = qh;
    gb.Bh[1] = wkh; gb.bias[1] = bk; gb.Ch[1] = kh;
    gb.Bh[2] = wvh; gb.bias[2] = bv; gb.Ch[2] = vh;
    dim3 qkvgrid(CDIM / 128, MROWS / 128, 3);   // (8, 32, 3)
    gemm_qkv<<<qkvgrid, 256, GEMM_SMEM>>>(gb, xh);

    // 3) attention
    dim3 agrid(TSEQ / 128, BATCH * NHEAD);  // (16, 32)
    attn_mma<<<agrid, 256, ATTN_SMEM>>>(qh, kh, vh, yh);

    // 4) output projection
    dim3 ogrid(CDIM / 128, MROWS / 128);    // (8, 32)
    gemm_o<<<ogrid, 256, GEMM_SMEM>>>(yh, woh, bo, out);
}